// round 1
// baseline (speedup 1.0000x reference)
#include <cuda_runtime.h>
#include <math.h>

#define BB 32
#define PP 1024
#define KNN 20
#define NPTS (BB*PP)

// ---------------- scratch (device globals; no allocs allowed) ----------------
__device__ __align__(16) float g_x1[NPTS*64];
__device__ __align__(16) float g_x2[NPTS*128];
__device__ int g_idx[NPTS*KNN];
__device__ unsigned int g_pool[BB*1024];

// ---------------- KNN over 3-D positions ----------------
// grid (4, 32): blockIdx.y = batch, blockIdx.x = 256-point tile. 256 threads, thread = point.
__global__ __launch_bounds__(256) void knn_pos_kernel(const float* __restrict__ pos)
{
    __shared__ float sx[PP], sy[PP], sz[PP], sq[PP];
    int b = blockIdx.y;
    const float* p = pos + (size_t)b * PP * 3;
    for (int j = threadIdx.x; j < PP; j += 256) {
        float x = p[3*j], y = p[3*j+1], z = p[3*j+2];
        sx[j] = x; sy[j] = y; sz[j] = z; sq[j] = x*x + y*y + z*z;
    }
    __syncthreads();
    int il = blockIdx.x * 256 + threadIdx.x;
    float xi = sx[il], yi = sy[il], zi = sz[il], sqi = sq[il];
    float bd[KNN]; int bi[KNN];
#pragma unroll
    for (int t = 0; t < KNN; t++) { bd[t] = 3.4e38f; bi[t] = 0; }
    for (int j = 0; j < PP; j++) {
        float d = sqi + sq[j] - 2.0f * (xi*sx[j] + yi*sy[j] + zi*sz[j]);
        if (d < bd[KNN-1]) {
            bd[KNN-1] = d; bi[KNN-1] = j;
#pragma unroll
            for (int t = KNN-1; t > 0; t--) {
                if (bd[t] < bd[t-1]) {
                    float td = bd[t]; bd[t] = bd[t-1]; bd[t-1] = td;
                    int ti = bi[t]; bi[t] = bi[t-1]; bi[t-1] = ti;
                }
            }
        }
    }
    int gi = b * PP + il;
#pragma unroll
    for (int t = 0; t < KNN; t++) g_idx[gi*KNN + t] = b * PP + bi[t];
}

// ---------------- EdgeConv1: e=[xi, xj-xi] -> (6->64) -> relu(64->64) -> relu(64->64) -> max_k ----------------
// 256 threads = 8 warps; warp handles one point at a time, 16 points per warp; grid 256 blocks.
__global__ __launch_bounds__(256) void conv1_kernel(
    const float* __restrict__ pos,
    const float* __restrict__ w0, const float* __restrict__ b0,
    const float* __restrict__ w1, const float* __restrict__ b1,
    const float* __restrict__ w2, const float* __restrict__ b2)
{
    __shared__ float sw0[6*64], sw1[64*64], sw2[64*64];
    __shared__ float sb0[64], sb1[64], sb2[64];
    __shared__ float sh0[8][64], sh1[8][64];
    int tid = threadIdx.x;
    for (int r = tid; r < 6*64; r += 256) sw0[r] = w0[r];
    for (int r = tid; r < 64*64; r += 256) { sw1[r] = w1[r]; sw2[r] = w2[r]; }
    if (tid < 64) { sb0[tid] = b0[tid]; sb1[tid] = b1[tid]; sb2[tid] = b2[tid]; }
    __syncthreads();
    int warp = tid >> 5, lane = tid & 31, c0 = lane * 2;
    const float2* sw1v = (const float2*)sw1;
    const float2* sw2v = (const float2*)sw2;
    for (int pi = 0; pi < 16; pi++) {
        int i = blockIdx.x * 128 + pi * 8 + warp;
        float xix = pos[i*3], xiy = pos[i*3+1], xiz = pos[i*3+2];
        // layer0 part that depends only on xi (no relu after layer0 in reference!)
        float base0 = sb0[c0]   + xix*sw0[c0]     + xiy*sw0[64+c0]   + xiz*sw0[128+c0];
        float base1 = sb0[c0+1] + xix*sw0[c0+1]   + xiy*sw0[64+c0+1] + xiz*sw0[128+c0+1];
        float m0 = -3.4e38f, m1 = -3.4e38f;
        for (int n = 0; n < KNN; n++) {
            int j = g_idx[i*KNN + n];
            float dx = pos[j*3]   - xix;
            float dy = pos[j*3+1] - xiy;
            float dz = pos[j*3+2] - xiz;
            float h0a = base0 + dx*sw0[192+c0]   + dy*sw0[256+c0]   + dz*sw0[320+c0];
            float h0b = base1 + dx*sw0[192+c0+1] + dy*sw0[256+c0+1] + dz*sw0[320+c0+1];
            sh0[warp][c0] = h0a; sh0[warp][c0+1] = h0b;
            __syncwarp();
            float a0 = sb1[c0], a1 = sb1[c0+1];
#pragma unroll
            for (int k = 0; k < 64; k++) {
                float h = sh0[warp][k];
                float2 wv = sw1v[k*32 + lane];
                a0 += h * wv.x; a1 += h * wv.y;
            }
            a0 = fmaxf(a0, 0.f); a1 = fmaxf(a1, 0.f);
            __syncwarp();
            sh1[warp][c0] = a0; sh1[warp][c0+1] = a1;
            __syncwarp();
            float gg0 = sb2[c0], gg1 = sb2[c0+1];
#pragma unroll
            for (int k = 0; k < 64; k++) {
                float h = sh1[warp][k];
                float2 wv = sw2v[k*32 + lane];
                gg0 += h * wv.x; gg1 += h * wv.y;
            }
            m0 = fmaxf(m0, fmaxf(gg0, 0.f));
            m1 = fmaxf(m1, fmaxf(gg1, 0.f));
            __syncwarp();
        }
        g_x1[(size_t)i*64 + c0]     = m0;
        g_x1[(size_t)i*64 + c0 + 1] = m1;
    }
}

// ---------------- KNN over 64-D features ----------------
// grid (4, 32). 256 threads, thread = one point (xi in regs), j tiled through SMEM.
__global__ __launch_bounds__(256) void knn_feat_kernel()
{
    extern __shared__ float smem[];
    float4* sj = (float4*)smem;              // 256 rows * 16 float4 = 64 KB
    float*  ssq = smem + 256*64;             // 256 floats
    int b = blockIdx.y;
    int i = b * PP + blockIdx.x * 256 + threadIdx.x;
    const float4* x1v = (const float4*)g_x1;
    float4 xi[16];
#pragma unroll
    for (int q = 0; q < 16; q++) xi[q] = x1v[(size_t)i*16 + q];
    float sqi = 0.f;
#pragma unroll
    for (int q = 0; q < 16; q++)
        sqi += xi[q].x*xi[q].x + xi[q].y*xi[q].y + xi[q].z*xi[q].z + xi[q].w*xi[q].w;
    float bd[KNN]; int bi[KNN];
#pragma unroll
    for (int t = 0; t < KNN; t++) { bd[t] = 3.4e38f; bi[t] = 0; }
    for (int t4 = 0; t4 < 4; t4++) {
        __syncthreads();
        for (int r = threadIdx.x; r < 256*16; r += 256)
            sj[r] = x1v[((size_t)(b*PP + t4*256))*16 + r];
        __syncthreads();
        {
            float s = 0.f;
#pragma unroll
            for (int q = 0; q < 16; q++) {
                float4 v = sj[threadIdx.x*16 + q];
                s += v.x*v.x + v.y*v.y + v.z*v.z + v.w*v.w;
            }
            ssq[threadIdx.x] = s;
        }
        __syncthreads();
        for (int jj = 0; jj < 256; jj++) {
            float dv = 0.f;
#pragma unroll
            for (int q = 0; q < 16; q++) {
                float4 v = sj[jj*16 + q];
                dv += xi[q].x*v.x + xi[q].y*v.y + xi[q].z*v.z + xi[q].w*v.w;
            }
            float d = sqi + ssq[jj] - 2.0f * dv;
            if (d < bd[KNN-1]) {
                bd[KNN-1] = d; bi[KNN-1] = t4*256 + jj;
#pragma unroll
                for (int t = KNN-1; t > 0; t--) {
                    if (bd[t] < bd[t-1]) {
                        float td = bd[t]; bd[t] = bd[t-1]; bd[t-1] = td;
                        int ti = bi[t]; bi[t] = bi[t-1]; bi[t-1] = ti;
                    }
                }
            }
        }
    }
#pragma unroll
    for (int t = 0; t < KNN; t++) g_idx[(size_t)i*KNN + t] = b * PP + bi[t];
}

// ---------------- EdgeConv2: e=[xi, xj-xi] (128) -> relu(128->128) -> max_k ----------------
__global__ __launch_bounds__(256) void conv2_kernel(
    const float* __restrict__ w, const float* __restrict__ bias)
{
    extern __shared__ float smem[];
    float* sw  = smem;                 // 128*128
    float* sbb = smem + 128*128;       // 128
    float* sxi = sbb + 128;            // 8*64
    float* sdx = sxi + 8*64;           // 8*64
    int tid = threadIdx.x;
    for (int r = tid; r < 128*128; r += 256) sw[r] = w[r];
    if (tid < 128) sbb[tid] = bias[tid];
    __syncthreads();
    int warp = tid >> 5, lane = tid & 31;
    const float4* swv = (const float4*)sw;
    float* xib = sxi + warp*64;
    float* dxb = sdx + warp*64;
    for (int pi = 0; pi < 16; pi++) {
        int i = blockIdx.x * 128 + pi * 8 + warp;
        float v0 = g_x1[(size_t)i*64 + lane];
        float v1 = g_x1[(size_t)i*64 + 32 + lane];
        xib[lane] = v0; xib[32+lane] = v1;
        __syncwarp();
        float4 base = ((const float4*)sbb)[lane];
#pragma unroll
        for (int k = 0; k < 64; k++) {
            float xv = xib[k];
            float4 wv = swv[k*32 + lane];
            base.x += xv*wv.x; base.y += xv*wv.y; base.z += xv*wv.z; base.w += xv*wv.w;
        }
        float4 m = make_float4(-3.4e38f, -3.4e38f, -3.4e38f, -3.4e38f);
        for (int n = 0; n < KNN; n++) {
            int j = g_idx[(size_t)i*KNN + n];
            dxb[lane]    = g_x1[(size_t)j*64 + lane]      - v0;
            dxb[32+lane] = g_x1[(size_t)j*64 + 32 + lane] - v1;
            __syncwarp();
            float4 a = base;
#pragma unroll
            for (int k = 0; k < 64; k++) {
                float dv = dxb[k];
                float4 wv = swv[(64+k)*32 + lane];
                a.x += dv*wv.x; a.y += dv*wv.y; a.z += dv*wv.z; a.w += dv*wv.w;
            }
            m.x = fmaxf(m.x, fmaxf(a.x, 0.f));
            m.y = fmaxf(m.y, fmaxf(a.y, 0.f));
            m.z = fmaxf(m.z, fmaxf(a.z, 0.f));
            m.w = fmaxf(m.w, fmaxf(a.w, 0.f));
            __syncwarp();
        }
        ((float4*)g_x2)[(size_t)i*32 + lane] = m;
    }
}

// ---------------- zero the maxpool accumulator ----------------
__global__ void zero_pool_kernel() { g_pool[blockIdx.x*1024 + threadIdx.x] = 0u; }

// ---------------- l1 (192->1024) + relu + max over P, fused via atomicMax on float bits ----------------
// grid (4 otiles of 256, 4 ptiles of 256, 32 batches); 64 threads, thread owns 4 outputs.
__global__ __launch_bounds__(64) void l1max_kernel(
    const float* __restrict__ w, const float* __restrict__ bias)
{
    extern __shared__ float smem[];
    float*  ws = smem;                        // 192*256 floats = 192 KB
    float4* sf = (float4*)(smem + 192*256);   // 16 pts * 48 float4 = 12 KB
    int tid = threadIdx.x;
    int oBase = blockIdx.x * 256;
    int b = blockIdx.z;
    const float4* wv  = (const float4*)w;     // row = 256 float4
    float4*       wsv = (float4*)ws;          // row = 64 float4
    for (int r = tid; r < 192*64; r += 64) {
        int c = r >> 6, oq = r & 63;
        wsv[c*64 + oq] = wv[(size_t)c*256 + (oBase >> 2) + oq];
    }
    __syncthreads();
    float4 bb = ((const float4*)bias)[(oBase >> 2) + tid];
    float4 mx = make_float4(0.f, 0.f, 0.f, 0.f);   // relu >= 0, so 0 is a safe identity
    const float4* x1v = (const float4*)g_x1;
    const float4* x2v = (const float4*)g_x2;
    for (int pt0 = 0; pt0 < 16; pt0++) {
        int pbase = b*PP + blockIdx.y*256 + pt0*16;
        __syncthreads();
        for (int r = tid; r < 16*48; r += 64) {
            int pt = r / 48, q = r % 48;
            float4 v = (q < 16) ? x1v[(size_t)(pbase+pt)*16 + q]
                                : x2v[(size_t)(pbase+pt)*32 + (q-16)];
            sf[pt*48 + q] = v;
        }
        __syncthreads();
        for (int pt = 0; pt < 16; pt++) {
            float4 acc = bb;
            const float4* fr = sf + pt*48;
#pragma unroll
            for (int cq = 0; cq < 48; cq++) {
                float4 f = fr[cq];
                float4 wA = wsv[(4*cq+0)*64 + tid];
                acc.x += f.x*wA.x; acc.y += f.x*wA.y; acc.z += f.x*wA.z; acc.w += f.x*wA.w;
                float4 wB = wsv[(4*cq+1)*64 + tid];
                acc.x += f.y*wB.x; acc.y += f.y*wB.y; acc.z += f.y*wB.z; acc.w += f.y*wB.w;
                float4 wC = wsv[(4*cq+2)*64 + tid];
                acc.x += f.z*wC.x; acc.y += f.z*wC.y; acc.z += f.z*wC.z; acc.w += f.z*wC.w;
                float4 wD = wsv[(4*cq+3)*64 + tid];
                acc.x += f.w*wD.x; acc.y += f.w*wD.y; acc.z += f.w*wD.z; acc.w += f.w*wD.w;
            }
            mx.x = fmaxf(mx.x, acc.x); mx.y = fmaxf(mx.y, acc.y);
            mx.z = fmaxf(mx.z, acc.z); mx.w = fmaxf(mx.w, acc.w);
        }
    }
    int o = oBase + tid*4;
    atomicMax(&g_pool[b*1024 + o + 0], __float_as_uint(mx.x));
    atomicMax(&g_pool[b*1024 + o + 1], __float_as_uint(mx.y));
    atomicMax(&g_pool[b*1024 + o + 2], __float_as_uint(mx.z));
    atomicMax(&g_pool[b*1024 + o + 3], __float_as_uint(mx.w));
}

// ---------------- head: 1024->512 relu ->256 relu ->40 + log_softmax ----------------
__global__ __launch_bounds__(256) void head_kernel(
    const float* __restrict__ w0, const float* __restrict__ b0,
    const float* __restrict__ w1, const float* __restrict__ b1,
    const float* __restrict__ w2, const float* __restrict__ b2,
    float* __restrict__ out)
{
    __shared__ float sp[1024], sh0[512], sh1[256], sl[40], red[2];
    int b = blockIdx.x, tid = threadIdx.x;
    for (int c = tid; c < 1024; c += 256) sp[c] = __uint_as_float(g_pool[b*1024 + c]);
    __syncthreads();
    {
        float a0 = b0[2*tid], a1 = b0[2*tid+1];
        const float2* w0v = (const float2*)w0;
        for (int c = 0; c < 1024; c++) {
            float f = sp[c];
            float2 wv = w0v[c*256 + tid];
            a0 += f * wv.x; a1 += f * wv.y;
        }
        sh0[2*tid]   = fmaxf(a0, 0.f);
        sh0[2*tid+1] = fmaxf(a1, 0.f);
    }
    __syncthreads();
    {
        float a = b1[tid];
        for (int c = 0; c < 512; c++) a += sh0[c] * w1[c*256 + tid];
        sh1[tid] = fmaxf(a, 0.f);
    }
    __syncthreads();
    if (tid < 40) {
        float a = b2[tid];
        for (int c = 0; c < 256; c++) a += sh1[c] * w2[c*40 + tid];
        sl[tid] = a;
    }
    __syncthreads();
    if (tid == 0) {
        float mxv = -3.4e38f;
        for (int t = 0; t < 40; t++) mxv = fmaxf(mxv, sl[t]);
        float s = 0.f;
        for (int t = 0; t < 40; t++) s += expf(sl[t] - mxv);
        red[0] = mxv; red[1] = logf(s);
    }
    __syncthreads();
    if (tid < 40) out[b*40 + tid] = sl[tid] - red[0] - red[1];
}

// ---------------- launch ----------------
extern "C" void kernel_launch(void* const* d_in, const int* in_sizes, int n_in,
                              void* d_out, int out_size)
{
    const float* pos   = (const float*)d_in[0];
    const float* c1_w0 = (const float*)d_in[2];
    const float* c1_b0 = (const float*)d_in[3];
    const float* c1_w1 = (const float*)d_in[4];
    const float* c1_b1 = (const float*)d_in[5];
    const float* c1_w2 = (const float*)d_in[6];
    const float* c1_b2 = (const float*)d_in[7];
    const float* c2_w0 = (const float*)d_in[8];
    const float* c2_b0 = (const float*)d_in[9];
    const float* l1_w  = (const float*)d_in[10];
    const float* l1_b  = (const float*)d_in[11];
    const float* m_w0  = (const float*)d_in[12];
    const float* m_b0  = (const float*)d_in[13];
    const float* m_w1  = (const float*)d_in[14];
    const float* m_b1  = (const float*)d_in[15];
    const float* m_w2  = (const float*)d_in[16];
    const float* m_b2  = (const float*)d_in[17];
    float* out = (float*)d_out;

    const int smem_knn2  = 256*64*4 + 256*4;                       // 66560
    const int smem_conv2 = 128*128*4 + 128*4 + 2*8*64*4;           // 70144
    const int smem_l1    = 192*256*4 + 16*48*16;                   // 208896

    cudaFuncSetAttribute(knn_feat_kernel, cudaFuncAttributeMaxDynamicSharedMemorySize, smem_knn2);
    cudaFuncSetAttribute(conv2_kernel,    cudaFuncAttributeMaxDynamicSharedMemorySize, smem_conv2);
    cudaFuncSetAttribute(l1max_kernel,    cudaFuncAttributeMaxDynamicSharedMemorySize, smem_l1);

    knn_pos_kernel<<<dim3(4, 32), 256>>>(pos);
    conv1_kernel<<<256, 256>>>(pos, c1_w0, c1_b0, c1_w1, c1_b1, c1_w2, c1_b2);
    knn_feat_kernel<<<dim3(4, 32), 256, smem_knn2>>>();
    conv2_kernel<<<256, 256, smem_conv2>>>(c2_w0, c2_b0);
    zero_pool_kernel<<<32, 1024>>>();
    l1max_kernel<<<dim3(4, 4, 32), 64, smem_l1>>>(l1_w, l1_b);
    head_kernel<<<32, 256>>>(m_w0, m_b0, m_w1, m_b1, m_w2, m_b2, out);
}

// round 2
// speedup vs baseline: 10.3957x; 10.3957x over previous
#include <cuda_runtime.h>
#include <math.h>

#define BB 32
#define PP 1024
#define KNN 20
#define NPTS (BB*PP)

// ---------------- scratch (device globals; no allocs allowed) ----------------
__device__ __align__(16) float g_x1[NPTS*64];
__device__ __align__(16) float g_x2[NPTS*128];
__device__ int g_idx[NPTS*KNN];
__device__ unsigned int g_pool[BB*1024];

// ---------------- KNN over 3-D positions ----------------
__global__ __launch_bounds__(256) void knn_pos_kernel(const float* __restrict__ pos)
{
    __shared__ float sx[PP], sy[PP], sz[PP], sq[PP];
    int b = blockIdx.y;
    const float* p = pos + (size_t)b * PP * 3;
    for (int j = threadIdx.x; j < PP; j += 256) {
        float x = p[3*j], y = p[3*j+1], z = p[3*j+2];
        sx[j] = x; sy[j] = y; sz[j] = z; sq[j] = x*x + y*y + z*z;
    }
    __syncthreads();
    int il = blockIdx.x * 256 + threadIdx.x;
    float xi = sx[il], yi = sy[il], zi = sz[il], sqi = sq[il];
    float bd[KNN]; int bi[KNN];
#pragma unroll
    for (int t = 0; t < KNN; t++) { bd[t] = 3.4e38f; bi[t] = 0; }
    for (int j = 0; j < PP; j++) {
        float d = sqi + sq[j] - 2.0f * (xi*sx[j] + yi*sy[j] + zi*sz[j]);
        if (d < bd[KNN-1]) {
            bd[KNN-1] = d; bi[KNN-1] = j;
#pragma unroll
            for (int t = KNN-1; t > 0; t--) {
                if (bd[t] < bd[t-1]) {
                    float td = bd[t]; bd[t] = bd[t-1]; bd[t-1] = td;
                    int ti = bi[t]; bi[t] = bi[t-1]; bi[t-1] = ti;
                }
            }
        }
    }
    int gi = b * PP + il;
#pragma unroll
    for (int t = 0; t < KNN; t++) g_idx[gi*KNN + t] = b * PP + bi[t];
}

// ---------------- EdgeConv1: register-tiled. Warp owns 1 point x 20 edges. ----------------
// 512 blocks x 256 threads (8 warps); each warp does 8 points.
__global__ __launch_bounds__(256) void conv1_kernel(
    const float* __restrict__ pos,
    const float* __restrict__ w0, const float* __restrict__ b0,
    const float* __restrict__ w1, const float* __restrict__ b1,
    const float* __restrict__ w2, const float* __restrict__ b2)
{
    extern __shared__ float sm[];
    float* sw0 = sm;              // 384
    float* sb0 = sm + 384;        // 64
    float* sw1 = sm + 448;        // 4096
    float* sb1 = sm + 4544;       // 64
    float* sw2 = sm + 4608;       // 4096
    float* sb2 = sm + 8704;       // 64
    float* shh = sm + 8768;       // 8 * 1280  (h buffer [64ch][20n] per warp)
    float* se  = sm + 19008;      // 8 * 64    (edge dx,dy,dz [3][20] per warp)

    int tid = threadIdx.x;
    for (int r = tid; r < 384; r += 256) sw0[r] = w0[r];
    for (int r = tid; r < 4096; r += 256) { sw1[r] = w1[r]; sw2[r] = w2[r]; }
    if (tid < 64) { sb0[tid] = b0[tid]; sb1[tid] = b1[tid]; sb2[tid] = b2[tid]; }
    __syncthreads();

    int warp = tid >> 5, lane = tid & 31, c0 = lane * 2;
    float* sh  = shh + warp * 1280;
    float* sew = se  + warp * 64;
    const float2* sw1v = (const float2*)sw1;
    const float2* sw2v = (const float2*)sw2;

    float w0r[6][2];
#pragma unroll
    for (int r = 0; r < 6; r++) { w0r[r][0] = sw0[r*64 + c0]; w0r[r][1] = sw0[r*64 + c0 + 1]; }
    float bb0a = sb0[c0], bb0b = sb0[c0+1];
    float2 bb1 = ((const float2*)sb1)[lane];
    float2 bb2 = ((const float2*)sb2)[lane];

    for (int pi = 0; pi < 8; pi++) {
        int i = blockIdx.x * 64 + pi * 8 + warp;
        float xix = pos[i*3], xiy = pos[i*3+1], xiz = pos[i*3+2];
        if (lane < KNN) {
            int j = g_idx[i*KNN + lane];
            sew[lane]      = pos[j*3]   - xix;
            sew[20 + lane] = pos[j*3+1] - xiy;
            sew[40 + lane] = pos[j*3+2] - xiz;
        }
        __syncwarp();
        // layer0 (no relu): h0[n][c] for this lane's 2 channels
        float basea = fmaf(xix, w0r[0][0], fmaf(xiy, w0r[1][0], fmaf(xiz, w0r[2][0], bb0a)));
        float baseb = fmaf(xix, w0r[0][1], fmaf(xiy, w0r[1][1], fmaf(xiz, w0r[2][1], bb0b)));
#pragma unroll
        for (int n = 0; n < KNN; n++) {
            float dx = sew[n], dy = sew[20+n], dz = sew[40+n];
            sh[c0*20 + n]     = basea + dx*w0r[3][0] + dy*w0r[4][0] + dz*w0r[5][0];
            sh[(c0+1)*20 + n] = baseb + dx*w0r[3][1] + dy*w0r[4][1] + dz*w0r[5][1];
        }
        __syncwarp();
        // GEMM1: h1 = relu(h0 @ W1 + b1), 20 edges at once
        float2 acc[KNN];
#pragma unroll
        for (int n = 0; n < KNN; n++) acc[n] = bb1;
#pragma unroll 4
        for (int k = 0; k < 64; k++) {
            float2 w = sw1v[k*32 + lane];
#pragma unroll
            for (int n = 0; n < KNN; n++) {
                float h = sh[k*20 + n];
                acc[n].x = fmaf(h, w.x, acc[n].x);
                acc[n].y = fmaf(h, w.y, acc[n].y);
            }
        }
        __syncwarp();
#pragma unroll
        for (int n = 0; n < KNN; n++) {
            sh[c0*20 + n]     = fmaxf(acc[n].x, 0.f);
            sh[(c0+1)*20 + n] = fmaxf(acc[n].y, 0.f);
        }
        __syncwarp();
        // GEMM2: h2 = relu(h1 @ W2 + b2), then max over 20 edges
#pragma unroll
        for (int n = 0; n < KNN; n++) acc[n] = bb2;
#pragma unroll 4
        for (int k = 0; k < 64; k++) {
            float2 w = sw2v[k*32 + lane];
#pragma unroll
            for (int n = 0; n < KNN; n++) {
                float h = sh[k*20 + n];
                acc[n].x = fmaf(h, w.x, acc[n].x);
                acc[n].y = fmaf(h, w.y, acc[n].y);
            }
        }
        float m0 = 0.f, m1 = 0.f;   // relu>=0 so 0 is identity; folds relu into max
#pragma unroll
        for (int n = 0; n < KNN; n++) { m0 = fmaxf(m0, acc[n].x); m1 = fmaxf(m1, acc[n].y); }
        ((float2*)g_x1)[(size_t)i*32 + lane] = make_float2(m0, m1);
        __syncwarp();
    }
}

// ---------------- KNN over 64-D features ----------------
__global__ __launch_bounds__(256) void knn_feat_kernel()
{
    extern __shared__ float smem[];
    float4* sj = (float4*)smem;              // 256 rows * 16 float4 = 64 KB
    float*  ssq = smem + 256*64;             // 256 floats
    int b = blockIdx.y;
    int i = b * PP + blockIdx.x * 256 + threadIdx.x;
    const float4* x1v = (const float4*)g_x1;
    float4 xi[16];
#pragma unroll
    for (int q = 0; q < 16; q++) xi[q] = x1v[(size_t)i*16 + q];
    float sqi = 0.f;
#pragma unroll
    for (int q = 0; q < 16; q++)
        sqi += xi[q].x*xi[q].x + xi[q].y*xi[q].y + xi[q].z*xi[q].z + xi[q].w*xi[q].w;
    float bd[KNN]; int bi[KNN];
#pragma unroll
    for (int t = 0; t < KNN; t++) { bd[t] = 3.4e38f; bi[t] = 0; }
    for (int t4 = 0; t4 < 4; t4++) {
        __syncthreads();
        for (int r = threadIdx.x; r < 256*16; r += 256)
            sj[r] = x1v[((size_t)(b*PP + t4*256))*16 + r];
        __syncthreads();
        {
            float s = 0.f;
#pragma unroll
            for (int q = 0; q < 16; q++) {
                float4 v = sj[threadIdx.x*16 + q];
                s += v.x*v.x + v.y*v.y + v.z*v.z + v.w*v.w;
            }
            ssq[threadIdx.x] = s;
        }
        __syncthreads();
        for (int jj = 0; jj < 256; jj++) {
            float dv = 0.f;
#pragma unroll
            for (int q = 0; q < 16; q++) {
                float4 v = sj[jj*16 + q];
                dv += xi[q].x*v.x + xi[q].y*v.y + xi[q].z*v.z + xi[q].w*v.w;
            }
            float d = sqi + ssq[jj] - 2.0f * dv;
            if (d < bd[KNN-1]) {
                bd[KNN-1] = d; bi[KNN-1] = t4*256 + jj;
#pragma unroll
                for (int t = KNN-1; t > 0; t--) {
                    if (bd[t] < bd[t-1]) {
                        float td = bd[t]; bd[t] = bd[t-1]; bd[t-1] = td;
                        int ti = bi[t]; bi[t] = bi[t-1]; bi[t-1] = ti;
                    }
                }
            }
        }
    }
#pragma unroll
    for (int t = 0; t < KNN; t++) g_idx[(size_t)i*KNN + t] = b * PP + bi[t];
}

// ---------------- EdgeConv2: register-tiled. Warp owns 1 point; lane = 4 channels x 10 edges x 2 passes ----------------
__global__ __launch_bounds__(256) void conv2_kernel(
    const float* __restrict__ w, const float* __restrict__ bias)
{
    extern __shared__ float sm[];
    float* sw  = sm;               // 16384 (128x128, [k][out])
    float* sb  = sm + 16384;       // 128
    float* sxi = sm + 16512;       // 8*64
    float* sdx = sm + 17024;       // 8*1280  ([64k][20n] per warp, diff part)
    int tid = threadIdx.x;
    for (int r = tid; r < 16384; r += 256) sw[r] = w[r];
    if (tid < 128) sb[tid] = bias[tid];
    __syncthreads();

    int warp = tid >> 5, lane = tid & 31;
    const float4* swv = (const float4*)sw;
    float* xib = sxi + warp*64;
    float* dxb = sdx + warp*1280;
    float4 bb = ((const float4*)sb)[lane];

    for (int pi = 0; pi < 8; pi++) {
        int i = blockIdx.x * 64 + pi * 8 + warp;
        float v0 = g_x1[(size_t)i*64 + lane];
        float v1 = g_x1[(size_t)i*64 + 32 + lane];
        xib[lane] = v0; xib[32+lane] = v1;
        int jv = 0;
        if (lane < KNN) jv = g_idx[(size_t)i*KNN + lane];
        __syncwarp();
        // base = b + xi @ W[0:64]  (neighbor-invariant half)
        float4 base = bb;
#pragma unroll 8
        for (int k = 0; k < 64; k++) {
            float xv = xib[k];
            float4 wv = swv[k*32 + lane];
            base.x = fmaf(xv, wv.x, base.x); base.y = fmaf(xv, wv.y, base.y);
            base.z = fmaf(xv, wv.z, base.z); base.w = fmaf(xv, wv.w, base.w);
        }
        // gather neighbor diffs into [k][n] smem
#pragma unroll
        for (int n = 0; n < KNN; n++) {
            int j = __shfl_sync(0xffffffff, jv, n);
            dxb[lane*20 + n]      = g_x1[(size_t)j*64 + lane]      - v0;
            dxb[(32+lane)*20 + n] = g_x1[(size_t)j*64 + 32 + lane] - v1;
        }
        __syncwarp();
        float4 m = make_float4(0.f, 0.f, 0.f, 0.f);   // relu identity
#pragma unroll
        for (int pass = 0; pass < 2; pass++) {
            float4 acc[10];
#pragma unroll
            for (int n = 0; n < 10; n++) acc[n] = base;
#pragma unroll 4
            for (int k = 0; k < 64; k++) {
                float4 wv = swv[(64+k)*32 + lane];
#pragma unroll
                for (int n = 0; n < 10; n++) {
                    float d = dxb[k*20 + pass*10 + n];
                    acc[n].x = fmaf(d, wv.x, acc[n].x);
                    acc[n].y = fmaf(d, wv.y, acc[n].y);
                    acc[n].z = fmaf(d, wv.z, acc[n].z);
                    acc[n].w = fmaf(d, wv.w, acc[n].w);
                }
            }
#pragma unroll
            for (int n = 0; n < 10; n++) {
                m.x = fmaxf(m.x, acc[n].x); m.y = fmaxf(m.y, acc[n].y);
                m.z = fmaxf(m.z, acc[n].z); m.w = fmaxf(m.w, acc[n].w);
            }
        }
        ((float4*)g_x2)[(size_t)i*32 + lane] = m;
        __syncwarp();
    }
}

// ---------------- zero the maxpool accumulator ----------------
__global__ void zero_pool_kernel() { g_pool[blockIdx.x*1024 + threadIdx.x] = 0u; }

// ---------------- l1 (192->1024) as tiled GEMM + fused relu + P-max ----------------
// grid (8 n-tiles, 8 m-tiles, 32 batches); 256 threads; 8x8 register tile.
__global__ __launch_bounds__(256) void l1max_kernel(
    const float* __restrict__ w, const float* __restrict__ bias)
{
    __shared__ float As[16][128];
    __shared__ float Bs[16][128];
    __shared__ unsigned int sred[128];
    int tid = threadIdx.x;
    int tx = tid & 15, ty = tid >> 4;
    int b = blockIdx.z;
    int n0 = blockIdx.x * 128, m0 = blockIdx.y * 128;
    int pbase = b * PP + m0;
    const float4* x1v = (const float4*)g_x1;
    const float4* x2v = (const float4*)g_x2;
    const float4* wv  = (const float4*)w;

    float acc[8][8];
#pragma unroll
    for (int i = 0; i < 8; i++)
#pragma unroll
        for (int j = 0; j < 8; j++) acc[i][j] = 0.f;

    for (int ks = 0; ks < 12; ks++) {
        int k0 = ks * 16;
        __syncthreads();
#pragma unroll
        for (int r = 0; r < 2; r++) {            // B tile: [16k][128out]
            int fi = tid + r*256;
            int kk = fi >> 5, colq = fi & 31;
            ((float4*)Bs[kk])[colq] = wv[(size_t)(k0+kk)*256 + (n0>>2) + colq];
        }
#pragma unroll
        for (int r = 0; r < 2; r++) {            // A tile (transposed): [16k][128pt]
            int fi = tid + r*256;
            int pt = fi >> 2, kq = fi & 3;
            float4 v;
            if (k0 < 64) v = x1v[(size_t)(pbase+pt)*16 + (k0>>2) + kq];
            else         v = x2v[(size_t)(pbase+pt)*32 + ((k0-64)>>2) + kq];
            As[kq*4+0][pt] = v.x; As[kq*4+1][pt] = v.y;
            As[kq*4+2][pt] = v.z; As[kq*4+3][pt] = v.w;
        }
        __syncthreads();
#pragma unroll
        for (int kk = 0; kk < 16; kk++) {
            float a[8], bv[8];
            *(float4*)&a[0]  = *(const float4*)&As[kk][ty*8];
            *(float4*)&a[4]  = *(const float4*)&As[kk][ty*8+4];
            *(float4*)&bv[0] = *(const float4*)&Bs[kk][tx*8];
            *(float4*)&bv[4] = *(const float4*)&Bs[kk][tx*8+4];
#pragma unroll
            for (int i = 0; i < 8; i++)
#pragma unroll
                for (int j = 0; j < 8; j++)
                    acc[i][j] = fmaf(a[i], bv[j], acc[i][j]);
        }
    }
    float bias8[8];
    *(float4*)&bias8[0] = ((const float4*)bias)[(n0>>2) + tx*2];
    *(float4*)&bias8[4] = ((const float4*)bias)[(n0>>2) + tx*2 + 1];
    float cm[8];
#pragma unroll
    for (int j = 0; j < 8; j++) {
        float m = 0.f;                    // relu identity
#pragma unroll
        for (int i = 0; i < 8; i++) m = fmaxf(m, acc[i][j] + bias8[j]);
        cm[j] = m;
    }
    if (tid < 128) sred[tid] = 0u;
    __syncthreads();
#pragma unroll
    for (int j = 0; j < 8; j++) atomicMax(&sred[tx*8 + j], __float_as_uint(cm[j]));
    __syncthreads();
    if (tid < 128) atomicMax(&g_pool[b*1024 + n0 + tid], sred[tid]);
}

// ---------------- head: 1024->512 relu ->256 relu ->40 + log_softmax ----------------
__global__ __launch_bounds__(256) void head_kernel(
    const float* __restrict__ w0, const float* __restrict__ b0,
    const float* __restrict__ w1, const float* __restrict__ b1,
    const float* __restrict__ w2, const float* __restrict__ b2,
    float* __restrict__ out)
{
    __shared__ float sp[1024], sh0[512], sh1[256], sl[40], red[2];
    int b = blockIdx.x, tid = threadIdx.x;
    for (int c = tid; c < 1024; c += 256) sp[c] = __uint_as_float(g_pool[b*1024 + c]);
    __syncthreads();
    {
        float a0 = b0[2*tid], a1 = b0[2*tid+1];
        const float2* w0v = (const float2*)w0;
        for (int c = 0; c < 1024; c++) {
            float f = sp[c];
            float2 wv = w0v[c*256 + tid];
            a0 += f * wv.x; a1 += f * wv.y;
        }
        sh0[2*tid]   = fmaxf(a0, 0.f);
        sh0[2*tid+1] = fmaxf(a1, 0.f);
    }
    __syncthreads();
    {
        float a = b1[tid];
        for (int c = 0; c < 512; c++) a += sh0[c] * w1[c*256 + tid];
        sh1[tid] = fmaxf(a, 0.f);
    }
    __syncthreads();
    if (tid < 40) {
        float a = b2[tid];
        for (int c = 0; c < 256; c++) a += sh1[c] * w2[c*40 + tid];
        sl[tid] = a;
    }
    __syncthreads();
    if (tid == 0) {
        float mxv = -3.4e38f;
        for (int t = 0; t < 40; t++) mxv = fmaxf(mxv, sl[t]);
        float s = 0.f;
        for (int t = 0; t < 40; t++) s += expf(sl[t] - mxv);
        red[0] = mxv; red[1] = logf(s);
    }
    __syncthreads();
    if (tid < 40) out[b*40 + tid] = sl[tid] - red[0] - red[1];
}

// ---------------- launch ----------------
extern "C" void kernel_launch(void* const* d_in, const int* in_sizes, int n_in,
                              void* d_out, int out_size)
{
    const float* pos   = (const float*)d_in[0];
    const float* c1_w0 = (const float*)d_in[2];
    const float* c1_b0 = (const float*)d_in[3];
    const float* c1_w1 = (const float*)d_in[4];
    const float* c1_b1 = (const float*)d_in[5];
    const float* c1_w2 = (const float*)d_in[6];
    const float* c1_b2 = (const float*)d_in[7];
    const float* c2_w0 = (const float*)d_in[8];
    const float* c2_b0 = (const float*)d_in[9];
    const float* l1_w  = (const float*)d_in[10];
    const float* l1_b  = (const float*)d_in[11];
    const float* m_w0  = (const float*)d_in[12];
    const float* m_b0  = (const float*)d_in[13];
    const float* m_w1  = (const float*)d_in[14];
    const float* m_b1  = (const float*)d_in[15];
    const float* m_w2  = (const float*)d_in[16];
    const float* m_b2  = (const float*)d_in[17];
    float* out = (float*)d_out;

    const int smem_conv1 = (19008 + 8*64) * 4;          // 77952
    const int smem_knn2  = 256*64*4 + 256*4;            // 66560
    const int smem_conv2 = (17024 + 8*1280) * 4;        // 109056

    cudaFuncSetAttribute(conv1_kernel,    cudaFuncAttributeMaxDynamicSharedMemorySize, smem_conv1);
    cudaFuncSetAttribute(knn_feat_kernel, cudaFuncAttributeMaxDynamicSharedMemorySize, smem_knn2);
    cudaFuncSetAttribute(conv2_kernel,    cudaFuncAttributeMaxDynamicSharedMemorySize, smem_conv2);

    knn_pos_kernel<<<dim3(4, 32), 256>>>(pos);
    conv1_kernel<<<512, 256, smem_conv1>>>(pos, c1_w0, c1_b0, c1_w1, c1_b1, c1_w2, c1_b2);
    knn_feat_kernel<<<dim3(4, 32), 256, smem_knn2>>>();
    conv2_kernel<<<512, 256, smem_conv2>>>(c2_w0, c2_b0);
    zero_pool_kernel<<<32, 1024>>>();
    l1max_kernel<<<dim3(8, 8, 32), 256>>>(l1_w, l1_b);
    head_kernel<<<32, 256>>>(m_w0, m_b0, m_w1, m_b1, m_w2, m_b2, out);
}

// round 3
// speedup vs baseline: 11.8857x; 1.1433x over previous
#include <cuda_runtime.h>
#include <math.h>
#include <stdint.h>

#define BB 32
#define PP 1024
#define KNN 20
#define NPTS (BB*PP)

// ---------------- scratch (device globals; no allocs allowed) ----------------
__device__ __align__(16) float g_x1[NPTS*64];
__device__ __align__(16) float g_x2[NPTS*128];
__device__ int g_idx[NPTS*KNN];
__device__ unsigned int g_pool[BB*1024];

// ---------------- tf32 mma helpers ----------------
__device__ __forceinline__ uint32_t f2tf(float x) {
    uint32_t r; asm("cvt.rna.tf32.f32 %0, %1;" : "=r"(r) : "f"(x)); return r;
}
__device__ __forceinline__ float tfbits(float x) {
    return __uint_as_float(f2tf(x));
}
__device__ __forceinline__ void mma8(float& c0, float& c1, float& c2, float& c3,
                                     uint32_t a0, uint32_t a1, uint32_t a2, uint32_t a3,
                                     uint32_t b0, uint32_t b1)
{
    asm volatile("mma.sync.aligned.m16n8k8.row.col.f32.tf32.tf32.f32 "
                 "{%0,%1,%2,%3},{%4,%5,%6,%7},{%8,%9},{%0,%1,%2,%3};"
                 : "+f"(c0), "+f"(c1), "+f"(c2), "+f"(c3)
                 : "r"(a0), "r"(a1), "r"(a2), "r"(a3), "r"(b0), "r"(b1));
}

// ---------------- KNN over 3-D positions (exact fp32) ----------------
__global__ __launch_bounds__(256) void knn_pos_kernel(const float* __restrict__ pos)
{
    __shared__ float sx[PP], sy[PP], sz[PP], sq[PP];
    int b = blockIdx.y;
    const float* p = pos + (size_t)b * PP * 3;
    for (int j = threadIdx.x; j < PP; j += 256) {
        float x = p[3*j], y = p[3*j+1], z = p[3*j+2];
        sx[j] = x; sy[j] = y; sz[j] = z; sq[j] = x*x + y*y + z*z;
    }
    __syncthreads();
    int il = blockIdx.x * 256 + threadIdx.x;
    float xi = sx[il], yi = sy[il], zi = sz[il], sqi = sq[il];
    float bd[KNN]; int bi[KNN];
#pragma unroll
    for (int t = 0; t < KNN; t++) { bd[t] = 3.4e38f; bi[t] = 0; }
    for (int j = 0; j < PP; j++) {
        float d = sqi + sq[j] - 2.0f * (xi*sx[j] + yi*sy[j] + zi*sz[j]);
        if (d < bd[KNN-1]) {
            bd[KNN-1] = d; bi[KNN-1] = j;
#pragma unroll
            for (int t = KNN-1; t > 0; t--) {
                if (bd[t] < bd[t-1]) {
                    float td = bd[t]; bd[t] = bd[t-1]; bd[t-1] = td;
                    int ti = bi[t]; bi[t] = bi[t-1]; bi[t-1] = ti;
                }
            }
        }
    }
    int gi = b * PP + il;
#pragma unroll
    for (int t = 0; t < KNN; t++) g_idx[gi*KNN + t] = b * PP + bi[t];
}

// ---------------- EdgeConv1: exact fp32 SIMT, vectorized h reads ----------------
__global__ __launch_bounds__(256) void conv1_kernel(
    const float* __restrict__ pos,
    const float* __restrict__ w0, const float* __restrict__ b0,
    const float* __restrict__ w1, const float* __restrict__ b1,
    const float* __restrict__ w2, const float* __restrict__ b2)
{
    extern __shared__ float sm[];
    float* sw0 = sm;              // 384
    float* sb0 = sm + 384;        // 64
    float* sw1 = sm + 448;        // 4096
    float* sb1 = sm + 4544;       // 64
    float* sw2 = sm + 4608;       // 4096
    float* sb2 = sm + 8704;       // 64
    float* shh = sm + 8768;       // 8 * 1280  (h buffer [64ch][20n] per warp)
    float* se  = sm + 19008;      // 8 * 64    (edge dx,dy,dz per warp)

    int tid = threadIdx.x;
    for (int r = tid; r < 384; r += 256) sw0[r] = w0[r];
    for (int r = tid; r < 4096; r += 256) { sw1[r] = w1[r]; sw2[r] = w2[r]; }
    if (tid < 64) { sb0[tid] = b0[tid]; sb1[tid] = b1[tid]; sb2[tid] = b2[tid]; }
    __syncthreads();

    int warp = tid >> 5, lane = tid & 31, c0 = lane * 2;
    float* sh  = shh + warp * 1280;
    float* sew = se  + warp * 64;
    const float2* sw1v = (const float2*)sw1;
    const float2* sw2v = (const float2*)sw2;

    float w0r[6][2];
#pragma unroll
    for (int r = 0; r < 6; r++) { w0r[r][0] = sw0[r*64 + c0]; w0r[r][1] = sw0[r*64 + c0 + 1]; }
    float bb0a = sb0[c0], bb0b = sb0[c0+1];
    float2 bb1 = ((const float2*)sb1)[lane];
    float2 bb2 = ((const float2*)sb2)[lane];

    for (int pi = 0; pi < 8; pi++) {
        int i = blockIdx.x * 64 + pi * 8 + warp;
        float xix = pos[i*3], xiy = pos[i*3+1], xiz = pos[i*3+2];
        if (lane < KNN) {
            int j = g_idx[i*KNN + lane];
            sew[lane]      = pos[j*3]   - xix;
            sew[20 + lane] = pos[j*3+1] - xiy;
            sew[40 + lane] = pos[j*3+2] - xiz;
        }
        __syncwarp();
        float basea = fmaf(xix, w0r[0][0], fmaf(xiy, w0r[1][0], fmaf(xiz, w0r[2][0], bb0a)));
        float baseb = fmaf(xix, w0r[0][1], fmaf(xiy, w0r[1][1], fmaf(xiz, w0r[2][1], bb0b)));
#pragma unroll
        for (int n = 0; n < KNN; n++) {
            float dx = sew[n], dy = sew[20+n], dz = sew[40+n];
            sh[c0*20 + n]     = basea + dx*w0r[3][0] + dy*w0r[4][0] + dz*w0r[5][0];
            sh[(c0+1)*20 + n] = baseb + dx*w0r[3][1] + dy*w0r[4][1] + dz*w0r[5][1];
        }
        __syncwarp();
        // GEMM1
        float2 acc[KNN];
#pragma unroll
        for (int n = 0; n < KNN; n++) acc[n] = bb1;
#pragma unroll 2
        for (int k = 0; k < 64; k++) {
            float2 w = sw1v[k*32 + lane];
            float h[20];
            const float4* h4 = (const float4*)(sh + k*20);
            *(float4*)&h[0]  = h4[0]; *(float4*)&h[4]  = h4[1];
            *(float4*)&h[8]  = h4[2]; *(float4*)&h[12] = h4[3];
            *(float4*)&h[16] = h4[4];
#pragma unroll
            for (int n = 0; n < KNN; n++) {
                acc[n].x = fmaf(h[n], w.x, acc[n].x);
                acc[n].y = fmaf(h[n], w.y, acc[n].y);
            }
        }
        __syncwarp();
#pragma unroll
        for (int n = 0; n < KNN; n++) {
            sh[c0*20 + n]     = fmaxf(acc[n].x, 0.f);
            sh[(c0+1)*20 + n] = fmaxf(acc[n].y, 0.f);
        }
        __syncwarp();
        // GEMM2
#pragma unroll
        for (int n = 0; n < KNN; n++) acc[n] = bb2;
#pragma unroll 2
        for (int k = 0; k < 64; k++) {
            float2 w = sw2v[k*32 + lane];
            float h[20];
            const float4* h4 = (const float4*)(sh + k*20);
            *(float4*)&h[0]  = h4[0]; *(float4*)&h[4]  = h4[1];
            *(float4*)&h[8]  = h4[2]; *(float4*)&h[12] = h4[3];
            *(float4*)&h[16] = h4[4];
#pragma unroll
            for (int n = 0; n < KNN; n++) {
                acc[n].x = fmaf(h[n], w.x, acc[n].x);
                acc[n].y = fmaf(h[n], w.y, acc[n].y);
            }
        }
        float m0 = 0.f, m1 = 0.f;
#pragma unroll
        for (int n = 0; n < KNN; n++) { m0 = fmaxf(m0, acc[n].x); m1 = fmaxf(m1, acc[n].y); }
        ((float2*)g_x1)[(size_t)i*32 + lane] = make_float2(m0, m1);
        __syncwarp();
    }
}

// ---------------- KNN over 64-D features (exact fp32) ----------------
__global__ __launch_bounds__(256) void knn_feat_kernel()
{
    extern __shared__ float smem[];
    float4* sj = (float4*)smem;
    float*  ssq = smem + 256*64;
    int b = blockIdx.y;
    int i = b * PP + blockIdx.x * 256 + threadIdx.x;
    const float4* x1v = (const float4*)g_x1;
    float4 xi[16];
#pragma unroll
    for (int q = 0; q < 16; q++) xi[q] = x1v[(size_t)i*16 + q];
    float sqi = 0.f;
#pragma unroll
    for (int q = 0; q < 16; q++)
        sqi += xi[q].x*xi[q].x + xi[q].y*xi[q].y + xi[q].z*xi[q].z + xi[q].w*xi[q].w;
    float bd[KNN]; int bi[KNN];
#pragma unroll
    for (int t = 0; t < KNN; t++) { bd[t] = 3.4e38f; bi[t] = 0; }
    for (int t4 = 0; t4 < 4; t4++) {
        __syncthreads();
        for (int r = threadIdx.x; r < 256*16; r += 256)
            sj[r] = x1v[((size_t)(b*PP + t4*256))*16 + r];
        __syncthreads();
        {
            float s = 0.f;
#pragma unroll
            for (int q = 0; q < 16; q++) {
                float4 v = sj[threadIdx.x*16 + q];
                s += v.x*v.x + v.y*v.y + v.z*v.z + v.w*v.w;
            }
            ssq[threadIdx.x] = s;
        }
        __syncthreads();
        for (int jj = 0; jj < 256; jj++) {
            float dv = 0.f;
#pragma unroll
            for (int q = 0; q < 16; q++) {
                float4 v = sj[jj*16 + q];
                dv += xi[q].x*v.x + xi[q].y*v.y + xi[q].z*v.z + xi[q].w*v.w;
            }
            float d = sqi + ssq[jj] - 2.0f * dv;
            if (d < bd[KNN-1]) {
                bd[KNN-1] = d; bi[KNN-1] = t4*256 + jj;
#pragma unroll
                for (int t = KNN-1; t > 0; t--) {
                    if (bd[t] < bd[t-1]) {
                        float td = bd[t]; bd[t] = bd[t-1]; bd[t-1] = td;
                        int ti = bi[t]; bi[t] = bi[t-1]; bi[t-1] = ti;
                    }
                }
            }
        }
    }
#pragma unroll
    for (int t = 0; t < KNN; t++) g_idx[(size_t)i*KNN + t] = b * PP + bi[t];
}

// ---------------- EdgeConv2: tf32 tensor-core GEMM over edge matrix ----------------
// 1024 blocks x 4 groups of 8 points. D[160 edges][128 feat] x W[128][128].
#define C2_LDD 132
#define C2_LDW 136
__global__ __launch_bounds__(256) void conv2_kernel(
    const float* __restrict__ w, const float* __restrict__ bias)
{
    extern __shared__ float sm[];
    float* sW    = sm;                        // 128*136
    float* sD    = sm + 128*C2_LDW;           // 160*132
    float* sXi   = sD + 160*C2_LDD;           // 8*64
    float* sbias = sXi + 8*64;                // 128

    int tid = threadIdx.x;
    int lane = tid & 31, warp = tid >> 5;
    int g4 = lane >> 2, tig = lane & 3;

    // stage W (tf32) + bias once per block
    for (int fi = tid; fi < 4096; fi += 256) {
        int kk = fi >> 5, nq = fi & 31;
        float4 v = ((const float4*)w)[kk*32 + nq];
        float4 t = make_float4(tfbits(v.x), tfbits(v.y), tfbits(v.z), tfbits(v.w));
        *(float4*)&sW[kk*C2_LDW + nq*4] = t;
    }
    if (tid < 128) sbias[tid] = bias[tid];

    int wm = warp >> 2, wn = warp & 3;
    int mB = wm*80, nB = wn*32;
    const float4* x1v = (const float4*)g_x1;

    for (int gi = 0; gi < 4; gi++) {
        int ibase = (blockIdx.x*4 + gi) * 8;
        __syncthreads();
        if (tid < 128) {
            int p = tid >> 4, q = tid & 15;
            ((float4*)&sXi[p*64])[q] = x1v[(size_t)(ibase+p)*16 + q];
        }
        __syncthreads();
        // build D: rows = 8 pts x 20 edges; cols 0..63 = tf32(xi), 64..127 = tf32(xj-xi)
        if (tid < 160) {
            int p = tid/20, e = tid - p*20;
            int j = g_idx[(size_t)(ibase+p)*KNN + e];
            float* drow = sD + tid*C2_LDD;
            const float4* xiv = (const float4*)&sXi[p*64];
#pragma unroll 4
            for (int q = 0; q < 16; q++) {
                float4 xj = x1v[(size_t)j*16 + q];
                float4 xi = xiv[q];
                float4 ta = make_float4(tfbits(xi.x), tfbits(xi.y), tfbits(xi.z), tfbits(xi.w));
                float4 tb = make_float4(tfbits(xj.x-xi.x), tfbits(xj.y-xi.y),
                                        tfbits(xj.z-xi.z), tfbits(xj.w-xi.w));
                *(float4*)&drow[q*4]      = ta;
                *(float4*)&drow[64 + q*4] = tb;
            }
        }
        __syncthreads();
        // mma: warp tile M=80 (5x m16), N=32 (4x n8), K=128 (16 k-steps)
        float acc[5][4][4];
#pragma unroll
        for (int mi = 0; mi < 5; mi++)
#pragma unroll
            for (int ni = 0; ni < 4; ni++)
#pragma unroll
                for (int c = 0; c < 4; c++) acc[mi][ni][c] = 0.f;
#pragma unroll 1
        for (int ks = 0; ks < 16; ks++) {
            int k0 = ks*8;
            uint32_t A[5][4];
#pragma unroll
            for (int mi = 0; mi < 5; mi++) {
                int row = mB + mi*16 + g4;
                A[mi][0] = __float_as_uint(sD[row*C2_LDD + k0 + tig]);
                A[mi][1] = __float_as_uint(sD[(row+8)*C2_LDD + k0 + tig]);
                A[mi][2] = __float_as_uint(sD[row*C2_LDD + k0 + tig + 4]);
                A[mi][3] = __float_as_uint(sD[(row+8)*C2_LDD + k0 + tig + 4]);
            }
            uint32_t Bf[4][2];
#pragma unroll
            for (int ni = 0; ni < 4; ni++) {
                int col = nB + ni*8 + g4;
                Bf[ni][0] = __float_as_uint(sW[(k0+tig)*C2_LDW + col]);
                Bf[ni][1] = __float_as_uint(sW[(k0+tig+4)*C2_LDW + col]);
            }
#pragma unroll
            for (int mi = 0; mi < 5; mi++)
#pragma unroll
                for (int ni = 0; ni < 4; ni++)
                    mma8(acc[mi][ni][0], acc[mi][ni][1], acc[mi][ni][2], acc[mi][ni][3],
                         A[mi][0], A[mi][1], A[mi][2], A[mi][3], Bf[ni][0], Bf[ni][1]);
        }
        __syncthreads();
        // write C back into sD
#pragma unroll
        for (int mi = 0; mi < 5; mi++) {
#pragma unroll
            for (int ni = 0; ni < 4; ni++) {
                int row = mB + mi*16 + g4, col = nB + ni*8 + tig*2;
                *(float2*)&sD[row*C2_LDD + col]     = make_float2(acc[mi][ni][0], acc[mi][ni][1]);
                *(float2*)&sD[(row+8)*C2_LDD + col] = make_float2(acc[mi][ni][2], acc[mi][ni][3]);
            }
        }
        __syncthreads();
        // reduce over 20 edges, + bias, relu, store x2
        {
            int p = tid >> 5, cq = tid & 31;
            float4 m = make_float4(-3.4e38f, -3.4e38f, -3.4e38f, -3.4e38f);
#pragma unroll 4
            for (int e = 0; e < KNN; e++) {
                float4 v = *(float4*)&sD[(p*20+e)*C2_LDD + cq*4];
                m.x = fmaxf(m.x, v.x); m.y = fmaxf(m.y, v.y);
                m.z = fmaxf(m.z, v.z); m.w = fmaxf(m.w, v.w);
            }
            float4 bbv = *(float4*)&sbias[cq*4];
            m.x = fmaxf(m.x + bbv.x, 0.f); m.y = fmaxf(m.y + bbv.y, 0.f);
            m.z = fmaxf(m.z + bbv.z, 0.f); m.w = fmaxf(m.w + bbv.w, 0.f);
            ((float4*)g_x2)[(size_t)(ibase+p)*32 + cq] = m;
        }
    }
}

// ---------------- zero the maxpool accumulator ----------------
__global__ void zero_pool_kernel() { g_pool[blockIdx.x*1024 + threadIdx.x] = 0u; }

// ---------------- l1 (192->1024) tf32 GEMM + fused relu + P-max ----------------
// grid (8 n-tiles, 8 m-tiles, 32 batches); 256 threads; warp tile 64x32.
__global__ __launch_bounds__(256) void l1max_kernel(
    const float* __restrict__ w, const float* __restrict__ bias)
{
    __shared__ float sA[128*20];
    __shared__ float sB[16*136];
    __shared__ float sbias[128];
    __shared__ unsigned int sred[128];
    int tid = threadIdx.x;
    int lane = tid & 31, warp = tid >> 5;
    int g4 = lane >> 2, tig = lane & 3;
    int b = blockIdx.z;
    int n0 = blockIdx.x * 128, m0 = blockIdx.y * 128;
    int pbase = b * PP + m0;
    const float4* x1v = (const float4*)g_x1;
    const float4* x2v = (const float4*)g_x2;
    const float4* wv  = (const float4*)w;
    if (tid < 128) { sred[tid] = 0u; sbias[tid] = bias[n0 + tid]; }

    int wm = warp >> 2, wn = warp & 3;
    float acc[4][4][4];
#pragma unroll
    for (int mi = 0; mi < 4; mi++)
#pragma unroll
        for (int ni = 0; ni < 4; ni++)
#pragma unroll
            for (int c = 0; c < 4; c++) acc[mi][ni][c] = 0.f;

    for (int ks = 0; ks < 12; ks++) {
        __syncthreads();
#pragma unroll
        for (int r = 0; r < 2; r++) {                // A chunk [128 pts][16 k]
            int fi = tid*2 + r;
            int pt = fi >> 2, kq = fi & 3;
            float4 v = (ks < 4) ? x1v[(size_t)(pbase+pt)*16 + ks*4 + kq]
                                : x2v[(size_t)(pbase+pt)*32 + (ks-4)*4 + kq];
            float4 t = make_float4(tfbits(v.x), tfbits(v.y), tfbits(v.z), tfbits(v.w));
            *(float4*)&sA[pt*20 + kq*4] = t;
        }
#pragma unroll
        for (int r = 0; r < 2; r++) {                // B chunk [16 k][128 out]
            int fi = tid*2 + r;
            int kk = fi >> 5, nq = fi & 31;
            float4 v = wv[(size_t)(ks*16+kk)*256 + (n0>>2) + nq];
            float4 t = make_float4(tfbits(v.x), tfbits(v.y), tfbits(v.z), tfbits(v.w));
            *(float4*)&sB[kk*136 + nq*4] = t;
        }
        __syncthreads();
#pragma unroll
        for (int kh = 0; kh < 2; kh++) {
            int k0 = kh*8;
            uint32_t A[4][4];
#pragma unroll
            for (int mi = 0; mi < 4; mi++) {
                int row = wm*64 + mi*16 + g4;
                A[mi][0] = __float_as_uint(sA[row*20 + k0 + tig]);
                A[mi][1] = __float_as_uint(sA[(row+8)*20 + k0 + tig]);
                A[mi][2] = __float_as_uint(sA[row*20 + k0 + tig + 4]);
                A[mi][3] = __float_as_uint(sA[(row+8)*20 + k0 + tig + 4]);
            }
            uint32_t Bf[4][2];
#pragma unroll
            for (int ni = 0; ni < 4; ni++) {
                int col = wn*32 + ni*8 + g4;
                Bf[ni][0] = __float_as_uint(sB[(k0+tig)*136 + col]);
                Bf[ni][1] = __float_as_uint(sB[(k0+tig+4)*136 + col]);
            }
#pragma unroll
            for (int mi = 0; mi < 4; mi++)
#pragma unroll
                for (int ni = 0; ni < 4; ni++)
                    mma8(acc[mi][ni][0], acc[mi][ni][1], acc[mi][ni][2], acc[mi][ni][3],
                         A[mi][0], A[mi][1], A[mi][2], A[mi][3], Bf[ni][0], Bf[ni][1]);
        }
    }
    // epilogue: max over rows (points), + bias, relu, atomicMax
#pragma unroll
    for (int ni = 0; ni < 4; ni++) {
        float v0 = -3.4e38f, v1 = -3.4e38f;
#pragma unroll
        for (int mi = 0; mi < 4; mi++) {
            v0 = fmaxf(v0, fmaxf(acc[mi][ni][0], acc[mi][ni][2]));
            v1 = fmaxf(v1, fmaxf(acc[mi][ni][1], acc[mi][ni][3]));
        }
#pragma unroll
        for (int off = 4; off < 32; off <<= 1) {
            v0 = fmaxf(v0, __shfl_xor_sync(0xffffffff, v0, off));
            v1 = fmaxf(v1, __shfl_xor_sync(0xffffffff, v1, off));
        }
        if (g4 == 0) {
            int col = wn*32 + ni*8 + tig*2;
            float a0 = fmaxf(v0 + sbias[col], 0.f);
            float a1 = fmaxf(v1 + sbias[col+1], 0.f);
            atomicMax(&sred[col],   __float_as_uint(a0));
            atomicMax(&sred[col+1], __float_as_uint(a1));
        }
    }
    __syncthreads();
    if (tid < 128) atomicMax(&g_pool[b*1024 + n0 + tid], sred[tid]);
}

// ---------------- head: 1024->512 relu ->256 relu ->40 + log_softmax ----------------
__global__ __launch_bounds__(256) void head_kernel(
    const float* __restrict__ w0, const float* __restrict__ b0,
    const float* __restrict__ w1, const float* __restrict__ b1,
    const float* __restrict__ w2, const float* __restrict__ b2,
    float* __restrict__ out)
{
    __shared__ float sp[1024], sh0[512], sh1[256], sl[40], red[2];
    int b = blockIdx.x, tid = threadIdx.x;
    for (int c = tid; c < 1024; c += 256) sp[c] = __uint_as_float(g_pool[b*1024 + c]);
    __syncthreads();
    {
        float a0 = b0[2*tid], a1 = b0[2*tid+1];
        const float2* w0v = (const float2*)w0;
        for (int c = 0; c < 1024; c++) {
            float f = sp[c];
            float2 wvv = w0v[c*256 + tid];
            a0 += f * wvv.x; a1 += f * wvv.y;
        }
        sh0[2*tid]   = fmaxf(a0, 0.f);
        sh0[2*tid+1] = fmaxf(a1, 0.f);
    }
    __syncthreads();
    {
        float a = b1[tid];
        for (int c = 0; c < 512; c++) a += sh0[c] * w1[c*256 + tid];
        sh1[tid] = fmaxf(a, 0.f);
    }
    __syncthreads();
    if (tid < 40) {
        float a = b2[tid];
        for (int c = 0; c < 256; c++) a += sh1[c] * w2[c*40 + tid];
        sl[tid] = a;
    }
    __syncthreads();
    if (tid == 0) {
        float mxv = -3.4e38f;
        for (int t = 0; t < 40; t++) mxv = fmaxf(mxv, sl[t]);
        float s = 0.f;
        for (int t = 0; t < 40; t++) s += expf(sl[t] - mxv);
        red[0] = mxv; red[1] = logf(s);
    }
    __syncthreads();
    if (tid < 40) out[b*40 + tid] = sl[tid] - red[0] - red[1];
}

// ---------------- launch ----------------
extern "C" void kernel_launch(void* const* d_in, const int* in_sizes, int n_in,
                              void* d_out, int out_size)
{
    const float* pos   = (const float*)d_in[0];
    const float* c1_w0 = (const float*)d_in[2];
    const float* c1_b0 = (const float*)d_in[3];
    const float* c1_w1 = (const float*)d_in[4];
    const float* c1_b1 = (const float*)d_in[5];
    const float* c1_w2 = (const float*)d_in[6];
    const float* c1_b2 = (const float*)d_in[7];
    const float* c2_w0 = (const float*)d_in[8];
    const float* c2_b0 = (const float*)d_in[9];
    const float* l1_w  = (const float*)d_in[10];
    const float* l1_b  = (const float*)d_in[11];
    const float* m_w0  = (const float*)d_in[12];
    const float* m_b0  = (const float*)d_in[13];
    const float* m_w1  = (const float*)d_in[14];
    const float* m_b1  = (const float*)d_in[15];
    const float* m_w2  = (const float*)d_in[16];
    const float* m_b2  = (const float*)d_in[17];
    float* out = (float*)d_out;

    const int smem_conv1 = (19008 + 8*64) * 4;                               // 77952
    const int smem_knn2  = 256*64*4 + 256*4;                                 // 66560
    const int smem_conv2 = (128*C2_LDW + 160*C2_LDD + 8*64 + 128) * 4;       // 156672

    cudaFuncSetAttribute(conv1_kernel,    cudaFuncAttributeMaxDynamicSharedMemorySize, smem_conv1);
    cudaFuncSetAttribute(knn_feat_kernel, cudaFuncAttributeMaxDynamicSharedMemorySize, smem_knn2);
    cudaFuncSetAttribute(conv2_kernel,    cudaFuncAttributeMaxDynamicSharedMemorySize, smem_conv2);

    knn_pos_kernel<<<dim3(4, 32), 256>>>(pos);
    conv1_kernel<<<512, 256, smem_conv1>>>(pos, c1_w0, c1_b0, c1_w1, c1_b1, c1_w2, c1_b2);
    knn_feat_kernel<<<dim3(4, 32), 256, smem_knn2>>>();
    conv2_kernel<<<1024, 256, smem_conv2>>>(c2_w0, c2_b0);
    zero_pool_kernel<<<32, 1024>>>();
    l1max_kernel<<<dim3(8, 8, 32), 256>>>(l1_w, l1_b);
    head_kernel<<<32, 256>>>(m_w0, m_b0, m_w1, m_b1, m_w2, m_b2, out);
}

// round 4
// speedup vs baseline: 13.6052x; 1.1447x over previous
#include <cuda_runtime.h>
#include <math.h>
#include <stdint.h>

#define BB 32
#define PP 1024
#define KNN 20
#define NPTS (BB*PP)

// ---------------- scratch (device globals; no allocs allowed) ----------------
__device__ __align__(16) float g_x1[NPTS*64];
__device__ __align__(16) float g_x2[NPTS*128];
__device__ int g_idx[NPTS*KNN];
__device__ unsigned int g_pool[BB*1024];

// ---------------- tf32 mma helpers ----------------
__device__ __forceinline__ uint32_t f2tf(float x) {
    uint32_t r; asm("cvt.rna.tf32.f32 %0, %1;" : "=r"(r) : "f"(x)); return r;
}
__device__ __forceinline__ float tfbits(float x) {
    return __uint_as_float(f2tf(x));
}
__device__ __forceinline__ void mma8(float& c0, float& c1, float& c2, float& c3,
                                     uint32_t a0, uint32_t a1, uint32_t a2, uint32_t a3,
                                     uint32_t b0, uint32_t b1)
{
    asm volatile("mma.sync.aligned.m16n8k8.row.col.f32.tf32.tf32.f32 "
                 "{%0,%1,%2,%3},{%4,%5,%6,%7},{%8,%9},{%0,%1,%2,%3};"
                 : "+f"(c0), "+f"(c1), "+f"(c2), "+f"(c3)
                 : "r"(a0), "r"(a1), "r"(a2), "r"(a3), "r"(b0), "r"(b1));
}

// shared 160x? (5 m-tiles) x 16-col (2 n-tiles) warp GEMM: D[M][K] x W[K][N]
__device__ __forceinline__ void mma_5x2(
    const float* sD, const float* sW, float acc[5][2][4],
    int mB, int nB, int g4, int tig, int ksteps, int ldd, int ldw)
{
#pragma unroll
    for (int mi = 0; mi < 5; mi++)
#pragma unroll
        for (int ni = 0; ni < 2; ni++)
#pragma unroll
            for (int c = 0; c < 4; c++) acc[mi][ni][c] = 0.f;
#pragma unroll 1
    for (int ks = 0; ks < ksteps; ks++) {
        int k0 = ks * 8;
        uint32_t A[5][4];
#pragma unroll
        for (int mi = 0; mi < 5; mi++) {
            int row = mB + mi*16 + g4;
            A[mi][0] = __float_as_uint(sD[row*ldd + k0 + tig]);
            A[mi][1] = __float_as_uint(sD[(row+8)*ldd + k0 + tig]);
            A[mi][2] = __float_as_uint(sD[row*ldd + k0 + tig + 4]);
            A[mi][3] = __float_as_uint(sD[(row+8)*ldd + k0 + tig + 4]);
        }
        uint32_t Bf[2][2];
#pragma unroll
        for (int ni = 0; ni < 2; ni++) {
            int col = nB + ni*8 + g4;
            Bf[ni][0] = __float_as_uint(sW[(k0+tig)*ldw + col]);
            Bf[ni][1] = __float_as_uint(sW[(k0+tig+4)*ldw + col]);
        }
#pragma unroll
        for (int mi = 0; mi < 5; mi++)
#pragma unroll
            for (int ni = 0; ni < 2; ni++)
                mma8(acc[mi][ni][0], acc[mi][ni][1], acc[mi][ni][2], acc[mi][ni][3],
                     A[mi][0], A[mi][1], A[mi][2], A[mi][3], Bf[ni][0], Bf[ni][1]);
    }
}

// writeback: mode 0 = +bias -> tf32; mode 1 = +bias,relu -> tf32; mode 2 = raw fp32
__device__ __forceinline__ void wb_5x2(
    float* sD, float acc[5][2][4], const float* bias,
    int mB, int nB, int g4, int tig, int ldd, int mode)
{
#pragma unroll
    for (int mi = 0; mi < 5; mi++) {
#pragma unroll
        for (int ni = 0; ni < 2; ni++) {
            int row = mB + mi*16 + g4, col = nB + ni*8 + tig*2;
            float v0 = acc[mi][ni][0], v1 = acc[mi][ni][1];
            float v2 = acc[mi][ni][2], v3 = acc[mi][ni][3];
            if (mode < 2) {
                float ba = bias[col], bb = bias[col+1];
                v0 += ba; v1 += bb; v2 += ba; v3 += bb;
            }
            if (mode == 1) {
                v0 = fmaxf(v0, 0.f); v1 = fmaxf(v1, 0.f);
                v2 = fmaxf(v2, 0.f); v3 = fmaxf(v3, 0.f);
            }
            if (mode < 2) { v0 = tfbits(v0); v1 = tfbits(v1); v2 = tfbits(v2); v3 = tfbits(v3); }
            sD[row*ldd + col] = v0;     sD[row*ldd + col + 1] = v1;
            sD[(row+8)*ldd + col] = v2; sD[(row+8)*ldd + col + 1] = v3;
        }
    }
}

// ---------------- KNN over 3-D positions (exact fp32) ----------------
__global__ __launch_bounds__(256) void knn_pos_kernel(const float* __restrict__ pos)
{
    __shared__ float sx[PP], sy[PP], sz[PP], sq[PP];
    int b = blockIdx.y;
    const float* p = pos + (size_t)b * PP * 3;
    for (int j = threadIdx.x; j < PP; j += 256) {
        float x = p[3*j], y = p[3*j+1], z = p[3*j+2];
        sx[j] = x; sy[j] = y; sz[j] = z; sq[j] = x*x + y*y + z*z;
    }
    __syncthreads();
    int il = blockIdx.x * 256 + threadIdx.x;
    float xi = sx[il], yi = sy[il], zi = sz[il], sqi = sq[il];
    float bd[KNN]; int bi[KNN];
#pragma unroll
    for (int t = 0; t < KNN; t++) { bd[t] = 3.4e38f; bi[t] = 0; }
    for (int j = 0; j < PP; j++) {
        float d = sqi + sq[j] - 2.0f * (xi*sx[j] + yi*sy[j] + zi*sz[j]);
        if (d < bd[KNN-1]) {
            bd[KNN-1] = d; bi[KNN-1] = j;
#pragma unroll
            for (int t = KNN-1; t > 0; t--) {
                if (bd[t] < bd[t-1]) {
                    float td = bd[t]; bd[t] = bd[t-1]; bd[t-1] = td;
                    int ti = bi[t]; bi[t] = bi[t-1]; bi[t-1] = ti;
                }
            }
        }
    }
    int gi = b * PP + il;
#pragma unroll
    for (int t = 0; t < KNN; t++) g_idx[gi*KNN + t] = b * PP + bi[t];
}

// ---------------- EdgeConv1: tf32 tensor cores, 3 chained GEMMs in SMEM ----------------
// 1024 blocks x 4 groups of 8 points (160 edges). Warps 2m x 4n.
#define C1_LDD 68
#define C1_LDW 72
__global__ __launch_bounds__(256, 2) void conv1_kernel(
    const float* __restrict__ pos,
    const float* __restrict__ w0, const float* __restrict__ b0,
    const float* __restrict__ w1, const float* __restrict__ b1,
    const float* __restrict__ w2, const float* __restrict__ b2)
{
    extern __shared__ float sm[];
    float* sW0 = sm;            // 8*72  = 576
    float* sW1 = sm + 576;      // 64*72 = 4608
    float* sW2 = sm + 5184;     // 4608
    float* sb0 = sm + 9792;     // 64
    float* sb1 = sm + 9856;     // 64
    float* sb2 = sm + 9920;     // 64
    float* sD  = sm + 9984;     // 160*68 = 10880

    int tid = threadIdx.x, lane = tid & 31, warp = tid >> 5;
    int g4 = lane >> 2, tig = lane & 3;
    int wm = warp >> 2, wn = warp & 3;
    int mB = wm * 80, nB = wn * 16;

    for (int fi = tid; fi < 512; fi += 256) {
        int kk = fi >> 6, o = fi & 63;
        sW0[kk*C1_LDW + o] = (kk < 6) ? tfbits(w0[kk*64 + o]) : 0.f;
    }
    for (int fi = tid; fi < 4096; fi += 256) {
        int kk = fi >> 6, o = fi & 63;
        sW1[kk*C1_LDW + o] = tfbits(w1[fi]);
        sW2[kk*C1_LDW + o] = tfbits(w2[fi]);
    }
    if (tid < 64) { sb0[tid] = b0[tid]; sb1[tid] = b1[tid]; sb2[tid] = b2[tid]; }

    float acc[5][2][4];
    for (int gi = 0; gi < 4; gi++) {
        int ibase = (blockIdx.x*4 + gi) * 8;
        __syncthreads();
        // build E[160][8] = [xi(3), xj-xi(3), 0, 0] in tf32
        if (tid < 160) {
            int p = tid / 20, e = tid - p*20;
            int i = ibase + p;
            int j = g_idx[i*KNN + e];
            float xx = pos[i*3], xy = pos[i*3+1], xz = pos[i*3+2];
            float jx = pos[j*3], jy = pos[j*3+1], jz = pos[j*3+2];
            float* dr = sD + tid*C1_LDD;
            dr[0] = tfbits(xx); dr[1] = tfbits(xy); dr[2] = tfbits(xz);
            dr[3] = tfbits(jx-xx); dr[4] = tfbits(jy-xy); dr[5] = tfbits(jz-xz);
            dr[6] = 0.f; dr[7] = 0.f;
        }
        __syncthreads();
        // layer0 (K=8): h0 = E @ W0 + b0 (no relu)
        mma_5x2(sD, sW0, acc, mB, nB, g4, tig, 1, C1_LDD, C1_LDW);
        __syncthreads();
        wb_5x2(sD, acc, sb0, mB, nB, g4, tig, C1_LDD, 0);
        __syncthreads();
        // layer1: h1 = relu(h0 @ W1 + b1)
        mma_5x2(sD, sW1, acc, mB, nB, g4, tig, 8, C1_LDD, C1_LDW);
        __syncthreads();
        wb_5x2(sD, acc, sb1, mB, nB, g4, tig, C1_LDD, 1);
        __syncthreads();
        // layer2: h2 = h1 @ W2 (bias/relu folded into epilogue)
        mma_5x2(sD, sW2, acc, mB, nB, g4, tig, 8, C1_LDD, C1_LDW);
        __syncthreads();
        wb_5x2(sD, acc, sb2, mB, nB, g4, tig, C1_LDD, 2);
        __syncthreads();
        // epilogue: max over 20 edges, +b2, relu, store x1
        {
            int p = tid >> 5, cq = tid & 31;
            float2 m = make_float2(-3.4e38f, -3.4e38f);
#pragma unroll 4
            for (int e = 0; e < KNN; e++) {
                float2 v = *(float2*)&sD[(p*20+e)*C1_LDD + cq*2];
                m.x = fmaxf(m.x, v.x); m.y = fmaxf(m.y, v.y);
            }
            float2 bbv = *(float2*)&sb2[cq*2];
            m.x = fmaxf(m.x + bbv.x, 0.f);
            m.y = fmaxf(m.y + bbv.y, 0.f);
            ((float2*)g_x1)[(size_t)(ibase+p)*32 + cq] = m;
        }
    }
}

// ---------------- KNN over 64-D features (exact fp32) ----------------
__global__ __launch_bounds__(256) void knn_feat_kernel()
{
    extern __shared__ float smem[];
    float4* sj = (float4*)smem;
    float*  ssq = smem + 256*64;
    int b = blockIdx.y;
    int i = b * PP + blockIdx.x * 256 + threadIdx.x;
    const float4* x1v = (const float4*)g_x1;
    float4 xi[16];
#pragma unroll
    for (int q = 0; q < 16; q++) xi[q] = x1v[(size_t)i*16 + q];
    float sqi = 0.f;
#pragma unroll
    for (int q = 0; q < 16; q++)
        sqi += xi[q].x*xi[q].x + xi[q].y*xi[q].y + xi[q].z*xi[q].z + xi[q].w*xi[q].w;
    float bd[KNN]; int bi[KNN];
#pragma unroll
    for (int t = 0; t < KNN; t++) { bd[t] = 3.4e38f; bi[t] = 0; }
    for (int t4 = 0; t4 < 4; t4++) {
        __syncthreads();
        for (int r = threadIdx.x; r < 256*16; r += 256)
            sj[r] = x1v[((size_t)(b*PP + t4*256))*16 + r];
        __syncthreads();
        {
            float s = 0.f;
#pragma unroll
            for (int q = 0; q < 16; q++) {
                float4 v = sj[threadIdx.x*16 + q];
                s += v.x*v.x + v.y*v.y + v.z*v.z + v.w*v.w;
            }
            ssq[threadIdx.x] = s;
        }
        __syncthreads();
        for (int jj = 0; jj < 256; jj++) {
            float dv = 0.f;
#pragma unroll
            for (int q = 0; q < 16; q++) {
                float4 v = sj[jj*16 + q];
                dv += xi[q].x*v.x + xi[q].y*v.y + xi[q].z*v.z + xi[q].w*v.w;
            }
            float d = sqi + ssq[jj] - 2.0f * dv;
            if (d < bd[KNN-1]) {
                bd[KNN-1] = d; bi[KNN-1] = t4*256 + jj;
#pragma unroll
                for (int t = KNN-1; t > 0; t--) {
                    if (bd[t] < bd[t-1]) {
                        float td = bd[t]; bd[t] = bd[t-1]; bd[t-1] = td;
                        int ti = bi[t]; bi[t] = bi[t-1]; bi[t-1] = ti;
                    }
                }
            }
        }
    }
#pragma unroll
    for (int t = 0; t < KNN; t++) g_idx[(size_t)i*KNN + t] = b * PP + bi[t];
}

// ---------------- EdgeConv2: tf32, 4-pt groups for 2 blocks/SM ----------------
#define C2_LDD 132
#define C2_LDW 136
__global__ __launch_bounds__(256, 2) void conv2_kernel(
    const float* __restrict__ w, const float* __restrict__ bias)
{
    extern __shared__ float sm[];
    float* sW    = sm;                        // 128*136 = 17408
    float* sD    = sm + 17408;                // 80*132 = 10560
    float* sXi   = sm + 27968;                // 4*64
    float* sbias = sm + 28224;                // 128

    int tid = threadIdx.x, lane = tid & 31, warp = tid >> 5;
    int g4 = lane >> 2, tig = lane & 3;
    int nB = warp * 16;     // 8 warps x 16 cols = 128

    for (int fi = tid; fi < 4096; fi += 256) {
        int kk = fi >> 5, nq = fi & 31;
        float4 v = ((const float4*)w)[fi];
        *(float4*)&sW[kk*C2_LDW + nq*4] =
            make_float4(tfbits(v.x), tfbits(v.y), tfbits(v.z), tfbits(v.w));
    }
    if (tid < 128) sbias[tid] = bias[tid];

    const float4* x1v = (const float4*)g_x1;
    float acc[5][2][4];

    for (int gi = 0; gi < 8; gi++) {
        int ibase = (blockIdx.x*8 + gi) * 4;
        __syncthreads();
        if (tid < 64) {
            int p = tid >> 4, q = tid & 15;
            ((float4*)&sXi[p*64])[q] = x1v[(size_t)(ibase+p)*16 + q];
        }
        __syncthreads();
        // build D[80][128]: cols 0..63 tf32(xi), 64..127 tf32(xj-xi)
        if (tid < 160) {
            int e = tid >> 1, half = tid & 1;
            int p = e / 20;
            float* dr = sD + e*C2_LDD + half*64;
            const float4* xiv = (const float4*)&sXi[p*64];
            if (half == 0) {
#pragma unroll 4
                for (int q = 0; q < 16; q++) {
                    float4 xi = xiv[q];
                    *(float4*)&dr[q*4] =
                        make_float4(tfbits(xi.x), tfbits(xi.y), tfbits(xi.z), tfbits(xi.w));
                }
            } else {
                int j = g_idx[(size_t)(ibase+p)*KNN + (e - p*20)];
#pragma unroll 4
                for (int q = 0; q < 16; q++) {
                    float4 xj = x1v[(size_t)j*16 + q];
                    float4 xi = xiv[q];
                    *(float4*)&dr[q*4] =
                        make_float4(tfbits(xj.x-xi.x), tfbits(xj.y-xi.y),
                                    tfbits(xj.z-xi.z), tfbits(xj.w-xi.w));
                }
            }
        }
        __syncthreads();
        mma_5x2(sD, sW, acc, 0, nB, g4, tig, 16, C2_LDD, C2_LDW);
        __syncthreads();
        wb_5x2(sD, acc, sbias, 0, nB, g4, tig, C2_LDD, 2);
        __syncthreads();
        // epilogue: max over 20 edges, +bias, relu, store x2
        if (tid < 128) {
            int p = tid >> 5, cq = tid & 31;
            float4 m = make_float4(-3.4e38f, -3.4e38f, -3.4e38f, -3.4e38f);
#pragma unroll 4
            for (int e = 0; e < KNN; e++) {
                float4 v = *(float4*)&sD[(p*20+e)*C2_LDD + cq*4];
                m.x = fmaxf(m.x, v.x); m.y = fmaxf(m.y, v.y);
                m.z = fmaxf(m.z, v.z); m.w = fmaxf(m.w, v.w);
            }
            float4 bbv = *(float4*)&sbias[cq*4];
            m.x = fmaxf(m.x + bbv.x, 0.f); m.y = fmaxf(m.y + bbv.y, 0.f);
            m.z = fmaxf(m.z + bbv.z, 0.f); m.w = fmaxf(m.w + bbv.w, 0.f);
            ((float4*)g_x2)[(size_t)(ibase+p)*32 + cq] = m;
        }
    }
}

// ---------------- zero the maxpool accumulator ----------------
__global__ void zero_pool_kernel() { g_pool[blockIdx.x*1024 + threadIdx.x] = 0u; }

// ---------------- l1 (192->1024) tf32 GEMM + fused relu + P-max ----------------
__global__ __launch_bounds__(256) void l1max_kernel(
    const float* __restrict__ w, const float* __restrict__ bias)
{
    __shared__ float sA[128*20];
    __shared__ float sB[16*136];
    __shared__ float sbias[128];
    __shared__ unsigned int sred[128];
    int tid = threadIdx.x;
    int lane = tid & 31, warp = tid >> 5;
    int g4 = lane >> 2, tig = lane & 3;
    int b = blockIdx.z;
    int n0 = blockIdx.x * 128, m0 = blockIdx.y * 128;
    int pbase = b * PP + m0;
    const float4* x1v = (const float4*)g_x1;
    const float4* x2v = (const float4*)g_x2;
    const float4* wv  = (const float4*)w;
    if (tid < 128) { sred[tid] = 0u; sbias[tid] = bias[n0 + tid]; }

    int wm = warp >> 2, wn = warp & 3;
    float acc[4][4][4];
#pragma unroll
    for (int mi = 0; mi < 4; mi++)
#pragma unroll
        for (int ni = 0; ni < 4; ni++)
#pragma unroll
            for (int c = 0; c < 4; c++) acc[mi][ni][c] = 0.f;

    for (int ks = 0; ks < 12; ks++) {
        __syncthreads();
#pragma unroll
        for (int r = 0; r < 2; r++) {
            int fi = tid*2 + r;
            int pt = fi >> 2, kq = fi & 3;
            float4 v = (ks < 4) ? x1v[(size_t)(pbase+pt)*16 + ks*4 + kq]
                                : x2v[(size_t)(pbase+pt)*32 + (ks-4)*4 + kq];
            *(float4*)&sA[pt*20 + kq*4] =
                make_float4(tfbits(v.x), tfbits(v.y), tfbits(v.z), tfbits(v.w));
        }
#pragma unroll
        for (int r = 0; r < 2; r++) {
            int fi = tid*2 + r;
            int kk = fi >> 5, nq = fi & 31;
            float4 v = wv[(size_t)(ks*16+kk)*256 + (n0>>2) + nq];
            *(float4*)&sB[kk*136 + nq*4] =
                make_float4(tfbits(v.x), tfbits(v.y), tfbits(v.z), tfbits(v.w));
        }
        __syncthreads();
#pragma unroll
        for (int kh = 0; kh < 2; kh++) {
            int k0 = kh*8;
            uint32_t A[4][4];
#pragma unroll
            for (int mi = 0; mi < 4; mi++) {
                int row = wm*64 + mi*16 + g4;
                A[mi][0] = __float_as_uint(sA[row*20 + k0 + tig]);
                A[mi][1] = __float_as_uint(sA[(row+8)*20 + k0 + tig]);
                A[mi][2] = __float_as_uint(sA[row*20 + k0 + tig + 4]);
                A[mi][3] = __float_as_uint(sA[(row+8)*20 + k0 + tig + 4]);
            }
            uint32_t Bf[4][2];
#pragma unroll
            for (int ni = 0; ni < 4; ni++) {
                int col = wn*32 + ni*8 + g4;
                Bf[ni][0] = __float_as_uint(sB[(k0+tig)*136 + col]);
                Bf[ni][1] = __float_as_uint(sB[(k0+tig+4)*136 + col]);
            }
#pragma unroll
            for (int mi = 0; mi < 4; mi++)
#pragma unroll
                for (int ni = 0; ni < 4; ni++)
                    mma8(acc[mi][ni][0], acc[mi][ni][1], acc[mi][ni][2], acc[mi][ni][3],
                         A[mi][0], A[mi][1], A[mi][2], A[mi][3], Bf[ni][0], Bf[ni][1]);
        }
    }
#pragma unroll
    for (int ni = 0; ni < 4; ni++) {
        float v0 = -3.4e38f, v1 = -3.4e38f;
#pragma unroll
        for (int mi = 0; mi < 4; mi++) {
            v0 = fmaxf(v0, fmaxf(acc[mi][ni][0], acc[mi][ni][2]));
            v1 = fmaxf(v1, fmaxf(acc[mi][ni][1], acc[mi][ni][3]));
        }
#pragma unroll
        for (int off = 4; off < 32; off <<= 1) {
            v0 = fmaxf(v0, __shfl_xor_sync(0xffffffff, v0, off));
            v1 = fmaxf(v1, __shfl_xor_sync(0xffffffff, v1, off));
        }
        if (g4 == 0) {
            int col = wn*32 + ni*8 + tig*2;
            float a0 = fmaxf(v0 + sbias[col], 0.f);
            float a1 = fmaxf(v1 + sbias[col+1], 0.f);
            atomicMax(&sred[col],   __float_as_uint(a0));
            atomicMax(&sred[col+1], __float_as_uint(a1));
        }
    }
    __syncthreads();
    if (tid < 128) atomicMax(&g_pool[b*1024 + n0 + tid], sred[tid]);
}

// ---------------- head: 1024->512 relu ->256 relu ->40 + log_softmax ----------------
__global__ __launch_bounds__(256) void head_kernel(
    const float* __restrict__ w0, const float* __restrict__ b0,
    const float* __restrict__ w1, const float* __restrict__ b1,
    const float* __restrict__ w2, const float* __restrict__ b2,
    float* __restrict__ out)
{
    __shared__ float sp[1024], sh0[512], sh1[256], sl[40], red[2];
    int b = blockIdx.x, tid = threadIdx.x;
    for (int c = tid; c < 1024; c += 256) sp[c] = __uint_as_float(g_pool[b*1024 + c]);
    __syncthreads();
    {
        float a0 = b0[2*tid], a1 = b0[2*tid+1];
        const float2* w0v = (const float2*)w0;
        for (int c = 0; c < 1024; c++) {
            float f = sp[c];
            float2 wvv = w0v[c*256 + tid];
            a0 += f * wvv.x; a1 += f * wvv.y;
        }
        sh0[2*tid]   = fmaxf(a0, 0.f);
        sh0[2*tid+1] = fmaxf(a1, 0.f);
    }
    __syncthreads();
    {
        float a = b1[tid];
        for (int c = 0; c < 512; c++) a += sh0[c] * w1[c*256 + tid];
        sh1[tid] = fmaxf(a, 0.f);
    }
    __syncthreads();
    if (tid < 40) {
        float a = b2[tid];
        for (int c = 0; c < 256; c++) a += sh1[c] * w2[c*40 + tid];
        sl[tid] = a;
    }
    __syncthreads();
    if (tid == 0) {
        float mxv = -3.4e38f;
        for (int t = 0; t < 40; t++) mxv = fmaxf(mxv, sl[t]);
        float s = 0.f;
        for (int t = 0; t < 40; t++) s += expf(sl[t] - mxv);
        red[0] = mxv; red[1] = logf(s);
    }
    __syncthreads();
    if (tid < 40) out[b*40 + tid] = sl[tid] - red[0] - red[1];
}

// ---------------- launch ----------------
extern "C" void kernel_launch(void* const* d_in, const int* in_sizes, int n_in,
                              void* d_out, int out_size)
{
    const float* pos   = (const float*)d_in[0];
    const float* c1_w0 = (const float*)d_in[2];
    const float* c1_b0 = (const float*)d_in[3];
    const float* c1_w1 = (const float*)d_in[4];
    const float* c1_b1 = (const float*)d_in[5];
    const float* c1_w2 = (const float*)d_in[6];
    const float* c1_b2 = (const float*)d_in[7];
    const float* c2_w0 = (const float*)d_in[8];
    const float* c2_b0 = (const float*)d_in[9];
    const float* l1_w  = (const float*)d_in[10];
    const float* l1_b  = (const float*)d_in[11];
    const float* m_w0  = (const float*)d_in[12];
    const float* m_b0  = (const float*)d_in[13];
    const float* m_w1  = (const float*)d_in[14];
    const float* m_b1  = (const float*)d_in[15];
    const float* m_w2  = (const float*)d_in[16];
    const float* m_b2  = (const float*)d_in[17];
    float* out = (float*)d_out;

    const int smem_conv1 = (576 + 4608 + 4608 + 192 + 160*C1_LDD) * 4;      // 83456
    const int smem_knn2  = 256*64*4 + 256*4;                                // 66560
    const int smem_conv2 = (128*C2_LDW + 80*C2_LDD + 256 + 128) * 4;        // 113408

    cudaFuncSetAttribute(conv1_kernel,    cudaFuncAttributeMaxDynamicSharedMemorySize, smem_conv1);
    cudaFuncSetAttribute(knn_feat_kernel, cudaFuncAttributeMaxDynamicSharedMemorySize, smem_knn2);
    cudaFuncSetAttribute(conv2_kernel,    cudaFuncAttributeMaxDynamicSharedMemorySize, smem_conv2);

    knn_pos_kernel<<<dim3(4, 32), 256>>>(pos);
    conv1_kernel<<<1024, 256, smem_conv1>>>(pos, c1_w0, c1_b0, c1_w1, c1_b1, c1_w2, c1_b2);
    knn_feat_kernel<<<dim3(4, 32), 256, smem_knn2>>>();
    conv2_kernel<<<1024, 256, smem_conv2>>>(c2_w0, c2_b0);
    zero_pool_kernel<<<32, 1024>>>();
    l1max_kernel<<<dim3(8, 8, 32), 256>>>(l1_w, l1_b);
    head_kernel<<<32, 256>>>(m_w0, m_b0, m_w1, m_b1, m_w2, m_b2, out);
}

// round 5
// speedup vs baseline: 14.9051x; 1.0956x over previous
#include <cuda_runtime.h>
#include <math.h>
#include <stdint.h>

#define BB 32
#define PP 1024
#define KNN 20
#define NPTS (BB*PP)

// ---------------- scratch (device globals; no allocs allowed) ----------------
__device__ __align__(16) float g_x1[NPTS*64];
__device__ __align__(16) float g_x2[NPTS*128];
__device__ int g_idx[NPTS*KNN];
__device__ unsigned int g_pool[BB*1024];

// ---------------- tf32 mma helpers ----------------
__device__ __forceinline__ uint32_t f2tf(float x) {
    uint32_t r; asm("cvt.rna.tf32.f32 %0, %1;" : "=r"(r) : "f"(x)); return r;
}
__device__ __forceinline__ float tfbits(float x) {
    return __uint_as_float(f2tf(x));
}
__device__ __forceinline__ void mma8(float& c0, float& c1, float& c2, float& c3,
                                     uint32_t a0, uint32_t a1, uint32_t a2, uint32_t a3,
                                     uint32_t b0, uint32_t b1)
{
    asm volatile("mma.sync.aligned.m16n8k8.row.col.f32.tf32.tf32.f32 "
                 "{%0,%1,%2,%3},{%4,%5,%6,%7},{%8,%9},{%0,%1,%2,%3};"
                 : "+f"(c0), "+f"(c1), "+f"(c2), "+f"(c3)
                 : "r"(a0), "r"(a1), "r"(a2), "r"(a3), "r"(b0), "r"(b1));
}

// 5 m-tiles x 2 n-tiles warp GEMM
__device__ __forceinline__ void mma_5x2(
    const float* sD, const float* sW, float acc[5][2][4],
    int mB, int nB, int g4, int tig, int ksteps, int ldd, int ldw)
{
#pragma unroll
    for (int mi = 0; mi < 5; mi++)
#pragma unroll
        for (int ni = 0; ni < 2; ni++)
#pragma unroll
            for (int c = 0; c < 4; c++) acc[mi][ni][c] = 0.f;
#pragma unroll 1
    for (int ks = 0; ks < ksteps; ks++) {
        int k0 = ks * 8;
        uint32_t A[5][4];
#pragma unroll
        for (int mi = 0; mi < 5; mi++) {
            int row = mB + mi*16 + g4;
            A[mi][0] = __float_as_uint(sD[row*ldd + k0 + tig]);
            A[mi][1] = __float_as_uint(sD[(row+8)*ldd + k0 + tig]);
            A[mi][2] = __float_as_uint(sD[row*ldd + k0 + tig + 4]);
            A[mi][3] = __float_as_uint(sD[(row+8)*ldd + k0 + tig + 4]);
        }
        uint32_t Bf[2][2];
#pragma unroll
        for (int ni = 0; ni < 2; ni++) {
            int col = nB + ni*8 + g4;
            Bf[ni][0] = __float_as_uint(sW[(k0+tig)*ldw + col]);
            Bf[ni][1] = __float_as_uint(sW[(k0+tig+4)*ldw + col]);
        }
#pragma unroll
        for (int mi = 0; mi < 5; mi++)
#pragma unroll
            for (int ni = 0; ni < 2; ni++)
                mma8(acc[mi][ni][0], acc[mi][ni][1], acc[mi][ni][2], acc[mi][ni][3],
                     A[mi][0], A[mi][1], A[mi][2], A[mi][3], Bf[ni][0], Bf[ni][1]);
    }
}

// writeback: mode 0 = +bias -> tf32; mode 1 = +bias,relu -> tf32; mode 2 = raw fp32
__device__ __forceinline__ void wb_5x2(
    float* sD, float acc[5][2][4], const float* bias,
    int mB, int nB, int g4, int tig, int ldd, int mode)
{
#pragma unroll
    for (int mi = 0; mi < 5; mi++) {
#pragma unroll
        for (int ni = 0; ni < 2; ni++) {
            int row = mB + mi*16 + g4, col = nB + ni*8 + tig*2;
            float v0 = acc[mi][ni][0], v1 = acc[mi][ni][1];
            float v2 = acc[mi][ni][2], v3 = acc[mi][ni][3];
            if (mode < 2) {
                float ba = bias[col], bb = bias[col+1];
                v0 += ba; v1 += bb; v2 += ba; v3 += bb;
            }
            if (mode == 1) {
                v0 = fmaxf(v0, 0.f); v1 = fmaxf(v1, 0.f);
                v2 = fmaxf(v2, 0.f); v3 = fmaxf(v3, 0.f);
            }
            if (mode < 2) { v0 = tfbits(v0); v1 = tfbits(v1); v2 = tfbits(v2); v3 = tfbits(v3); }
            sD[row*ldd + col] = v0;     sD[row*ldd + col + 1] = v1;
            sD[(row+8)*ldd + col] = v2; sD[(row+8)*ldd + col + 1] = v3;
        }
    }
}

// ---------------- KNN over 3-D positions (exact fp32) + pool zero ----------------
__global__ __launch_bounds__(256) void knn_pos_kernel(const float* __restrict__ pos)
{
    __shared__ float sx[PP], sy[PP], sz[PP], sq[PP];
    int b = blockIdx.y;
    // fold zero_pool: 128 blocks x 256 threads == 32768 pool words
    g_pool[(blockIdx.y*4 + blockIdx.x)*256 + threadIdx.x] = 0u;
    const float* p = pos + (size_t)b * PP * 3;
    for (int j = threadIdx.x; j < PP; j += 256) {
        float x = p[3*j], y = p[3*j+1], z = p[3*j+2];
        sx[j] = x; sy[j] = y; sz[j] = z; sq[j] = x*x + y*y + z*z;
    }
    __syncthreads();
    int il = blockIdx.x * 256 + threadIdx.x;
    float xi = sx[il], yi = sy[il], zi = sz[il], sqi = sq[il];
    float bd[KNN]; int bi[KNN];
#pragma unroll
    for (int t = 0; t < KNN; t++) { bd[t] = 3.4e38f; bi[t] = 0; }
    for (int j = 0; j < PP; j++) {
        float d = sqi + sq[j] - 2.0f * (xi*sx[j] + yi*sy[j] + zi*sz[j]);
        if (d < bd[KNN-1]) {
            bd[KNN-1] = d; bi[KNN-1] = j;
#pragma unroll
            for (int t = KNN-1; t > 0; t--) {
                if (bd[t] < bd[t-1]) {
                    float td = bd[t]; bd[t] = bd[t-1]; bd[t-1] = td;
                    int ti = bi[t]; bi[t] = bi[t-1]; bi[t-1] = ti;
                }
            }
        }
    }
    int gi = b * PP + il;
#pragma unroll
    for (int t = 0; t < KNN; t++) g_idx[gi*KNN + t] = b * PP + bi[t];
}

// ---------------- EdgeConv1: tf32 tensor cores, 3 chained GEMMs in SMEM ----------------
#define C1_LDD 68
#define C1_LDW 72
__global__ __launch_bounds__(256, 2) void conv1_kernel(
    const float* __restrict__ pos,
    const float* __restrict__ w0, const float* __restrict__ b0,
    const float* __restrict__ w1, const float* __restrict__ b1,
    const float* __restrict__ w2, const float* __restrict__ b2)
{
    extern __shared__ float sm[];
    float* sW0 = sm;            // 8*72
    float* sW1 = sm + 576;      // 64*72
    float* sW2 = sm + 5184;
    float* sb0 = sm + 9792;
    float* sb1 = sm + 9856;
    float* sb2 = sm + 9920;
    float* sD  = sm + 9984;     // 160*68

    int tid = threadIdx.x, lane = tid & 31, warp = tid >> 5;
    int g4 = lane >> 2, tig = lane & 3;
    int wm = warp >> 2, wn = warp & 3;
    int mB = wm * 80, nB = wn * 16;

    for (int fi = tid; fi < 512; fi += 256) {
        int kk = fi >> 6, o = fi & 63;
        sW0[kk*C1_LDW + o] = (kk < 6) ? tfbits(w0[kk*64 + o]) : 0.f;
    }
    for (int fi = tid; fi < 4096; fi += 256) {
        int kk = fi >> 6, o = fi & 63;
        sW1[kk*C1_LDW + o] = tfbits(w1[fi]);
        sW2[kk*C1_LDW + o] = tfbits(w2[fi]);
    }
    if (tid < 64) { sb0[tid] = b0[tid]; sb1[tid] = b1[tid]; sb2[tid] = b2[tid]; }

    float acc[5][2][4];
    for (int gi = 0; gi < 4; gi++) {
        int ibase = (blockIdx.x*4 + gi) * 8;
        __syncthreads();
        if (tid < 160) {
            int p = tid / 20, e = tid - p*20;
            int i = ibase + p;
            int j = g_idx[i*KNN + e];
            float xx = pos[i*3], xy = pos[i*3+1], xz = pos[i*3+2];
            float jx = pos[j*3], jy = pos[j*3+1], jz = pos[j*3+2];
            float* dr = sD + tid*C1_LDD;
            dr[0] = tfbits(xx); dr[1] = tfbits(xy); dr[2] = tfbits(xz);
            dr[3] = tfbits(jx-xx); dr[4] = tfbits(jy-xy); dr[5] = tfbits(jz-xz);
            dr[6] = 0.f; dr[7] = 0.f;
        }
        __syncthreads();
        mma_5x2(sD, sW0, acc, mB, nB, g4, tig, 1, C1_LDD, C1_LDW);
        __syncthreads();
        wb_5x2(sD, acc, sb0, mB, nB, g4, tig, C1_LDD, 0);
        __syncthreads();
        mma_5x2(sD, sW1, acc, mB, nB, g4, tig, 8, C1_LDD, C1_LDW);
        __syncthreads();
        wb_5x2(sD, acc, sb1, mB, nB, g4, tig, C1_LDD, 1);
        __syncthreads();
        mma_5x2(sD, sW2, acc, mB, nB, g4, tig, 8, C1_LDD, C1_LDW);
        __syncthreads();
        wb_5x2(sD, acc, sb2, mB, nB, g4, tig, C1_LDD, 2);
        __syncthreads();
        {
            int p = tid >> 5, cq = tid & 31;
            float2 m = make_float2(-3.4e38f, -3.4e38f);
#pragma unroll 4
            for (int e = 0; e < KNN; e++) {
                float2 v = *(float2*)&sD[(p*20+e)*C1_LDD + cq*2];
                m.x = fmaxf(m.x, v.x); m.y = fmaxf(m.y, v.y);
            }
            float2 bbv = *(float2*)&sb2[cq*2];
            m.x = fmaxf(m.x + bbv.x, 0.f);
            m.y = fmaxf(m.y + bbv.y, 0.f);
            ((float2*)g_x1)[(size_t)(ibase+p)*32 + cq] = m;
        }
    }
}

// ---------------- KNN over 64-D features: tf32 MMA dot matrix + top-k scan ----------------
// grid (8 i-tiles of 128, 32 batches), 256 threads.
#define KF_LDA 68
#define KF_LDT 132
__global__ __launch_bounds__(256) void knn_feat_kernel()
{
    extern __shared__ float sm[];
    float* sA   = sm;                    // 128*68  (Xi tf32)
    float* sB   = sm + 128*KF_LDA;       // 128*68  (Xj tf32)
    float* sdot = sm + 2*128*KF_LDA;     // 128*132
    float* sqi  = sdot + 128*KF_LDT;     // 128
    float* sqj  = sqi + 128;             // 128

    int tid = threadIdx.x, lane = tid & 31, warp = tid >> 5;
    int g4 = lane >> 2, tig = lane & 3;
    int wm = warp >> 2, wn = warp & 3;
    int b = blockIdx.y;
    int i0 = b*PP + blockIdx.x*128;
    const float4* x1v = (const float4*)g_x1;

    // load Xi tile (tf32) + exact fp32 sq_i
    for (int fi = tid; fi < 128*16; fi += 256) {
        int pt = fi >> 4, q = fi & 15;
        float4 v = x1v[(size_t)(i0+pt)*16 + q];
        *(float4*)&sA[pt*KF_LDA + q*4] =
            make_float4(tfbits(v.x), tfbits(v.y), tfbits(v.z), tfbits(v.w));
    }
    if (tid < 128) {
        float s = 0.f;
#pragma unroll
        for (int q = 0; q < 16; q++) {
            float4 v = x1v[(size_t)(i0+tid)*16 + q];
            s += v.x*v.x + v.y*v.y + v.z*v.z + v.w*v.w;
        }
        sqi[tid] = s;
    }

    float bd[KNN]; int bi[KNN];
#pragma unroll
    for (int t = 0; t < KNN; t++) { bd[t] = 3.4e38f; bi[t] = 0; }
    float mysq = 0.f;

    for (int jt = 0; jt < 8; jt++) {
        int j0 = b*PP + jt*128;
        __syncthreads();   // prev selection done; safe to overwrite sB/sdot
        for (int fi = tid; fi < 128*16; fi += 256) {
            int pt = fi >> 4, q = fi & 15;
            float4 v = x1v[(size_t)(j0+pt)*16 + q];
            *(float4*)&sB[pt*KF_LDA + q*4] =
                make_float4(tfbits(v.x), tfbits(v.y), tfbits(v.z), tfbits(v.w));
        }
        if (tid < 128) {
            float s = 0.f;
#pragma unroll
            for (int q = 0; q < 16; q++) {
                float4 v = x1v[(size_t)(j0+tid)*16 + q];
                s += v.x*v.x + v.y*v.y + v.z*v.z + v.w*v.w;
            }
            sqj[tid] = s;
        }
        __syncthreads();
        // GEMM: dot[128 i][128 j], K=64. warp tile 64x32 (4m x 4n).
        float acc[4][4][4];
#pragma unroll
        for (int mi = 0; mi < 4; mi++)
#pragma unroll
            for (int ni = 0; ni < 4; ni++)
#pragma unroll
                for (int c = 0; c < 4; c++) acc[mi][ni][c] = 0.f;
#pragma unroll
        for (int ks = 0; ks < 8; ks++) {
            int k0 = ks*8;
            uint32_t A[4][4];
#pragma unroll
            for (int mi = 0; mi < 4; mi++) {
                int row = wm*64 + mi*16 + g4;
                A[mi][0] = __float_as_uint(sA[row*KF_LDA + k0 + tig]);
                A[mi][1] = __float_as_uint(sA[(row+8)*KF_LDA + k0 + tig]);
                A[mi][2] = __float_as_uint(sA[row*KF_LDA + k0 + tig + 4]);
                A[mi][3] = __float_as_uint(sA[(row+8)*KF_LDA + k0 + tig + 4]);
            }
            uint32_t Bf[4][2];
#pragma unroll
            for (int ni = 0; ni < 4; ni++) {
                int col = wn*32 + ni*8 + g4;
                Bf[ni][0] = __float_as_uint(sB[col*KF_LDA + k0 + tig]);
                Bf[ni][1] = __float_as_uint(sB[col*KF_LDA + k0 + tig + 4]);
            }
#pragma unroll
            for (int mi = 0; mi < 4; mi++)
#pragma unroll
                for (int ni = 0; ni < 4; ni++)
                    mma8(acc[mi][ni][0], acc[mi][ni][1], acc[mi][ni][2], acc[mi][ni][3],
                         A[mi][0], A[mi][1], A[mi][2], A[mi][3], Bf[ni][0], Bf[ni][1]);
        }
#pragma unroll
        for (int mi = 0; mi < 4; mi++) {
#pragma unroll
            for (int ni = 0; ni < 4; ni++) {
                int row = wm*64 + mi*16 + g4, col = wn*32 + ni*8 + tig*2;
                *(float2*)&sdot[row*KF_LDT + col]     = make_float2(acc[mi][ni][0], acc[mi][ni][1]);
                *(float2*)&sdot[(row+8)*KF_LDT + col] = make_float2(acc[mi][ni][2], acc[mi][ni][3]);
            }
        }
        __syncthreads();
        // selection: thread tid<128 owns point i0+tid
        if (tid < 128) {
            if (jt == 0) mysq = sqi[tid];
            const float* drow = sdot + tid*KF_LDT;
            int jbase = jt*128;
            for (int j = 0; j < 128; j++) {
                float d = mysq + sqj[j] - 2.0f * drow[j];
                if (d < bd[KNN-1]) {
                    bd[KNN-1] = d; bi[KNN-1] = jbase + j;
#pragma unroll
                    for (int t = KNN-1; t > 0; t--) {
                        if (bd[t] < bd[t-1]) {
                            float td = bd[t]; bd[t] = bd[t-1]; bd[t-1] = td;
                            int ti = bi[t]; bi[t] = bi[t-1]; bi[t-1] = ti;
                        }
                    }
                }
            }
        }
    }
    if (tid < 128) {
        int gi = i0 + tid;
#pragma unroll
        for (int t = 0; t < KNN; t++) g_idx[(size_t)gi*KNN + t] = b*PP + bi[t];
    }
}

// ---------------- EdgeConv2: tf32, 8-pt groups (R3 shape) ----------------
#define C2_LDD 132
#define C2_LDW 136
__global__ __launch_bounds__(256) void conv2_kernel(
    const float* __restrict__ w, const float* __restrict__ bias)
{
    extern __shared__ float sm[];
    float* sW    = sm;                        // 128*136
    float* sD    = sm + 128*C2_LDW;           // 160*132
    float* sXi   = sD + 160*C2_LDD;           // 8*64
    float* sbias = sXi + 8*64;                // 128

    int tid = threadIdx.x;
    int lane = tid & 31, warp = tid >> 5;
    int g4 = lane >> 2, tig = lane & 3;

    for (int fi = tid; fi < 4096; fi += 256) {
        int kk = fi >> 5, nq = fi & 31;
        float4 v = ((const float4*)w)[kk*32 + nq];
        *(float4*)&sW[kk*C2_LDW + nq*4] =
            make_float4(tfbits(v.x), tfbits(v.y), tfbits(v.z), tfbits(v.w));
    }
    if (tid < 128) sbias[tid] = bias[tid];

    int wm = warp >> 2, wn = warp & 3;
    int mB = wm*80, nB = wn*32;
    const float4* x1v = (const float4*)g_x1;

    for (int gi = 0; gi < 4; gi++) {
        int ibase = (blockIdx.x*4 + gi) * 8;
        __syncthreads();
        if (tid < 128) {
            int p = tid >> 4, q = tid & 15;
            ((float4*)&sXi[p*64])[q] = x1v[(size_t)(ibase+p)*16 + q];
        }
        __syncthreads();
        if (tid < 160) {
            int p = tid/20, e = tid - p*20;
            int j = g_idx[(size_t)(ibase+p)*KNN + e];
            float* drow = sD + tid*C2_LDD;
            const float4* xiv = (const float4*)&sXi[p*64];
#pragma unroll 4
            for (int q = 0; q < 16; q++) {
                float4 xj = x1v[(size_t)j*16 + q];
                float4 xi = xiv[q];
                *(float4*)&drow[q*4] =
                    make_float4(tfbits(xi.x), tfbits(xi.y), tfbits(xi.z), tfbits(xi.w));
                *(float4*)&drow[64 + q*4] =
                    make_float4(tfbits(xj.x-xi.x), tfbits(xj.y-xi.y),
                                tfbits(xj.z-xi.z), tfbits(xj.w-xi.w));
            }
        }
        __syncthreads();
        float acc[5][4][4];
#pragma unroll
        for (int mi = 0; mi < 5; mi++)
#pragma unroll
            for (int ni = 0; ni < 4; ni++)
#pragma unroll
                for (int c = 0; c < 4; c++) acc[mi][ni][c] = 0.f;
#pragma unroll 1
        for (int ks = 0; ks < 16; ks++) {
            int k0 = ks*8;
            uint32_t A[5][4];
#pragma unroll
            for (int mi = 0; mi < 5; mi++) {
                int row = mB + mi*16 + g4;
                A[mi][0] = __float_as_uint(sD[row*C2_LDD + k0 + tig]);
                A[mi][1] = __float_as_uint(sD[(row+8)*C2_LDD + k0 + tig]);
                A[mi][2] = __float_as_uint(sD[row*C2_LDD + k0 + tig + 4]);
                A[mi][3] = __float_as_uint(sD[(row+8)*C2_LDD + k0 + tig + 4]);
            }
            uint32_t Bf[4][2];
#pragma unroll
            for (int ni = 0; ni < 4; ni++) {
                int col = nB + ni*8 + g4;
                Bf[ni][0] = __float_as_uint(sW[(k0+tig)*C2_LDW + col]);
                Bf[ni][1] = __float_as_uint(sW[(k0+tig+4)*C2_LDW + col]);
            }
#pragma unroll
            for (int mi = 0; mi < 5; mi++)
#pragma unroll
                for (int ni = 0; ni < 4; ni++)
                    mma8(acc[mi][ni][0], acc[mi][ni][1], acc[mi][ni][2], acc[mi][ni][3],
                         A[mi][0], A[mi][1], A[mi][2], A[mi][3], Bf[ni][0], Bf[ni][1]);
        }
        __syncthreads();
#pragma unroll
        for (int mi = 0; mi < 5; mi++) {
#pragma unroll
            for (int ni = 0; ni < 4; ni++) {
                int row = mB + mi*16 + g4, col = nB + ni*8 + tig*2;
                *(float2*)&sD[row*C2_LDD + col]     = make_float2(acc[mi][ni][0], acc[mi][ni][1]);
                *(float2*)&sD[(row+8)*C2_LDD + col] = make_float2(acc[mi][ni][2], acc[mi][ni][3]);
            }
        }
        __syncthreads();
        {
            int p = tid >> 5, cq = tid & 31;
            float4 m = make_float4(-3.4e38f, -3.4e38f, -3.4e38f, -3.4e38f);
#pragma unroll 4
            for (int e = 0; e < KNN; e++) {
                float4 v = *(float4*)&sD[(p*20+e)*C2_LDD + cq*4];
                m.x = fmaxf(m.x, v.x); m.y = fmaxf(m.y, v.y);
                m.z = fmaxf(m.z, v.z); m.w = fmaxf(m.w, v.w);
            }
            float4 bbv = *(float4*)&sbias[cq*4];
            m.x = fmaxf(m.x + bbv.x, 0.f); m.y = fmaxf(m.y + bbv.y, 0.f);
            m.z = fmaxf(m.z + bbv.z, 0.f); m.w = fmaxf(m.w + bbv.w, 0.f);
            ((float4*)g_x2)[(size_t)(ibase+p)*32 + cq] = m;
        }
    }
}

// ---------------- l1 (192->1024) tf32 GEMM + fused relu + P-max ----------------
__global__ __launch_bounds__(256) void l1max_kernel(
    const float* __restrict__ w, const float* __restrict__ bias)
{
    __shared__ float sA[128*20];
    __shared__ float sB[16*136];
    __shared__ float sbias[128];
    __shared__ unsigned int sred[128];
    int tid = threadIdx.x;
    int lane = tid & 31, warp = tid >> 5;
    int g4 = lane >> 2, tig = lane & 3;
    int b = blockIdx.z;
    int n0 = blockIdx.x * 128, m0 = blockIdx.y * 128;
    int pbase = b * PP + m0;
    const float4* x1v = (const float4*)g_x1;
    const float4* x2v = (const float4*)g_x2;
    const float4* wv  = (const float4*)w;
    if (tid < 128) { sred[tid] = 0u; sbias[tid] = bias[n0 + tid]; }

    int wm = warp >> 2, wn = warp & 3;
    float acc[4][4][4];
#pragma unroll
    for (int mi = 0; mi < 4; mi++)
#pragma unroll
        for (int ni = 0; ni < 4; ni++)
#pragma unroll
            for (int c = 0; c < 4; c++) acc[mi][ni][c] = 0.f;

    for (int ks = 0; ks < 12; ks++) {
        __syncthreads();
#pragma unroll
        for (int r = 0; r < 2; r++) {
            int fi = tid*2 + r;
            int pt = fi >> 2, kq = fi & 3;
            float4 v = (ks < 4) ? x1v[(size_t)(pbase+pt)*16 + ks*4 + kq]
                                : x2v[(size_t)(pbase+pt)*32 + (ks-4)*4 + kq];
            *(float4*)&sA[pt*20 + kq*4] =
                make_float4(tfbits(v.x), tfbits(v.y), tfbits(v.z), tfbits(v.w));
        }
#pragma unroll
        for (int r = 0; r < 2; r++) {
            int fi = tid*2 + r;
            int kk = fi >> 5, nq = fi & 31;
            float4 v = wv[(size_t)(ks*16+kk)*256 + (n0>>2) + nq];
            *(float4*)&sB[kk*136 + nq*4] =
                make_float4(tfbits(v.x), tfbits(v.y), tfbits(v.z), tfbits(v.w));
        }
        __syncthreads();
#pragma unroll
        for (int kh = 0; kh < 2; kh++) {
            int k0 = kh*8;
            uint32_t A[4][4];
#pragma unroll
            for (int mi = 0; mi < 4; mi++) {
                int row = wm*64 + mi*16 + g4;
                A[mi][0] = __float_as_uint(sA[row*20 + k0 + tig]);
                A[mi][1] = __float_as_uint(sA[(row+8)*20 + k0 + tig]);
                A[mi][2] = __float_as_uint(sA[row*20 + k0 + tig + 4]);
                A[mi][3] = __float_as_uint(sA[(row+8)*20 + k0 + tig + 4]);
            }
            uint32_t Bf[4][2];
#pragma unroll
            for (int ni = 0; ni < 4; ni++) {
                int col = wn*32 + ni*8 + g4;
                Bf[ni][0] = __float_as_uint(sB[(k0+tig)*136 + col]);
                Bf[ni][1] = __float_as_uint(sB[(k0+tig+4)*136 + col]);
            }
#pragma unroll
            for (int mi = 0; mi < 4; mi++)
#pragma unroll
                for (int ni = 0; ni < 4; ni++)
                    mma8(acc[mi][ni][0], acc[mi][ni][1], acc[mi][ni][2], acc[mi][ni][3],
                         A[mi][0], A[mi][1], A[mi][2], A[mi][3], Bf[ni][0], Bf[ni][1]);
        }
    }
#pragma unroll
    for (int ni = 0; ni < 4; ni++) {
        float v0 = -3.4e38f, v1 = -3.4e38f;
#pragma unroll
        for (int mi = 0; mi < 4; mi++) {
            v0 = fmaxf(v0, fmaxf(acc[mi][ni][0], acc[mi][ni][2]));
            v1 = fmaxf(v1, fmaxf(acc[mi][ni][1], acc[mi][ni][3]));
        }
#pragma unroll
        for (int off = 4; off < 32; off <<= 1) {
            v0 = fmaxf(v0, __shfl_xor_sync(0xffffffff, v0, off));
            v1 = fmaxf(v1, __shfl_xor_sync(0xffffffff, v1, off));
        }
        if (g4 == 0) {
            int col = wn*32 + ni*8 + tig*2;
            float a0 = fmaxf(v0 + sbias[col], 0.f);
            float a1 = fmaxf(v1 + sbias[col+1], 0.f);
            atomicMax(&sred[col],   __float_as_uint(a0));
            atomicMax(&sred[col+1], __float_as_uint(a1));
        }
    }
    __syncthreads();
    if (tid < 128) atomicMax(&g_pool[b*1024 + n0 + tid], sred[tid]);
}

// ---------------- head: 1024->512 relu ->256 relu ->40 + log_softmax ----------------
__global__ __launch_bounds__(256) void head_kernel(
    const float* __restrict__ w0, const float* __restrict__ b0,
    const float* __restrict__ w1, const float* __restrict__ b1,
    const float* __restrict__ w2, const float* __restrict__ b2,
    float* __restrict__ out)
{
    __shared__ float sp[1024], sh0[512], sh1[256], sl[40], red[2];
    int b = blockIdx.x, tid = threadIdx.x;
    for (int c = tid; c < 1024; c += 256) sp[c] = __uint_as_float(g_pool[b*1024 + c]);
    __syncthreads();
    {
        float a0 = b0[2*tid], a1 = b0[2*tid+1];
        const float2* w0v = (const float2*)w0;
        for (int c = 0; c < 1024; c++) {
            float f = sp[c];
            float2 wvv = w0v[c*256 + tid];
            a0 += f * wvv.x; a1 += f * wvv.y;
        }
        sh0[2*tid]   = fmaxf(a0, 0.f);
        sh0[2*tid+1] = fmaxf(a1, 0.f);
    }
    __syncthreads();
    {
        float a = b1[tid];
        for (int c = 0; c < 512; c++) a += sh0[c] * w1[c*256 + tid];
        sh1[tid] = fmaxf(a, 0.f);
    }
    __syncthreads();
    if (tid < 40) {
        float a = b2[tid];
        for (int c = 0; c < 256; c++) a += sh1[c] * w2[c*40 + tid];
        sl[tid] = a;
    }
    __syncthreads();
    if (tid == 0) {
        float mxv = -3.4e38f;
        for (int t = 0; t < 40; t++) mxv = fmaxf(mxv, sl[t]);
        float s = 0.f;
        for (int t = 0; t < 40; t++) s += expf(sl[t] - mxv);
        red[0] = mxv; red[1] = logf(s);
    }
    __syncthreads();
    if (tid < 40) out[b*40 + tid] = sl[tid] - red[0] - red[1];
}

// ---------------- launch ----------------
extern "C" void kernel_launch(void* const* d_in, const int* in_sizes, int n_in,
                              void* d_out, int out_size)
{
    const float* pos   = (const float*)d_in[0];
    const float* c1_w0 = (const float*)d_in[2];
    const float* c1_b0 = (const float*)d_in[3];
    const float* c1_w1 = (const float*)d_in[4];
    const float* c1_b1 = (const float*)d_in[5];
    const float* c1_w2 = (const float*)d_in[6];
    const float* c1_b2 = (const float*)d_in[7];
    const float* c2_w0 = (const float*)d_in[8];
    const float* c2_b0 = (const float*)d_in[9];
    const float* l1_w  = (const float*)d_in[10];
    const float* l1_b  = (const float*)d_in[11];
    const float* m_w0  = (const float*)d_in[12];
    const float* m_b0  = (const float*)d_in[13];
    const float* m_w1  = (const float*)d_in[14];
    const float* m_b1  = (const float*)d_in[15];
    const float* m_w2  = (const float*)d_in[16];
    const float* m_b2  = (const float*)d_in[17];
    float* out = (float*)d_out;

    const int smem_conv1 = (576 + 4608 + 4608 + 192 + 160*C1_LDD) * 4;          // 83456
    const int smem_knn2  = (2*128*KF_LDA + 128*KF_LDT + 256) * 4;               // 138240
    const int smem_conv2 = (128*C2_LDW + 160*C2_LDD + 8*64 + 128) * 4;          // 156672

    cudaFuncSetAttribute(conv1_kernel,    cudaFuncAttributeMaxDynamicSharedMemorySize, smem_conv1);
    cudaFuncSetAttribute(knn_feat_kernel, cudaFuncAttributeMaxDynamicSharedMemorySize, smem_knn2);
    cudaFuncSetAttribute(conv2_kernel,    cudaFuncAttributeMaxDynamicSharedMemorySize, smem_conv2);

    knn_pos_kernel<<<dim3(4, 32), 256>>>(pos);
    conv1_kernel<<<1024, 256, smem_conv1>>>(pos, c1_w0, c1_b0, c1_w1, c1_b1, c1_w2, c1_b2);
    knn_feat_kernel<<<dim3(8, 32), 256, smem_knn2>>>();
    conv2_kernel<<<1024, 256, smem_conv2>>>(c2_w0, c2_b0);
    l1max_kernel<<<dim3(8, 8, 32), 256>>>(l1_w, l1_b);
    head_kernel<<<32, 256>>>(m_w0, m_b0, m_w1, m_b1, m_w2, m_b2, out);
}

// round 6
// speedup vs baseline: 15.4451x; 1.0362x over previous
#include <cuda_runtime.h>
#include <math.h>
#include <stdint.h>

#define BB 32
#define PP 1024
#define KNN 20
#define NPTS (BB*PP)

// ---------------- scratch (device globals; no allocs allowed) ----------------
__device__ __align__(16) float g_x1[NPTS*64];
__device__ __align__(16) float g_x2[NPTS*128];
__device__ int g_idx[NPTS*KNN];
__device__ unsigned int g_pool[BB*1024];

// ---------------- tf32 mma helpers ----------------
__device__ __forceinline__ uint32_t f2tf(float x) {
    uint32_t r; asm("cvt.rna.tf32.f32 %0, %1;" : "=r"(r) : "f"(x)); return r;
}
__device__ __forceinline__ float tfbits(float x) {
    return __uint_as_float(f2tf(x));
}
__device__ __forceinline__ void mma8(float& c0, float& c1, float& c2, float& c3,
                                     uint32_t a0, uint32_t a1, uint32_t a2, uint32_t a3,
                                     uint32_t b0, uint32_t b1)
{
    asm volatile("mma.sync.aligned.m16n8k8.row.col.f32.tf32.tf32.f32 "
                 "{%0,%1,%2,%3},{%4,%5,%6,%7},{%8,%9},{%0,%1,%2,%3};"
                 : "+f"(c0), "+f"(c1), "+f"(c2), "+f"(c3)
                 : "r"(a0), "r"(a1), "r"(a2), "r"(a3), "r"(b0), "r"(b1));
}

// 5 m-tiles x 2 n-tiles warp GEMM (used by conv1)
__device__ __forceinline__ void mma_5x2(
    const float* sD, const float* sW, float acc[5][2][4],
    int mB, int nB, int g4, int tig, int ksteps, int ldd, int ldw)
{
#pragma unroll
    for (int mi = 0; mi < 5; mi++)
#pragma unroll
        for (int ni = 0; ni < 2; ni++)
#pragma unroll
            for (int c = 0; c < 4; c++) acc[mi][ni][c] = 0.f;
#pragma unroll 1
    for (int ks = 0; ks < ksteps; ks++) {
        int k0 = ks * 8;
        uint32_t A[5][4];
#pragma unroll
        for (int mi = 0; mi < 5; mi++) {
            int row = mB + mi*16 + g4;
            A[mi][0] = __float_as_uint(sD[row*ldd + k0 + tig]);
            A[mi][1] = __float_as_uint(sD[(row+8)*ldd + k0 + tig]);
            A[mi][2] = __float_as_uint(sD[row*ldd + k0 + tig + 4]);
            A[mi][3] = __float_as_uint(sD[(row+8)*ldd + k0 + tig + 4]);
        }
        uint32_t Bf[2][2];
#pragma unroll
        for (int ni = 0; ni < 2; ni++) {
            int col = nB + ni*8 + g4;
            Bf[ni][0] = __float_as_uint(sW[(k0+tig)*ldw + col]);
            Bf[ni][1] = __float_as_uint(sW[(k0+tig+4)*ldw + col]);
        }
#pragma unroll
        for (int mi = 0; mi < 5; mi++)
#pragma unroll
            for (int ni = 0; ni < 2; ni++)
                mma8(acc[mi][ni][0], acc[mi][ni][1], acc[mi][ni][2], acc[mi][ni][3],
                     A[mi][0], A[mi][1], A[mi][2], A[mi][3], Bf[ni][0], Bf[ni][1]);
    }
}

__device__ __forceinline__ void wb_5x2(
    float* sD, float acc[5][2][4], const float* bias,
    int mB, int nB, int g4, int tig, int ldd, int mode)
{
#pragma unroll
    for (int mi = 0; mi < 5; mi++) {
#pragma unroll
        for (int ni = 0; ni < 2; ni++) {
            int row = mB + mi*16 + g4, col = nB + ni*8 + tig*2;
            float v0 = acc[mi][ni][0], v1 = acc[mi][ni][1];
            float v2 = acc[mi][ni][2], v3 = acc[mi][ni][3];
            if (mode < 2) {
                float ba = bias[col], bb = bias[col+1];
                v0 += ba; v1 += bb; v2 += ba; v3 += bb;
            }
            if (mode == 1) {
                v0 = fmaxf(v0, 0.f); v1 = fmaxf(v1, 0.f);
                v2 = fmaxf(v2, 0.f); v3 = fmaxf(v3, 0.f);
            }
            if (mode < 2) { v0 = tfbits(v0); v1 = tfbits(v1); v2 = tfbits(v2); v3 = tfbits(v3); }
            sD[row*ldd + col] = v0;     sD[row*ldd + col + 1] = v1;
            sD[(row+8)*ldd + col] = v2; sD[(row+8)*ldd + col + 1] = v3;
        }
    }
}

// ---------------- KNN over 3-D positions (exact fp32) + pool zero ----------------
__global__ __launch_bounds__(256) void knn_pos_kernel(const float* __restrict__ pos)
{
    __shared__ float sx[PP], sy[PP], sz[PP], sq[PP];
    int b = blockIdx.y;
    g_pool[(blockIdx.y*4 + blockIdx.x)*256 + threadIdx.x] = 0u;
    const float* p = pos + (size_t)b * PP * 3;
    for (int j = threadIdx.x; j < PP; j += 256) {
        float x = p[3*j], y = p[3*j+1], z = p[3*j+2];
        sx[j] = x; sy[j] = y; sz[j] = z; sq[j] = x*x + y*y + z*z;
    }
    __syncthreads();
    int il = blockIdx.x * 256 + threadIdx.x;
    float xi = sx[il], yi = sy[il], zi = sz[il], sqi = sq[il];
    float bd[KNN]; int bi[KNN];
#pragma unroll
    for (int t = 0; t < KNN; t++) { bd[t] = 3.4e38f; bi[t] = 0; }
    for (int j = 0; j < PP; j++) {
        float d = sqi + sq[j] - 2.0f * (xi*sx[j] + yi*sy[j] + zi*sz[j]);
        if (d < bd[KNN-1]) {
            bd[KNN-1] = d; bi[KNN-1] = j;
#pragma unroll
            for (int t = KNN-1; t > 0; t--) {
                if (bd[t] < bd[t-1]) {
                    float td = bd[t]; bd[t] = bd[t-1]; bd[t-1] = td;
                    int ti = bi[t]; bi[t] = bi[t-1]; bi[t-1] = ti;
                }
            }
        }
    }
    int gi = b * PP + il;
#pragma unroll
    for (int t = 0; t < KNN; t++) g_idx[gi*KNN + t] = b * PP + bi[t];
}

// ---------------- EdgeConv1: tf32 tensor cores, 3 chained GEMMs in SMEM ----------------
#define C1_LDD 68
#define C1_LDW 72
__global__ __launch_bounds__(256, 2) void conv1_kernel(
    const float* __restrict__ pos,
    const float* __restrict__ w0, const float* __restrict__ b0,
    const float* __restrict__ w1, const float* __restrict__ b1,
    const float* __restrict__ w2, const float* __restrict__ b2)
{
    extern __shared__ float sm[];
    float* sW0 = sm;
    float* sW1 = sm + 576;
    float* sW2 = sm + 5184;
    float* sb0 = sm + 9792;
    float* sb1 = sm + 9856;
    float* sb2 = sm + 9920;
    float* sD  = sm + 9984;     // 160*68

    int tid = threadIdx.x, lane = tid & 31, warp = tid >> 5;
    int g4 = lane >> 2, tig = lane & 3;
    int wm = warp >> 2, wn = warp & 3;
    int mB = wm * 80, nB = wn * 16;

    for (int fi = tid; fi < 512; fi += 256) {
        int kk = fi >> 6, o = fi & 63;
        sW0[kk*C1_LDW + o] = (kk < 6) ? tfbits(w0[kk*64 + o]) : 0.f;
    }
    for (int fi = tid; fi < 4096; fi += 256) {
        int kk = fi >> 6, o = fi & 63;
        sW1[kk*C1_LDW + o] = tfbits(w1[fi]);
        sW2[kk*C1_LDW + o] = tfbits(w2[fi]);
    }
    if (tid < 64) { sb0[tid] = b0[tid]; sb1[tid] = b1[tid]; sb2[tid] = b2[tid]; }

    float acc[5][2][4];
    for (int gi = 0; gi < 4; gi++) {
        int ibase = (blockIdx.x*4 + gi) * 8;
        __syncthreads();
        if (tid < 160) {
            int p = tid / 20, e = tid - p*20;
            int i = ibase + p;
            int j = g_idx[i*KNN + e];
            float xx = pos[i*3], xy = pos[i*3+1], xz = pos[i*3+2];
            float jx = pos[j*3], jy = pos[j*3+1], jz = pos[j*3+2];
            float* dr = sD + tid*C1_LDD;
            dr[0] = tfbits(xx); dr[1] = tfbits(xy); dr[2] = tfbits(xz);
            dr[3] = tfbits(jx-xx); dr[4] = tfbits(jy-xy); dr[5] = tfbits(jz-xz);
            dr[6] = 0.f; dr[7] = 0.f;
        }
        __syncthreads();
        mma_5x2(sD, sW0, acc, mB, nB, g4, tig, 1, C1_LDD, C1_LDW);
        __syncthreads();
        wb_5x2(sD, acc, sb0, mB, nB, g4, tig, C1_LDD, 0);
        __syncthreads();
        mma_5x2(sD, sW1, acc, mB, nB, g4, tig, 8, C1_LDD, C1_LDW);
        __syncthreads();
        wb_5x2(sD, acc, sb1, mB, nB, g4, tig, C1_LDD, 1);
        __syncthreads();
        mma_5x2(sD, sW2, acc, mB, nB, g4, tig, 8, C1_LDD, C1_LDW);
        __syncthreads();
        wb_5x2(sD, acc, sb2, mB, nB, g4, tig, C1_LDD, 2);
        __syncthreads();
        {
            int p = tid >> 5, cq = tid & 31;
            float2 m = make_float2(-3.4e38f, -3.4e38f);
#pragma unroll 4
            for (int e = 0; e < KNN; e++) {
                float2 v = *(float2*)&sD[(p*20+e)*C1_LDD + cq*2];
                m.x = fmaxf(m.x, v.x); m.y = fmaxf(m.y, v.y);
            }
            float2 bbv = *(float2*)&sb2[cq*2];
            m.x = fmaxf(m.x + bbv.x, 0.f);
            m.y = fmaxf(m.y + bbv.y, 0.f);
            ((float2*)g_x1)[(size_t)(ibase+p)*32 + cq] = m;
        }
    }
}

// ---------------- KNN over 64-D features: tf32 MMA dot matrix + top-k scan ----------------
#define KF_LDA 68
#define KF_LDT 132
__global__ __launch_bounds__(256) void knn_feat_kernel()
{
    extern __shared__ float sm[];
    float* sA   = sm;
    float* sB   = sm + 128*KF_LDA;
    float* sdot = sm + 2*128*KF_LDA;
    float* sqi  = sdot + 128*KF_LDT;
    float* sqj  = sqi + 128;

    int tid = threadIdx.x, lane = tid & 31, warp = tid >> 5;
    int g4 = lane >> 2, tig = lane & 3;
    int wm = warp >> 2, wn = warp & 3;
    int b = blockIdx.y;
    int i0 = b*PP + blockIdx.x*128;
    const float4* x1v = (const float4*)g_x1;

    for (int fi = tid; fi < 128*16; fi += 256) {
        int pt = fi >> 4, q = fi & 15;
        float4 v = x1v[(size_t)(i0+pt)*16 + q];
        *(float4*)&sA[pt*KF_LDA + q*4] =
            make_float4(tfbits(v.x), tfbits(v.y), tfbits(v.z), tfbits(v.w));
    }
    if (tid < 128) {
        float s = 0.f;
#pragma unroll
        for (int q = 0; q < 16; q++) {
            float4 v = x1v[(size_t)(i0+tid)*16 + q];
            s += v.x*v.x + v.y*v.y + v.z*v.z + v.w*v.w;
        }
        sqi[tid] = s;
    }

    float bd[KNN]; int bi[KNN];
#pragma unroll
    for (int t = 0; t < KNN; t++) { bd[t] = 3.4e38f; bi[t] = 0; }
    float mysq = 0.f;

    for (int jt = 0; jt < 8; jt++) {
        int j0 = b*PP + jt*128;
        __syncthreads();
        for (int fi = tid; fi < 128*16; fi += 256) {
            int pt = fi >> 4, q = fi & 15;
            float4 v = x1v[(size_t)(j0+pt)*16 + q];
            *(float4*)&sB[pt*KF_LDA + q*4] =
                make_float4(tfbits(v.x), tfbits(v.y), tfbits(v.z), tfbits(v.w));
        }
        if (tid < 128) {
            float s = 0.f;
#pragma unroll
            for (int q = 0; q < 16; q++) {
                float4 v = x1v[(size_t)(j0+tid)*16 + q];
                s += v.x*v.x + v.y*v.y + v.z*v.z + v.w*v.w;
            }
            sqj[tid] = s;
        }
        __syncthreads();
        float acc[4][4][4];
#pragma unroll
        for (int mi = 0; mi < 4; mi++)
#pragma unroll
            for (int ni = 0; ni < 4; ni++)
#pragma unroll
                for (int c = 0; c < 4; c++) acc[mi][ni][c] = 0.f;
#pragma unroll
        for (int ks = 0; ks < 8; ks++) {
            int k0 = ks*8;
            uint32_t A[4][4];
#pragma unroll
            for (int mi = 0; mi < 4; mi++) {
                int row = wm*64 + mi*16 + g4;
                A[mi][0] = __float_as_uint(sA[row*KF_LDA + k0 + tig]);
                A[mi][1] = __float_as_uint(sA[(row+8)*KF_LDA + k0 + tig]);
                A[mi][2] = __float_as_uint(sA[row*KF_LDA + k0 + tig + 4]);
                A[mi][3] = __float_as_uint(sA[(row+8)*KF_LDA + k0 + tig + 4]);
            }
            uint32_t Bf[4][2];
#pragma unroll
            for (int ni = 0; ni < 4; ni++) {
                int col = wn*32 + ni*8 + g4;
                Bf[ni][0] = __float_as_uint(sB[col*KF_LDA + k0 + tig]);
                Bf[ni][1] = __float_as_uint(sB[col*KF_LDA + k0 + tig + 4]);
            }
#pragma unroll
            for (int mi = 0; mi < 4; mi++)
#pragma unroll
                for (int ni = 0; ni < 4; ni++)
                    mma8(acc[mi][ni][0], acc[mi][ni][1], acc[mi][ni][2], acc[mi][ni][3],
                         A[mi][0], A[mi][1], A[mi][2], A[mi][3], Bf[ni][0], Bf[ni][1]);
        }
#pragma unroll
        for (int mi = 0; mi < 4; mi++) {
#pragma unroll
            for (int ni = 0; ni < 4; ni++) {
                int row = wm*64 + mi*16 + g4, col = wn*32 + ni*8 + tig*2;
                *(float2*)&sdot[row*KF_LDT + col]     = make_float2(acc[mi][ni][0], acc[mi][ni][1]);
                *(float2*)&sdot[(row+8)*KF_LDT + col] = make_float2(acc[mi][ni][2], acc[mi][ni][3]);
            }
        }
        __syncthreads();
        if (tid < 128) {
            if (jt == 0) mysq = sqi[tid];
            const float* drow = sdot + tid*KF_LDT;
            int jbase = jt*128;
            for (int j = 0; j < 128; j++) {
                float d = mysq + sqj[j] - 2.0f * drow[j];
                if (d < bd[KNN-1]) {
                    bd[KNN-1] = d; bi[KNN-1] = jbase + j;
#pragma unroll
                    for (int t = KNN-1; t > 0; t--) {
                        if (bd[t] < bd[t-1]) {
                            float td = bd[t]; bd[t] = bd[t-1]; bd[t-1] = td;
                            int ti = bi[t]; bi[t] = bi[t-1]; bi[t-1] = ti;
                        }
                    }
                }
            }
        }
    }
    if (tid < 128) {
        int gi = i0 + tid;
#pragma unroll
        for (int t = 0; t < KNN; t++) g_idx[(size_t)gi*KNN + t] = b*PP + bi[t];
    }
}

// ---------------- EdgeConv2 v3: base (SIMT, exact) + diff GEMM (tf32, K=64) ----------------
// out = relu( xi@W_top + b + max_e( diff_e@W_bot ) ).  83 KB SMEM -> 2 blocks/SM.
#define C2_LDD 68
#define C2_LDW 136
#define C2_LDB 132
__global__ __launch_bounds__(256, 2) void conv2_kernel(
    const float* __restrict__ w, const float* __restrict__ bias)
{
    extern __shared__ float sm[];
    float* sWb   = sm;                        // 64*136 (W rows 64..127, tf32)
    float* sD    = sm + 64*C2_LDW;            // 160*68 diff tf32
    float* sXi   = sD + 160*C2_LDD;           // 8*68 exact fp32
    float* sBase = sXi + 8*68;                // 8*132
    float* sbias = sBase + 8*C2_LDB;          // 128

    int tid = threadIdx.x, lane = tid & 31, warp = tid >> 5;
    int g4 = lane >> 2, tig = lane & 3;
    int wm = warp >> 2, wn = warp & 3;
    int mB = wm*80, nB = wn*32;

    // stage W_bot (tf32) + bias
    for (int fi = tid; fi < 2048; fi += 256) {
        int kk = fi >> 5, nq = fi & 31;
        float4 v = ((const float4*)w)[(64+kk)*32 + nq];
        *(float4*)&sWb[kk*C2_LDW + nq*4] =
            make_float4(tfbits(v.x), tfbits(v.y), tfbits(v.z), tfbits(v.w));
    }
    if (tid < 128) sbias[tid] = bias[tid];

    const float4* x1v = (const float4*)g_x1;

    for (int gi = 0; gi < 4; gi++) {
        int ibase = (blockIdx.x*4 + gi) * 8;
        __syncthreads();
        if (tid < 128) {
            int p = tid >> 4, q = tid & 15;
            *(float4*)&sXi[p*68 + q*4] = x1v[(size_t)(ibase+p)*16 + q];
        }
        __syncthreads();
        // build diff rows (tid<160) — only the xj-xi half
        if (tid < 160) {
            int p = tid/20, e = tid - p*20;
            int j = g_idx[(size_t)(ibase+p)*KNN + e];
            float* drow = sD + tid*C2_LDD;
            const float* xir = &sXi[p*68];
#pragma unroll 4
            for (int q = 0; q < 16; q++) {
                float4 xj = x1v[(size_t)j*16 + q];
                float4 xi = *(const float4*)&xir[q*4];
                *(float4*)&drow[q*4] =
                    make_float4(tfbits(xj.x-xi.x), tfbits(xj.y-xi.y),
                                tfbits(xj.z-xi.z), tfbits(xj.w-xi.w));
            }
        }
        // base[p][col] = bias[col] + sum_k xi[p][k] * w[k][col]  (exact fp32 SIMT)
        {
            int p = tid >> 5;
            const float* xir = &sXi[p*68];
            float4 acc4 = *(const float4*)&sbias[lane*4];
#pragma unroll 8
            for (int k = 0; k < 64; k++) {
                float xv = xir[k];
                float4 wv = ((const float4*)w)[k*32 + lane];
                acc4.x = fmaf(xv, wv.x, acc4.x); acc4.y = fmaf(xv, wv.y, acc4.y);
                acc4.z = fmaf(xv, wv.z, acc4.z); acc4.w = fmaf(xv, wv.w, acc4.w);
            }
            *(float4*)&sBase[p*C2_LDB + lane*4] = acc4;
        }
        __syncthreads();
        // diff GEMM: [160][64] x [64][128]; warp tile M=80, N=32, 8 k-steps
        float acc[5][4][4];
#pragma unroll
        for (int mi = 0; mi < 5; mi++)
#pragma unroll
            for (int ni = 0; ni < 4; ni++)
#pragma unroll
                for (int c = 0; c < 4; c++) acc[mi][ni][c] = 0.f;
#pragma unroll 1
        for (int ks = 0; ks < 8; ks++) {
            int k0 = ks*8;
            uint32_t A[5][4];
#pragma unroll
            for (int mi = 0; mi < 5; mi++) {
                int row = mB + mi*16 + g4;
                A[mi][0] = __float_as_uint(sD[row*C2_LDD + k0 + tig]);
                A[mi][1] = __float_as_uint(sD[(row+8)*C2_LDD + k0 + tig]);
                A[mi][2] = __float_as_uint(sD[row*C2_LDD + k0 + tig + 4]);
                A[mi][3] = __float_as_uint(sD[(row+8)*C2_LDD + k0 + tig + 4]);
            }
            uint32_t Bf[4][2];
#pragma unroll
            for (int ni = 0; ni < 4; ni++) {
                int col = nB + ni*8 + g4;
                Bf[ni][0] = __float_as_uint(sWb[(k0+tig)*C2_LDW + col]);
                Bf[ni][1] = __float_as_uint(sWb[(k0+tig+4)*C2_LDW + col]);
            }
#pragma unroll
            for (int mi = 0; mi < 5; mi++)
#pragma unroll
                for (int ni = 0; ni < 4; ni++)
                    mma8(acc[mi][ni][0], acc[mi][ni][1], acc[mi][ni][2], acc[mi][ni][3],
                         A[mi][0], A[mi][1], A[mi][2], A[mi][3], Bf[ni][0], Bf[ni][1]);
        }
        // register epilogue: per-point max over edges without SMEM round-trip.
        // warp rows mB..mB+79 = points wp0..wp0+3 (20 rows each).
        float pm[4][4][2];
#pragma unroll
        for (int p = 0; p < 4; p++)
#pragma unroll
            for (int ni = 0; ni < 4; ni++) { pm[p][ni][0] = -3.4e38f; pm[p][ni][1] = -3.4e38f; }
        bool hi1 = (g4 >= 4);   // mi=1 low half: rows 16..23 -> p0 (g4<4) else p1
        bool hi3 = (g4 >= 4);   // mi=3 high half: rows 56..63 -> p2 (g4<4) else p3
#pragma unroll
        for (int ni = 0; ni < 4; ni++) {
            // low halves (row = mi*16+g4)
            pm[0][ni][0] = fmaxf(pm[0][ni][0], acc[0][ni][0]);
            pm[0][ni][1] = fmaxf(pm[0][ni][1], acc[0][ni][1]);
            if (!hi1) { pm[0][ni][0] = fmaxf(pm[0][ni][0], acc[1][ni][0]);
                        pm[0][ni][1] = fmaxf(pm[0][ni][1], acc[1][ni][1]); }
            else      { pm[1][ni][0] = fmaxf(pm[1][ni][0], acc[1][ni][0]);
                        pm[1][ni][1] = fmaxf(pm[1][ni][1], acc[1][ni][1]); }
            pm[1][ni][0] = fmaxf(pm[1][ni][0], acc[2][ni][0]);
            pm[1][ni][1] = fmaxf(pm[1][ni][1], acc[2][ni][1]);
            pm[2][ni][0] = fmaxf(pm[2][ni][0], acc[3][ni][0]);
            pm[2][ni][1] = fmaxf(pm[2][ni][1], acc[3][ni][1]);
            pm[3][ni][0] = fmaxf(pm[3][ni][0], acc[4][ni][0]);
            pm[3][ni][1] = fmaxf(pm[3][ni][1], acc[4][ni][1]);
            // high halves (row = mi*16+g4+8)
            pm[0][ni][0] = fmaxf(pm[0][ni][0], acc[0][ni][2]);
            pm[0][ni][1] = fmaxf(pm[0][ni][1], acc[0][ni][3]);
            pm[1][ni][0] = fmaxf(pm[1][ni][0], acc[1][ni][2]);
            pm[1][ni][1] = fmaxf(pm[1][ni][1], acc[1][ni][3]);
            pm[2][ni][0] = fmaxf(pm[2][ni][0], acc[2][ni][2]);
            pm[2][ni][1] = fmaxf(pm[2][ni][1], acc[2][ni][3]);
            if (!hi3) { pm[2][ni][0] = fmaxf(pm[2][ni][0], acc[3][ni][2]);
                        pm[2][ni][1] = fmaxf(pm[2][ni][1], acc[3][ni][3]); }
            else      { pm[3][ni][0] = fmaxf(pm[3][ni][0], acc[3][ni][2]);
                        pm[3][ni][1] = fmaxf(pm[3][ni][1], acc[3][ni][3]); }
            pm[3][ni][0] = fmaxf(pm[3][ni][0], acc[4][ni][2]);
            pm[3][ni][1] = fmaxf(pm[3][ni][1], acc[4][ni][3]);
        }
        // reduce across the 8 g4 lanes (same tig = same columns)
#pragma unroll
        for (int off = 4; off < 32; off <<= 1)
#pragma unroll
            for (int p = 0; p < 4; p++)
#pragma unroll
                for (int ni = 0; ni < 4; ni++) {
                    pm[p][ni][0] = fmaxf(pm[p][ni][0], __shfl_xor_sync(0xffffffff, pm[p][ni][0], off));
                    pm[p][ni][1] = fmaxf(pm[p][ni][1], __shfl_xor_sync(0xffffffff, pm[p][ni][1], off));
                }
        if (g4 == 0) {
#pragma unroll
            for (int p = 0; p < 4; p++) {
                int wp = wm*4 + p;
#pragma unroll
                for (int ni = 0; ni < 4; ni++) {
                    int col = nB + ni*8 + tig*2;
                    float b0v = sBase[wp*C2_LDB + col];
                    float b1v = sBase[wp*C2_LDB + col + 1];
                    float2 o;
                    o.x = fmaxf(pm[p][ni][0] + b0v, 0.f);
                    o.y = fmaxf(pm[p][ni][1] + b1v, 0.f);
                    *(float2*)&g_x2[(size_t)(ibase+wp)*128 + col] = o;
                }
            }
        }
    }
}

// ---------------- l1 (192->1024) tf32 GEMM + fused relu + P-max ----------------
__global__ __launch_bounds__(256) void l1max_kernel(
    const float* __restrict__ w, const float* __restrict__ bias)
{
    __shared__ float sA[128*20];
    __shared__ float sB[16*136];
    __shared__ float sbias[128];
    __shared__ unsigned int sred[128];
    int tid = threadIdx.x;
    int lane = tid & 31, warp = tid >> 5;
    int g4 = lane >> 2, tig = lane & 3;
    int b = blockIdx.z;
    int n0 = blockIdx.x * 128, m0 = blockIdx.y * 128;
    int pbase = b * PP + m0;
    const float4* x1v = (const float4*)g_x1;
    const float4* x2v = (const float4*)g_x2;
    const float4* wv  = (const float4*)w;
    if (tid < 128) { sred[tid] = 0u; sbias[tid] = bias[n0 + tid]; }

    int wm = warp >> 2, wn = warp & 3;
    float acc[4][4][4];
#pragma unroll
    for (int mi = 0; mi < 4; mi++)
#pragma unroll
        for (int ni = 0; ni < 4; ni++)
#pragma unroll
            for (int c = 0; c < 4; c++) acc[mi][ni][c] = 0.f;

    for (int ks = 0; ks < 12; ks++) {
        __syncthreads();
#pragma unroll
        for (int r = 0; r < 2; r++) {
            int fi = tid*2 + r;
            int pt = fi >> 2, kq = fi & 3;
            float4 v = (ks < 4) ? x1v[(size_t)(pbase+pt)*16 + ks*4 + kq]
                                : x2v[(size_t)(pbase+pt)*32 + (ks-4)*4 + kq];
            *(float4*)&sA[pt*20 + kq*4] =
                make_float4(tfbits(v.x), tfbits(v.y), tfbits(v.z), tfbits(v.w));
        }
#pragma unroll
        for (int r = 0; r < 2; r++) {
            int fi = tid*2 + r;
            int kk = fi >> 5, nq = fi & 31;
            float4 v = wv[(size_t)(ks*16+kk)*256 + (n0>>2) + nq];
            *(float4*)&sB[kk*136 + nq*4] =
                make_float4(tfbits(v.x), tfbits(v.y), tfbits(v.z), tfbits(v.w));
        }
        __syncthreads();
#pragma unroll
        for (int kh = 0; kh < 2; kh++) {
            int k0 = kh*8;
            uint32_t A[4][4];
#pragma unroll
            for (int mi = 0; mi < 4; mi++) {
                int row = wm*64 + mi*16 + g4;
                A[mi][0] = __float_as_uint(sA[row*20 + k0 + tig]);
                A[mi][1] = __float_as_uint(sA[(row+8)*20 + k0 + tig]);
                A[mi][2] = __float_as_uint(sA[row*20 + k0 + tig + 4]);
                A[mi][3] = __float_as_uint(sA[(row+8)*20 + k0 + tig + 4]);
            }
            uint32_t Bf[4][2];
#pragma unroll
            for (int ni = 0; ni < 4; ni++) {
                int col = wn*32 + ni*8 + g4;
                Bf[ni][0] = __float_as_uint(sB[(k0+tig)*136 + col]);
                Bf[ni][1] = __float_as_uint(sB[(k0+tig+4)*136 + col]);
            }
#pragma unroll
            for (int mi = 0; mi < 4; mi++)
#pragma unroll
                for (int ni = 0; ni < 4; ni++)
                    mma8(acc[mi][ni][0], acc[mi][ni][1], acc[mi][ni][2], acc[mi][ni][3],
                         A[mi][0], A[mi][1], A[mi][2], A[mi][3], Bf[ni][0], Bf[ni][1]);
        }
    }
#pragma unroll
    for (int ni = 0; ni < 4; ni++) {
        float v0 = -3.4e38f, v1 = -3.4e38f;
#pragma unroll
        for (int mi = 0; mi < 4; mi++) {
            v0 = fmaxf(v0, fmaxf(acc[mi][ni][0], acc[mi][ni][2]));
            v1 = fmaxf(v1, fmaxf(acc[mi][ni][1], acc[mi][ni][3]));
        }
#pragma unroll
        for (int off = 4; off < 32; off <<= 1) {
            v0 = fmaxf(v0, __shfl_xor_sync(0xffffffff, v0, off));
            v1 = fmaxf(v1, __shfl_xor_sync(0xffffffff, v1, off));
        }
        if (g4 == 0) {
            int col = wn*32 + ni*8 + tig*2;
            float a0 = fmaxf(v0 + sbias[col], 0.f);
            float a1 = fmaxf(v1 + sbias[col+1], 0.f);
            atomicMax(&sred[col],   __float_as_uint(a0));
            atomicMax(&sred[col+1], __float_as_uint(a1));
        }
    }
    __syncthreads();
    if (tid < 128) atomicMax(&g_pool[b*1024 + n0 + tid], sred[tid]);
}

// ---------------- head: 1024->512 relu ->256 relu ->40 + log_softmax ----------------
__global__ __launch_bounds__(256) void head_kernel(
    const float* __restrict__ w0, const float* __restrict__ b0,
    const float* __restrict__ w1, const float* __restrict__ b1,
    const float* __restrict__ w2, const float* __restrict__ b2,
    float* __restrict__ out)
{
    __shared__ float sp[1024], sh0[512], sh1[256], sl[40], red[2];
    int b = blockIdx.x, tid = threadIdx.x;
    for (int c = tid; c < 1024; c += 256) sp[c] = __uint_as_float(g_pool[b*1024 + c]);
    __syncthreads();
    {
        float a0 = b0[2*tid], a1 = b0[2*tid+1];
        const float2* w0v = (const float2*)w0;
        for (int c = 0; c < 1024; c++) {
            float f = sp[c];
            float2 wvv = w0v[c*256 + tid];
            a0 += f * wvv.x; a1 += f * wvv.y;
        }
        sh0[2*tid]   = fmaxf(a0, 0.f);
        sh0[2*tid+1] = fmaxf(a1, 0.f);
    }
    __syncthreads();
    {
        float a = b1[tid];
        for (int c = 0; c < 512; c++) a += sh0[c] * w1[c*256 + tid];
        sh1[tid] = fmaxf(a, 0.f);
    }
    __syncthreads();
    if (tid < 40) {
        float a = b2[tid];
        for (int c = 0; c < 256; c++) a += sh1[c] * w2[c*40 + tid];
        sl[tid] = a;
    }
    __syncthreads();
    if (tid == 0) {
        float mxv = -3.4e38f;
        for (int t = 0; t < 40; t++) mxv = fmaxf(mxv, sl[t]);
        float s = 0.f;
        for (int t = 0; t < 40; t++) s += expf(sl[t] - mxv);
        red[0] = mxv; red[1] = logf(s);
    }
    __syncthreads();
    if (tid < 40) out[b*40 + tid] = sl[tid] - red[0] - red[1];
}

// ---------------- launch ----------------
extern "C" void kernel_launch(void* const* d_in, const int* in_sizes, int n_in,
                              void* d_out, int out_size)
{
    const float* pos   = (const float*)d_in[0];
    const float* c1_w0 = (const float*)d_in[2];
    const float* c1_b0 = (const float*)d_in[3];
    const float* c1_w1 = (const float*)d_in[4];
    const float* c1_b1 = (const float*)d_in[5];
    const float* c1_w2 = (const float*)d_in[6];
    const float* c1_b2 = (const float*)d_in[7];
    const float* c2_w0 = (const float*)d_in[8];
    const float* c2_b0 = (const float*)d_in[9];
    const float* l1_w  = (const float*)d_in[10];
    const float* l1_b  = (const float*)d_in[11];
    const float* m_w0  = (const float*)d_in[12];
    const float* m_b0  = (const float*)d_in[13];
    const float* m_w1  = (const float*)d_in[14];
    const float* m_b1  = (const float*)d_in[15];
    const float* m_w2  = (const float*)d_in[16];
    const float* m_b2  = (const float*)d_in[17];
    float* out = (float*)d_out;

    const int smem_conv1 = (576 + 4608 + 4608 + 192 + 160*C1_LDD) * 4;          // 83456
    const int smem_knn2  = (2*128*KF_LDA + 128*KF_LDT + 256) * 4;               // 138240
    const int smem_conv2 = (64*C2_LDW + 160*C2_LDD + 8*68 + 8*C2_LDB + 128) * 4; // ~85 KB

    cudaFuncSetAttribute(conv1_kernel,    cudaFuncAttributeMaxDynamicSharedMemorySize, smem_conv1);
    cudaFuncSetAttribute(knn_feat_kernel, cudaFuncAttributeMaxDynamicSharedMemorySize, smem_knn2);
    cudaFuncSetAttribute(conv2_kernel,    cudaFuncAttributeMaxDynamicSharedMemorySize, smem_conv2);

    knn_pos_kernel<<<dim3(4, 32), 256>>>(pos);
    conv1_kernel<<<1024, 256, smem_conv1>>>(pos, c1_w0, c1_b0, c1_w1, c1_b1, c1_w2, c1_b2);
    knn_feat_kernel<<<dim3(8, 32), 256, smem_knn2>>>();
    conv2_kernel<<<1024, 256, smem_conv2>>>(c2_w0, c2_b0);
    l1max_kernel<<<dim3(8, 8, 32), 256>>>(l1_w, l1_b);
    head_kernel<<<32, 256>>>(m_w0, m_b0, m_w1, m_b1, m_w2, m_b2, out);
}

// round 7
// speedup vs baseline: 15.6364x; 1.0124x over previous
#include <cuda_runtime.h>
#include <math.h>
#include <stdint.h>

#define BB 32
#define PP 1024
#define KNN 20
#define NPTS (BB*PP)

// ---------------- scratch (device globals; no allocs allowed) ----------------
__device__ __align__(16) float g_x1[NPTS*64];
__device__ __align__(16) float g_x2[NPTS*128];
__device__ int g_idx[NPTS*KNN];
__device__ unsigned int g_pool[BB*1024];

// ---------------- tf32 mma helpers ----------------
__device__ __forceinline__ uint32_t f2tf(float x) {
    uint32_t r; asm("cvt.rna.tf32.f32 %0, %1;" : "=r"(r) : "f"(x)); return r;
}
__device__ __forceinline__ float tfbits(float x) {
    return __uint_as_float(f2tf(x));
}
__device__ __forceinline__ void mma8(float& c0, float& c1, float& c2, float& c3,
                                     uint32_t a0, uint32_t a1, uint32_t a2, uint32_t a3,
                                     uint32_t b0, uint32_t b1)
{
    asm volatile("mma.sync.aligned.m16n8k8.row.col.f32.tf32.tf32.f32 "
                 "{%0,%1,%2,%3},{%4,%5,%6,%7},{%8,%9},{%0,%1,%2,%3};"
                 : "+f"(c0), "+f"(c1), "+f"(c2), "+f"(c3)
                 : "r"(a0), "r"(a1), "r"(a2), "r"(a3), "r"(b0), "r"(b1));
}

// top-k insertion (strict <, keeps earliest index on ties — matches jax top_k)
__device__ __forceinline__ void topk_insert(float* bd, int* bi, float d, int j)
{
    if (d < bd[KNN-1]) {
        bd[KNN-1] = d; bi[KNN-1] = j;
#pragma unroll
        for (int t = KNN-1; t > 0; t--) {
            if (bd[t] < bd[t-1]) {
                float td = bd[t]; bd[t] = bd[t-1]; bd[t-1] = td;
                int ti = bi[t]; bi[t] = bi[t-1]; bi[t-1] = ti;
            }
        }
    }
}

// 5 m-tiles x 2 n-tiles warp GEMM (used by conv1)
__device__ __forceinline__ void mma_5x2(
    const float* sD, const float* sW, float acc[5][2][4],
    int mB, int nB, int g4, int tig, int ksteps, int ldd, int ldw)
{
#pragma unroll
    for (int mi = 0; mi < 5; mi++)
#pragma unroll
        for (int ni = 0; ni < 2; ni++)
#pragma unroll
            for (int c = 0; c < 4; c++) acc[mi][ni][c] = 0.f;
#pragma unroll 1
    for (int ks = 0; ks < ksteps; ks++) {
        int k0 = ks * 8;
        uint32_t A[5][4];
#pragma unroll
        for (int mi = 0; mi < 5; mi++) {
            int row = mB + mi*16 + g4;
            A[mi][0] = __float_as_uint(sD[row*ldd + k0 + tig]);
            A[mi][1] = __float_as_uint(sD[(row+8)*ldd + k0 + tig]);
            A[mi][2] = __float_as_uint(sD[row*ldd + k0 + tig + 4]);
            A[mi][3] = __float_as_uint(sD[(row+8)*ldd + k0 + tig + 4]);
        }
        uint32_t Bf[2][2];
#pragma unroll
        for (int ni = 0; ni < 2; ni++) {
            int col = nB + ni*8 + g4;
            Bf[ni][0] = __float_as_uint(sW[(k0+tig)*ldw + col]);
            Bf[ni][1] = __float_as_uint(sW[(k0+tig+4)*ldw + col]);
        }
#pragma unroll
        for (int mi = 0; mi < 5; mi++)
#pragma unroll
            for (int ni = 0; ni < 2; ni++)
                mma8(acc[mi][ni][0], acc[mi][ni][1], acc[mi][ni][2], acc[mi][ni][3],
                     A[mi][0], A[mi][1], A[mi][2], A[mi][3], Bf[ni][0], Bf[ni][1]);
    }
}

__device__ __forceinline__ void wb_5x2(
    float* sD, float acc[5][2][4], const float* bias,
    int mB, int nB, int g4, int tig, int ldd, int mode)
{
#pragma unroll
    for (int mi = 0; mi < 5; mi++) {
#pragma unroll
        for (int ni = 0; ni < 2; ni++) {
            int row = mB + mi*16 + g4, col = nB + ni*8 + tig*2;
            float v0 = acc[mi][ni][0], v1 = acc[mi][ni][1];
            float v2 = acc[mi][ni][2], v3 = acc[mi][ni][3];
            if (mode < 2) {
                float ba = bias[col], bb = bias[col+1];
                v0 += ba; v1 += bb; v2 += ba; v3 += bb;
            }
            if (mode == 1) {
                v0 = fmaxf(v0, 0.f); v1 = fmaxf(v1, 0.f);
                v2 = fmaxf(v2, 0.f); v3 = fmaxf(v3, 0.f);
            }
            if (mode < 2) { v0 = tfbits(v0); v1 = tfbits(v1); v2 = tfbits(v2); v3 = tfbits(v3); }
            sD[row*ldd + col] = v0;     sD[row*ldd + col + 1] = v1;
            sD[(row+8)*ldd + col] = v2; sD[(row+8)*ldd + col + 1] = v3;
        }
    }
}

// ---------------- KNN over 3-D positions (exact fp32) + pool zero ----------------
__global__ __launch_bounds__(256) void knn_pos_kernel(const float* __restrict__ pos)
{
    __shared__ float4 spos[PP];   // (x, y, z, |x|^2)
    int b = blockIdx.y;
    g_pool[(blockIdx.y*4 + blockIdx.x)*256 + threadIdx.x] = 0u;
    const float* p = pos + (size_t)b * PP * 3;
    for (int j = threadIdx.x; j < PP; j += 256) {
        float x = p[3*j], y = p[3*j+1], z = p[3*j+2];
        spos[j] = make_float4(x, y, z, x*x + y*y + z*z);
    }
    __syncthreads();
    int il = blockIdx.x * 256 + threadIdx.x;
    float4 me = spos[il];
    float xi = me.x, yi = me.y, zi = me.z, sqi = me.w;
    float bd[KNN]; int bi[KNN];
#pragma unroll
    for (int t = 0; t < KNN; t++) { bd[t] = 3.4e38f; bi[t] = 0; }
    for (int j4 = 0; j4 < PP/4; j4++) {
        float4 v0 = spos[4*j4+0], v1 = spos[4*j4+1], v2 = spos[4*j4+2], v3 = spos[4*j4+3];
        float d0 = sqi + v0.w - 2.0f*(xi*v0.x + yi*v0.y + zi*v0.z);
        float d1 = sqi + v1.w - 2.0f*(xi*v1.x + yi*v1.y + zi*v1.z);
        float d2 = sqi + v2.w - 2.0f*(xi*v2.x + yi*v2.y + zi*v2.z);
        float d3 = sqi + v3.w - 2.0f*(xi*v3.x + yi*v3.y + zi*v3.z);
        float mn = fminf(fminf(d0, d1), fminf(d2, d3));
        if (mn < bd[KNN-1]) {
            topk_insert(bd, bi, d0, 4*j4+0);
            topk_insert(bd, bi, d1, 4*j4+1);
            topk_insert(bd, bi, d2, 4*j4+2);
            topk_insert(bd, bi, d3, 4*j4+3);
        }
    }
    int gi = b * PP + il;
#pragma unroll
    for (int t = 0; t < KNN; t++) g_idx[gi*KNN + t] = b * PP + bi[t];
}

// ---------------- EdgeConv1: tf32 tensor cores, 3 chained GEMMs in SMEM ----------------
#define C1_LDD 68
#define C1_LDW 72
__global__ __launch_bounds__(256, 2) void conv1_kernel(
    const float* __restrict__ pos,
    const float* __restrict__ w0, const float* __restrict__ b0,
    const float* __restrict__ w1, const float* __restrict__ b1,
    const float* __restrict__ w2, const float* __restrict__ b2)
{
    extern __shared__ float sm[];
    float* sW0 = sm;
    float* sW1 = sm + 576;
    float* sW2 = sm + 5184;
    float* sb0 = sm + 9792;
    float* sb1 = sm + 9856;
    float* sb2 = sm + 9920;
    float* sD  = sm + 9984;     // 160*68

    int tid = threadIdx.x, lane = tid & 31, warp = tid >> 5;
    int g4 = lane >> 2, tig = lane & 3;
    int wm = warp >> 2, wn = warp & 3;
    int mB = wm * 80, nB = wn * 16;

    for (int fi = tid; fi < 512; fi += 256) {
        int kk = fi >> 6, o = fi & 63;
        sW0[kk*C1_LDW + o] = (kk < 6) ? tfbits(w0[kk*64 + o]) : 0.f;
    }
    for (int fi = tid; fi < 4096; fi += 256) {
        int kk = fi >> 6, o = fi & 63;
        sW1[kk*C1_LDW + o] = tfbits(w1[fi]);
        sW2[kk*C1_LDW + o] = tfbits(w2[fi]);
    }
    if (tid < 64) { sb0[tid] = b0[tid]; sb1[tid] = b1[tid]; sb2[tid] = b2[tid]; }

    float acc[5][2][4];
    for (int gi = 0; gi < 4; gi++) {
        int ibase = (blockIdx.x*4 + gi) * 8;
        __syncthreads();
        if (tid < 160) {
            int p = tid / 20, e = tid - p*20;
            int i = ibase + p;
            int j = g_idx[i*KNN + e];
            float xx = pos[i*3], xy = pos[i*3+1], xz = pos[i*3+2];
            float jx = pos[j*3], jy = pos[j*3+1], jz = pos[j*3+2];
            float* dr = sD + tid*C1_LDD;
            dr[0] = tfbits(xx); dr[1] = tfbits(xy); dr[2] = tfbits(xz);
            dr[3] = tfbits(jx-xx); dr[4] = tfbits(jy-xy); dr[5] = tfbits(jz-xz);
            dr[6] = 0.f; dr[7] = 0.f;
        }
        __syncthreads();
        mma_5x2(sD, sW0, acc, mB, nB, g4, tig, 1, C1_LDD, C1_LDW);
        __syncthreads();
        wb_5x2(sD, acc, sb0, mB, nB, g4, tig, C1_LDD, 0);
        __syncthreads();
        mma_5x2(sD, sW1, acc, mB, nB, g4, tig, 8, C1_LDD, C1_LDW);
        __syncthreads();
        wb_5x2(sD, acc, sb1, mB, nB, g4, tig, C1_LDD, 1);
        __syncthreads();
        mma_5x2(sD, sW2, acc, mB, nB, g4, tig, 8, C1_LDD, C1_LDW);
        __syncthreads();
        wb_5x2(sD, acc, sb2, mB, nB, g4, tig, C1_LDD, 2);
        __syncthreads();
        {
            int p = tid >> 5, cq = tid & 31;
            float2 m = make_float2(-3.4e38f, -3.4e38f);
#pragma unroll 4
            for (int e = 0; e < KNN; e++) {
                float2 v = *(float2*)&sD[(p*20+e)*C1_LDD + cq*2];
                m.x = fmaxf(m.x, v.x); m.y = fmaxf(m.y, v.y);
            }
            float2 bbv = *(float2*)&sb2[cq*2];
            m.x = fmaxf(m.x + bbv.x, 0.f);
            m.y = fmaxf(m.y + bbv.y, 0.f);
            ((float2*)g_x1)[(size_t)(ibase+p)*32 + cq] = m;
        }
    }
}

// ---------------- KNN over 64-D features: tf32 MMA dot matrix + fast top-k scan ----------------
#define KF_LDA 68
#define KF_LDT 132
__global__ __launch_bounds__(256) void knn_feat_kernel()
{
    extern __shared__ float sm[];
    float* sA   = sm;
    float* sB   = sm + 128*KF_LDA;
    float* sdot = sm + 2*128*KF_LDA;
    float* sqi  = sdot + 128*KF_LDT;
    float* sqj  = sqi + 128;

    int tid = threadIdx.x, lane = tid & 31, warp = tid >> 5;
    int g4 = lane >> 2, tig = lane & 3;
    int wm = warp >> 2, wn = warp & 3;
    int b = blockIdx.y;
    int i0 = b*PP + blockIdx.x*128;
    const float4* x1v = (const float4*)g_x1;

    for (int fi = tid; fi < 128*16; fi += 256) {
        int pt = fi >> 4, q = fi & 15;
        float4 v = x1v[(size_t)(i0+pt)*16 + q];
        *(float4*)&sA[pt*KF_LDA + q*4] =
            make_float4(tfbits(v.x), tfbits(v.y), tfbits(v.z), tfbits(v.w));
    }
    if (tid < 128) {
        float s = 0.f;
#pragma unroll
        for (int q = 0; q < 16; q++) {
            float4 v = x1v[(size_t)(i0+tid)*16 + q];
            s += v.x*v.x + v.y*v.y + v.z*v.z + v.w*v.w;
        }
        sqi[tid] = s;
    }

    float bd[KNN]; int bi[KNN];
#pragma unroll
    for (int t = 0; t < KNN; t++) { bd[t] = 3.4e38f; bi[t] = 0; }
    float mysq = 0.f;

    for (int jt = 0; jt < 8; jt++) {
        int j0 = b*PP + jt*128;
        __syncthreads();
        for (int fi = tid; fi < 128*16; fi += 256) {
            int pt = fi >> 4, q = fi & 15;
            float4 v = x1v[(size_t)(j0+pt)*16 + q];
            *(float4*)&sB[pt*KF_LDA + q*4] =
                make_float4(tfbits(v.x), tfbits(v.y), tfbits(v.z), tfbits(v.w));
        }
        if (tid < 128) {
            float s = 0.f;
#pragma unroll
            for (int q = 0; q < 16; q++) {
                float4 v = x1v[(size_t)(j0+tid)*16 + q];
                s += v.x*v.x + v.y*v.y + v.z*v.z + v.w*v.w;
            }
            sqj[tid] = s;
        }
        __syncthreads();
        float acc[4][4][4];
#pragma unroll
        for (int mi = 0; mi < 4; mi++)
#pragma unroll
            for (int ni = 0; ni < 4; ni++)
#pragma unroll
                for (int c = 0; c < 4; c++) acc[mi][ni][c] = 0.f;
#pragma unroll
        for (int ks = 0; ks < 8; ks++) {
            int k0 = ks*8;
            uint32_t A[4][4];
#pragma unroll
            for (int mi = 0; mi < 4; mi++) {
                int row = wm*64 + mi*16 + g4;
                A[mi][0] = __float_as_uint(sA[row*KF_LDA + k0 + tig]);
                A[mi][1] = __float_as_uint(sA[(row+8)*KF_LDA + k0 + tig]);
                A[mi][2] = __float_as_uint(sA[row*KF_LDA + k0 + tig + 4]);
                A[mi][3] = __float_as_uint(sA[(row+8)*KF_LDA + k0 + tig + 4]);
            }
            uint32_t Bf[4][2];
#pragma unroll
            for (int ni = 0; ni < 4; ni++) {
                int col = wn*32 + ni*8 + g4;
                Bf[ni][0] = __float_as_uint(sB[col*KF_LDA + k0 + tig]);
                Bf[ni][1] = __float_as_uint(sB[col*KF_LDA + k0 + tig + 4]);
            }
#pragma unroll
            for (int mi = 0; mi < 4; mi++)
#pragma unroll
                for (int ni = 0; ni < 4; ni++)
                    mma8(acc[mi][ni][0], acc[mi][ni][1], acc[mi][ni][2], acc[mi][ni][3],
                         A[mi][0], A[mi][1], A[mi][2], A[mi][3], Bf[ni][0], Bf[ni][1]);
        }
#pragma unroll
        for (int mi = 0; mi < 4; mi++) {
#pragma unroll
            for (int ni = 0; ni < 4; ni++) {
                int row = wm*64 + mi*16 + g4, col = wn*32 + ni*8 + tig*2;
                *(float2*)&sdot[row*KF_LDT + col]     = make_float2(acc[mi][ni][0], acc[mi][ni][1]);
                *(float2*)&sdot[(row+8)*KF_LDT + col] = make_float2(acc[mi][ni][2], acc[mi][ni][3]);
            }
        }
        __syncthreads();
        // fast selection: float4 + min early-out
        if (tid < 128) {
            if (jt == 0) mysq = sqi[tid];
            const float4* drow4 = (const float4*)(sdot + tid*KF_LDT);
            const float4* sqj4  = (const float4*)sqj;
            int jbase = jt*128;
            for (int j4 = 0; j4 < 32; j4++) {
                float4 dv = drow4[j4];
                float4 sv = sqj4[j4];
                float d0 = mysq + sv.x - 2.0f*dv.x;
                float d1 = mysq + sv.y - 2.0f*dv.y;
                float d2 = mysq + sv.z - 2.0f*dv.z;
                float d3 = mysq + sv.w - 2.0f*dv.w;
                float mn = fminf(fminf(d0, d1), fminf(d2, d3));
                if (mn < bd[KNN-1]) {
                    topk_insert(bd, bi, d0, jbase + 4*j4 + 0);
                    topk_insert(bd, bi, d1, jbase + 4*j4 + 1);
                    topk_insert(bd, bi, d2, jbase + 4*j4 + 2);
                    topk_insert(bd, bi, d3, jbase + 4*j4 + 3);
                }
            }
        }
    }
    if (tid < 128) {
        int gi = i0 + tid;
#pragma unroll
        for (int t = 0; t < KNN; t++) g_idx[(size_t)gi*KNN + t] = b*PP + bi[t];
    }
}

// ---------------- EdgeConv2 v4: cooperative base + diff GEMM (tf32, K=64) ----------------
#define C2_LDD 68
#define C2_LDW 136
#define C2_LDB 132
__global__ __launch_bounds__(256, 2) void conv2_kernel(
    const float* __restrict__ w, const float* __restrict__ bias)
{
    extern __shared__ float sm[];
    float* sWb   = sm;                        // 64*136 (W rows 64..127, tf32)
    float* sD    = sm + 64*C2_LDW;            // 160*68 diff tf32
    float* sXi   = sD + 160*C2_LDD;           // 8*68 exact fp32
    float* sBase = sXi + 8*68;                // 8*132
    float* sbias = sBase + 8*C2_LDB;          // 128

    int tid = threadIdx.x, lane = tid & 31, warp = tid >> 5;
    int g4 = lane >> 2, tig = lane & 3;
    int wm = warp >> 2, wn = warp & 3;
    int mB = wm*80, nB = wn*32;

    for (int fi = tid; fi < 2048; fi += 256) {
        int kk = fi >> 5, nq = fi & 31;
        float4 v = ((const float4*)w)[(64+kk)*32 + nq];
        *(float4*)&sWb[kk*C2_LDW + nq*4] =
            make_float4(tfbits(v.x), tfbits(v.y), tfbits(v.z), tfbits(v.w));
    }
    if (tid < 128) sbias[tid] = bias[tid];

    const float4* x1v = (const float4*)g_x1;

    for (int gi = 0; gi < 4; gi++) {
        int ibase = (blockIdx.x*4 + gi) * 8;
        __syncthreads();
        if (tid < 128) {
            int p = tid >> 4, q = tid & 15;
            *(float4*)&sXi[p*68 + q*4] = x1v[(size_t)(ibase+p)*16 + q];
        }
        __syncthreads();
        // build diff rows (tid<160) — only the xj-xi half
        if (tid < 160) {
            int p = tid/20, e = tid - p*20;
            int j = g_idx[(size_t)(ibase+p)*KNN + e];
            float* drow = sD + tid*C2_LDD;
            const float* xir = &sXi[p*68];
#pragma unroll 4
            for (int q = 0; q < 16; q++) {
                float4 xj = x1v[(size_t)j*16 + q];
                float4 xi = *(const float4*)&xir[q*4];
                *(float4*)&drow[q*4] =
                    make_float4(tfbits(xj.x-xi.x), tfbits(xj.y-xi.y),
                                tfbits(xj.z-xi.z), tfbits(xj.w-xi.w));
            }
        }
        // base: warp covers 16 cols for ALL 8 points (no redundant W loads)
        {
            int p = lane >> 2, c4 = lane & 3;       // point, col-quad within warp's 16 cols
            int colq = warp*4 + c4;                  // float4 index into 128-wide row
            const float* xir = &sXi[p*68];
            float4 acc4 = ((const float4*)sbias)[colq];
#pragma unroll 8
            for (int k = 0; k < 64; k++) {
                float xv = xir[k];
                float4 wv = ((const float4*)w)[k*32 + colq];
                acc4.x = fmaf(xv, wv.x, acc4.x); acc4.y = fmaf(xv, wv.y, acc4.y);
                acc4.z = fmaf(xv, wv.z, acc4.z); acc4.w = fmaf(xv, wv.w, acc4.w);
            }
            *(float4*)&sBase[p*C2_LDB + colq*4] = acc4;
        }
        __syncthreads();
        // diff GEMM: [160][64] x [64][128]; warp tile M=80, N=32, 8 k-steps
        float acc[5][4][4];
#pragma unroll
        for (int mi = 0; mi < 5; mi++)
#pragma unroll
            for (int ni = 0; ni < 4; ni++)
#pragma unroll
                for (int c = 0; c < 4; c++) acc[mi][ni][c] = 0.f;
#pragma unroll 1
        for (int ks = 0; ks < 8; ks++) {
            int k0 = ks*8;
            uint32_t A[5][4];
#pragma unroll
            for (int mi = 0; mi < 5; mi++) {
                int row = mB + mi*16 + g4;
                A[mi][0] = __float_as_uint(sD[row*C2_LDD + k0 + tig]);
                A[mi][1] = __float_as_uint(sD[(row+8)*C2_LDD + k0 + tig]);
                A[mi][2] = __float_as_uint(sD[row*C2_LDD + k0 + tig + 4]);
                A[mi][3] = __float_as_uint(sD[(row+8)*C2_LDD + k0 + tig + 4]);
            }
            uint32_t Bf[4][2];
#pragma unroll
            for (int ni = 0; ni < 4; ni++) {
                int col = nB + ni*8 + g4;
                Bf[ni][0] = __float_as_uint(sWb[(k0+tig)*C2_LDW + col]);
                Bf[ni][1] = __float_as_uint(sWb[(k0+tig+4)*C2_LDW + col]);
            }
#pragma unroll
            for (int mi = 0; mi < 5; mi++)
#pragma unroll
                for (int ni = 0; ni < 4; ni++)
                    mma8(acc[mi][ni][0], acc[mi][ni][1], acc[mi][ni][2], acc[mi][ni][3],
                         A[mi][0], A[mi][1], A[mi][2], A[mi][3], Bf[ni][0], Bf[ni][1]);
        }
        // register epilogue: per-point max over edges
        float pm[4][4][2];
#pragma unroll
        for (int p = 0; p < 4; p++)
#pragma unroll
            for (int ni = 0; ni < 4; ni++) { pm[p][ni][0] = -3.4e38f; pm[p][ni][1] = -3.4e38f; }
        bool hi1 = (g4 >= 4);
        bool hi3 = (g4 >= 4);
#pragma unroll
        for (int ni = 0; ni < 4; ni++) {
            pm[0][ni][0] = fmaxf(pm[0][ni][0], acc[0][ni][0]);
            pm[0][ni][1] = fmaxf(pm[0][ni][1], acc[0][ni][1]);
            if (!hi1) { pm[0][ni][0] = fmaxf(pm[0][ni][0], acc[1][ni][0]);
                        pm[0][ni][1] = fmaxf(pm[0][ni][1], acc[1][ni][1]); }
            else      { pm[1][ni][0] = fmaxf(pm[1][ni][0], acc[1][ni][0]);
                        pm[1][ni][1] = fmaxf(pm[1][ni][1], acc[1][ni][1]); }
            pm[1][ni][0] = fmaxf(pm[1][ni][0], acc[2][ni][0]);
            pm[1][ni][1] = fmaxf(pm[1][ni][1], acc[2][ni][1]);
            pm[2][ni][0] = fmaxf(pm[2][ni][0], acc[3][ni][0]);
            pm[2][ni][1] = fmaxf(pm[2][ni][1], acc[3][ni][1]);
            pm[3][ni][0] = fmaxf(pm[3][ni][0], acc[4][ni][0]);
            pm[3][ni][1] = fmaxf(pm[3][ni][1], acc[4][ni][1]);
            pm[0][ni][0] = fmaxf(pm[0][ni][0], acc[0][ni][2]);
            pm[0][ni][1] = fmaxf(pm[0][ni][1], acc[0][ni][3]);
            pm[1][ni][0] = fmaxf(pm[1][ni][0], acc[1][ni][2]);
            pm[1][ni][1] = fmaxf(pm[1][ni][1], acc[1][ni][3]);
            pm[2][ni][0] = fmaxf(pm[2][ni][0], acc[2][ni][2]);
            pm[2][ni][1] = fmaxf(pm[2][ni][1], acc[2][ni][3]);
            if (!hi3) { pm[2][ni][0] = fmaxf(pm[2][ni][0], acc[3][ni][2]);
                        pm[2][ni][1] = fmaxf(pm[2][ni][1], acc[3][ni][3]); }
            else      { pm[3][ni][0] = fmaxf(pm[3][ni][0], acc[3][ni][2]);
                        pm[3][ni][1] = fmaxf(pm[3][ni][1], acc[3][ni][3]); }
            pm[3][ni][0] = fmaxf(pm[3][ni][0], acc[4][ni][2]);
            pm[3][ni][1] = fmaxf(pm[3][ni][1], acc[4][ni][3]);
        }
#pragma unroll
        for (int off = 4; off < 32; off <<= 1)
#pragma unroll
            for (int p = 0; p < 4; p++)
#pragma unroll
                for (int ni = 0; ni < 4; ni++) {
                    pm[p][ni][0] = fmaxf(pm[p][ni][0], __shfl_xor_sync(0xffffffff, pm[p][ni][0], off));
                    pm[p][ni][1] = fmaxf(pm[p][ni][1], __shfl_xor_sync(0xffffffff, pm[p][ni][1], off));
                }
        if (g4 == 0) {
#pragma unroll
            for (int p = 0; p < 4; p++) {
                int wp = wm*4 + p;
#pragma unroll
                for (int ni = 0; ni < 4; ni++) {
                    int col = nB + ni*8 + tig*2;
                    float b0v = sBase[wp*C2_LDB + col];
                    float b1v = sBase[wp*C2_LDB + col + 1];
                    float2 o;
                    o.x = fmaxf(pm[p][ni][0] + b0v, 0.f);
                    o.y = fmaxf(pm[p][ni][1] + b1v, 0.f);
                    *(float2*)&g_x2[(size_t)(ibase+wp)*128 + col] = o;
                }
            }
        }
    }
}

// ---------------- l1 (192->1024) tf32 GEMM + fused relu + P-max ----------------
__global__ __launch_bounds__(256) void l1max_kernel(
    const float* __restrict__ w, const float* __restrict__ bias)
{
    __shared__ float sA[128*20];
    __shared__ float sB[16*136];
    __shared__ float sbias[128];
    __shared__ unsigned int sred[128];
    int tid = threadIdx.x;
    int lane = tid & 31, warp = tid >> 5;
    int g4 = lane >> 2, tig = lane & 3;
    int b = blockIdx.z;
    int n0 = blockIdx.x * 128, m0 = blockIdx.y * 128;
    int pbase = b * PP + m0;
    const float4* x1v = (const float4*)g_x1;
    const float4* x2v = (const float4*)g_x2;
    const float4* wv  = (const float4*)w;
    if (tid < 128) { sred[tid] = 0u; sbias[tid] = bias[n0 + tid]; }

    int wm = warp >> 2, wn = warp & 3;
    float acc[4][4][4];
#pragma unroll
    for (int mi = 0; mi < 4; mi++)
#pragma unroll
        for (int ni = 0; ni < 4; ni++)
#pragma unroll
            for (int c = 0; c < 4; c++) acc[mi][ni][c] = 0.f;

    for (int ks = 0; ks < 12; ks++) {
        __syncthreads();
#pragma unroll
        for (int r = 0; r < 2; r++) {
            int fi = tid*2 + r;
            int pt = fi >> 2, kq = fi & 3;
            float4 v = (ks < 4) ? x1v[(size_t)(pbase+pt)*16 + ks*4 + kq]
                                : x2v[(size_t)(pbase+pt)*32 + (ks-4)*4 + kq];
            *(float4*)&sA[pt*20 + kq*4] =
                make_float4(tfbits(v.x), tfbits(v.y), tfbits(v.z), tfbits(v.w));
        }
#pragma unroll
        for (int r = 0; r < 2; r++) {
            int fi = tid*2 + r;
            int kk = fi >> 5, nq = fi & 31;
            float4 v = wv[(size_t)(ks*16+kk)*256 + (n0>>2) + nq];
            *(float4*)&sB[kk*136 + nq*4] =
                make_float4(tfbits(v.x), tfbits(v.y), tfbits(v.z), tfbits(v.w));
        }
        __syncthreads();
#pragma unroll
        for (int kh = 0; kh < 2; kh++) {
            int k0 = kh*8;
            uint32_t A[4][4];
#pragma unroll
            for (int mi = 0; mi < 4; mi++) {
                int row = wm*64 + mi*16 + g4;
                A[mi][0] = __float_as_uint(sA[row*20 + k0 + tig]);
                A[mi][1] = __float_as_uint(sA[(row+8)*20 + k0 + tig]);
                A[mi][2] = __float_as_uint(sA[row*20 + k0 + tig + 4]);
                A[mi][3] = __float_as_uint(sA[(row+8)*20 + k0 + tig + 4]);
            }
            uint32_t Bf[4][2];
#pragma unroll
            for (int ni = 0; ni < 4; ni++) {
                int col = wn*32 + ni*8 + g4;
                Bf[ni][0] = __float_as_uint(sB[(k0+tig)*136 + col]);
                Bf[ni][1] = __float_as_uint(sB[(k0+tig+4)*136 + col]);
            }
#pragma unroll
            for (int mi = 0; mi < 4; mi++)
#pragma unroll
                for (int ni = 0; ni < 4; ni++)
                    mma8(acc[mi][ni][0], acc[mi][ni][1], acc[mi][ni][2], acc[mi][ni][3],
                         A[mi][0], A[mi][1], A[mi][2], A[mi][3], Bf[ni][0], Bf[ni][1]);
        }
    }
#pragma unroll
    for (int ni = 0; ni < 4; ni++) {
        float v0 = -3.4e38f, v1 = -3.4e38f;
#pragma unroll
        for (int mi = 0; mi < 4; mi++) {
            v0 = fmaxf(v0, fmaxf(acc[mi][ni][0], acc[mi][ni][2]));
            v1 = fmaxf(v1, fmaxf(acc[mi][ni][1], acc[mi][ni][3]));
        }
#pragma unroll
        for (int off = 4; off < 32; off <<= 1) {
            v0 = fmaxf(v0, __shfl_xor_sync(0xffffffff, v0, off));
            v1 = fmaxf(v1, __shfl_xor_sync(0xffffffff, v1, off));
        }
        if (g4 == 0) {
            int col = wn*32 + ni*8 + tig*2;
            float a0 = fmaxf(v0 + sbias[col], 0.f);
            float a1 = fmaxf(v1 + sbias[col+1], 0.f);
            atomicMax(&sred[col],   __float_as_uint(a0));
            atomicMax(&sred[col+1], __float_as_uint(a1));
        }
    }
    __syncthreads();
    if (tid < 128) atomicMax(&g_pool[b*1024 + n0 + tid], sred[tid]);
}

// ---------------- head: 1024->512 relu ->256 relu ->40 + log_softmax ----------------
__global__ __launch_bounds__(256) void head_kernel(
    const float* __restrict__ w0, const float* __restrict__ b0,
    const float* __restrict__ w1, const float* __restrict__ b1,
    const float* __restrict__ w2, const float* __restrict__ b2,
    float* __restrict__ out)
{
    __shared__ float sp[1024], sh0[512], sh1[256], sl[40], red[2];
    int b = blockIdx.x, tid = threadIdx.x;
    for (int c = tid; c < 1024; c += 256) sp[c] = __uint_as_float(g_pool[b*1024 + c]);
    __syncthreads();
    {
        float a0 = b0[2*tid], a1 = b0[2*tid+1];
        const float2* w0v = (const float2*)w0;
        for (int c = 0; c < 1024; c++) {
            float f = sp[c];
            float2 wvv = w0v[c*256 + tid];
            a0 += f * wvv.x; a1 += f * wvv.y;
        }
        sh0[2*tid]   = fmaxf(a0, 0.f);
        sh0[2*tid+1] = fmaxf(a1, 0.f);
    }
    __syncthreads();
    {
        float a = b1[tid];
        for (int c = 0; c < 512; c++) a += sh0[c] * w1[c*256 + tid];
        sh1[tid] = fmaxf(a, 0.f);
    }
    __syncthreads();
    if (tid < 40) {
        float a = b2[tid];
        for (int c = 0; c < 256; c++) a += sh1[c] * w2[c*40 + tid];
        sl[tid] = a;
    }
    __syncthreads();
    if (tid == 0) {
        float mxv = -3.4e38f;
        for (int t = 0; t < 40; t++) mxv = fmaxf(mxv, sl[t]);
        float s = 0.f;
        for (int t = 0; t < 40; t++) s += expf(sl[t] - mxv);
        red[0] = mxv; red[1] = logf(s);
    }
    __syncthreads();
    if (tid < 40) out[b*40 + tid] = sl[tid] - red[0] - red[1];
}

// ---------------- launch ----------------
extern "C" void kernel_launch(void* const* d_in, const int* in_sizes, int n_in,
                              void* d_out, int out_size)
{
    const float* pos   = (const float*)d_in[0];
    const float* c1_w0 = (const float*)d_in[2];
    const float* c1_b0 = (const float*)d_in[3];
    const float* c1_w1 = (const float*)d_in[4];
    const float* c1_b1 = (const float*)d_in[5];
    const float* c1_w2 = (const float*)d_in[6];
    const float* c1_b2 = (const float*)d_in[7];
    const float* c2_w0 = (const float*)d_in[8];
    const float* c2_b0 = (const float*)d_in[9];
    const float* l1_w  = (const float*)d_in[10];
    const float* l1_b  = (const float*)d_in[11];
    const float* m_w0  = (const float*)d_in[12];
    const float* m_b0  = (const float*)d_in[13];
    const float* m_w1  = (const float*)d_in[14];
    const float* m_b1  = (const float*)d_in[15];
    const float* m_w2  = (const float*)d_in[16];
    const float* m_b2  = (const float*)d_in[17];
    float* out = (float*)d_out;

    const int smem_conv1 = (576 + 4608 + 4608 + 192 + 160*C1_LDD) * 4;           // 83456
    const int smem_knn2  = (2*128*KF_LDA + 128*KF_LDT + 256) * 4;                // 138240
    const int smem_conv2 = (64*C2_LDW + 160*C2_LDD + 8*68 + 8*C2_LDB + 128) * 4; // ~85 KB

    cudaFuncSetAttribute(conv1_kernel,    cudaFuncAttributeMaxDynamicSharedMemorySize, smem_conv1);
    cudaFuncSetAttribute(knn_feat_kernel, cudaFuncAttributeMaxDynamicSharedMemorySize, smem_knn2);
    cudaFuncSetAttribute(conv2_kernel,    cudaFuncAttributeMaxDynamicSharedMemorySize, smem_conv2);

    knn_pos_kernel<<<dim3(4, 32), 256>>>(pos);
    conv1_kernel<<<1024, 256, smem_conv1>>>(pos, c1_w0, c1_b0, c1_w1, c1_b1, c1_w2, c1_b2);
    knn_feat_kernel<<<dim3(8, 32), 256, smem_knn2>>>();
    conv2_kernel<<<1024, 256, smem_conv2>>>(c2_w0, c2_b0);
    l1max_kernel<<<dim3(8, 8, 32), 256>>>(l1_w, l1_b);
    head_kernel<<<32, 256>>>(m_w0, m_b0, m_w1, m_b1, m_w2, m_b2, out);
}

// round 8
// speedup vs baseline: 16.9746x; 1.0856x over previous
#include <cuda_runtime.h>
#include <math.h>
#include <stdint.h>

#define BB 32
#define PP 1024
#define KNN 20
#define NPTS (BB*PP)

// ---------------- scratch (device globals; no allocs allowed) ----------------
__device__ __align__(16) float g_x1[NPTS*64];
__device__ __align__(16) float g_x2[NPTS*128];
__device__ int g_idx[NPTS*KNN];
__device__ unsigned int g_pool[BB*1024];

// ---------------- tf32 mma helpers ----------------
__device__ __forceinline__ uint32_t f2tf(float x) {
    uint32_t r; asm("cvt.rna.tf32.f32 %0, %1;" : "=r"(r) : "f"(x)); return r;
}
__device__ __forceinline__ float tfbits(float x) {
    return __uint_as_float(f2tf(x));
}
__device__ __forceinline__ void mma8(float& c0, float& c1, float& c2, float& c3,
                                     uint32_t a0, uint32_t a1, uint32_t a2, uint32_t a3,
                                     uint32_t b0, uint32_t b1)
{
    asm volatile("mma.sync.aligned.m16n8k8.row.col.f32.tf32.tf32.f32 "
                 "{%0,%1,%2,%3},{%4,%5,%6,%7},{%8,%9},{%0,%1,%2,%3};"
                 : "+f"(c0), "+f"(c1), "+f"(c2), "+f"(c3)
                 : "r"(a0), "r"(a1), "r"(a2), "r"(a3), "r"(b0), "r"(b1));
}

// top-k insertion (strict <, keeps earliest index on ties — matches jax top_k)
__device__ __forceinline__ void topk_insert(float* bd, int* bi, float d, int j)
{
    if (d < bd[KNN-1]) {
        bd[KNN-1] = d; bi[KNN-1] = j;
#pragma unroll
        for (int t = KNN-1; t > 0; t--) {
            if (bd[t] < bd[t-1]) {
                float td = bd[t]; bd[t] = bd[t-1]; bd[t-1] = td;
                int ti = bi[t]; bi[t] = bi[t-1]; bi[t-1] = ti;
            }
        }
    }
}

// 5 m-tiles x 2 n-tiles warp GEMM (used by conv1)
__device__ __forceinline__ void mma_5x2(
    const float* sD, const float* sW, float acc[5][2][4],
    int mB, int nB, int g4, int tig, int ksteps, int ldd, int ldw)
{
#pragma unroll
    for (int mi = 0; mi < 5; mi++)
#pragma unroll
        for (int ni = 0; ni < 2; ni++)
#pragma unroll
            for (int c = 0; c < 4; c++) acc[mi][ni][c] = 0.f;
#pragma unroll 1
    for (int ks = 0; ks < ksteps; ks++) {
        int k0 = ks * 8;
        uint32_t A[5][4];
#pragma unroll
        for (int mi = 0; mi < 5; mi++) {
            int row = mB + mi*16 + g4;
            A[mi][0] = __float_as_uint(sD[row*ldd + k0 + tig]);
            A[mi][1] = __float_as_uint(sD[(row+8)*ldd + k0 + tig]);
            A[mi][2] = __float_as_uint(sD[row*ldd + k0 + tig + 4]);
            A[mi][3] = __float_as_uint(sD[(row+8)*ldd + k0 + tig + 4]);
        }
        uint32_t Bf[2][2];
#pragma unroll
        for (int ni = 0; ni < 2; ni++) {
            int col = nB + ni*8 + g4;
            Bf[ni][0] = __float_as_uint(sW[(k0+tig)*ldw + col]);
            Bf[ni][1] = __float_as_uint(sW[(k0+tig+4)*ldw + col]);
        }
#pragma unroll
        for (int mi = 0; mi < 5; mi++)
#pragma unroll
            for (int ni = 0; ni < 2; ni++)
                mma8(acc[mi][ni][0], acc[mi][ni][1], acc[mi][ni][2], acc[mi][ni][3],
                     A[mi][0], A[mi][1], A[mi][2], A[mi][3], Bf[ni][0], Bf[ni][1]);
    }
}

__device__ __forceinline__ void wb_5x2(
    float* sD, float acc[5][2][4], const float* bias,
    int mB, int nB, int g4, int tig, int ldd, int mode)
{
#pragma unroll
    for (int mi = 0; mi < 5; mi++) {
#pragma unroll
        for (int ni = 0; ni < 2; ni++) {
            int row = mB + mi*16 + g4, col = nB + ni*8 + tig*2;
            float v0 = acc[mi][ni][0], v1 = acc[mi][ni][1];
            float v2 = acc[mi][ni][2], v3 = acc[mi][ni][3];
            float ba = bias[col], bb = bias[col+1];
            v0 += ba; v1 += bb; v2 += ba; v3 += bb;
            if (mode == 1) {
                v0 = fmaxf(v0, 0.f); v1 = fmaxf(v1, 0.f);
                v2 = fmaxf(v2, 0.f); v3 = fmaxf(v3, 0.f);
            }
            v0 = tfbits(v0); v1 = tfbits(v1); v2 = tfbits(v2); v3 = tfbits(v3);
            sD[row*ldd + col] = v0;     sD[row*ldd + col + 1] = v1;
            sD[(row+8)*ldd + col] = v2; sD[(row+8)*ldd + col + 1] = v3;
        }
    }
}

// ---------------- KNN over 3-D positions (exact fp32) + pool zero ----------------
__global__ __launch_bounds__(256) void knn_pos_kernel(const float* __restrict__ pos)
{
    __shared__ float4 spos[PP];   // (x, y, z, |x|^2)
    int b = blockIdx.y;
    g_pool[(blockIdx.y*4 + blockIdx.x)*256 + threadIdx.x] = 0u;
    const float* p = pos + (size_t)b * PP * 3;
    for (int j = threadIdx.x; j < PP; j += 256) {
        float x = p[3*j], y = p[3*j+1], z = p[3*j+2];
        spos[j] = make_float4(x, y, z, x*x + y*y + z*z);
    }
    __syncthreads();
    int il = blockIdx.x * 256 + threadIdx.x;
    float4 me = spos[il];
    float xi = me.x, yi = me.y, zi = me.z, sqi = me.w;
    float bd[KNN]; int bi[KNN];
#pragma unroll
    for (int t = 0; t < KNN; t++) { bd[t] = 3.4e38f; bi[t] = 0; }
    for (int j4 = 0; j4 < PP/4; j4++) {
        float4 v0 = spos[4*j4+0], v1 = spos[4*j4+1], v2 = spos[4*j4+2], v3 = spos[4*j4+3];
        float d0 = sqi + v0.w - 2.0f*(xi*v0.x + yi*v0.y + zi*v0.z);
        float d1 = sqi + v1.w - 2.0f*(xi*v1.x + yi*v1.y + zi*v1.z);
        float d2 = sqi + v2.w - 2.0f*(xi*v2.x + yi*v2.y + zi*v2.z);
        float d3 = sqi + v3.w - 2.0f*(xi*v3.x + yi*v3.y + zi*v3.z);
        float mn = fminf(fminf(d0, d1), fminf(d2, d3));
        if (mn < bd[KNN-1]) {
            topk_insert(bd, bi, d0, 4*j4+0);
            topk_insert(bd, bi, d1, 4*j4+1);
            topk_insert(bd, bi, d2, 4*j4+2);
            topk_insert(bd, bi, d3, 4*j4+3);
        }
    }
    int gi = b * PP + il;
#pragma unroll
    for (int t = 0; t < KNN; t++) g_idx[gi*KNN + t] = b * PP + bi[t];
}

// ---------------- EdgeConv1: tf32 tensor cores, register max epilogue ----------------
#define C1_LDD 68
#define C1_LDW 72
__global__ __launch_bounds__(256, 2) void conv1_kernel(
    const float* __restrict__ pos,
    const float* __restrict__ w0, const float* __restrict__ b0,
    const float* __restrict__ w1, const float* __restrict__ b1,
    const float* __restrict__ w2, const float* __restrict__ b2)
{
    extern __shared__ float sm[];
    float* sW0 = sm;
    float* sW1 = sm + 576;
    float* sW2 = sm + 5184;
    float* sb0 = sm + 9792;
    float* sb1 = sm + 9856;
    float* sb2 = sm + 9920;
    float* sD  = sm + 9984;     // 160*68

    int tid = threadIdx.x, lane = tid & 31, warp = tid >> 5;
    int g4 = lane >> 2, tig = lane & 3;
    int wm = warp >> 2, wn = warp & 3;
    int mB = wm * 80, nB = wn * 16;

    for (int fi = tid; fi < 512; fi += 256) {
        int kk = fi >> 6, o = fi & 63;
        sW0[kk*C1_LDW + o] = (kk < 6) ? tfbits(w0[kk*64 + o]) : 0.f;
    }
    for (int fi = tid; fi < 4096; fi += 256) {
        int kk = fi >> 6, o = fi & 63;
        sW1[kk*C1_LDW + o] = tfbits(w1[fi]);
        sW2[kk*C1_LDW + o] = tfbits(w2[fi]);
    }
    if (tid < 64) { sb0[tid] = b0[tid]; sb1[tid] = b1[tid]; sb2[tid] = b2[tid]; }

    float acc[5][2][4];
    for (int gi = 0; gi < 4; gi++) {
        int ibase = (blockIdx.x*4 + gi) * 8;
        __syncthreads();
        if (tid < 160) {
            int p = tid / 20, e = tid - p*20;
            int i = ibase + p;
            int j = g_idx[i*KNN + e];
            float xx = pos[i*3], xy = pos[i*3+1], xz = pos[i*3+2];
            float jx = pos[j*3], jy = pos[j*3+1], jz = pos[j*3+2];
            float* dr = sD + tid*C1_LDD;
            dr[0] = tfbits(xx); dr[1] = tfbits(xy); dr[2] = tfbits(xz);
            dr[3] = tfbits(jx-xx); dr[4] = tfbits(jy-xy); dr[5] = tfbits(jz-xz);
            dr[6] = 0.f; dr[7] = 0.f;
        }
        __syncthreads();
        mma_5x2(sD, sW0, acc, mB, nB, g4, tig, 1, C1_LDD, C1_LDW);
        __syncthreads();
        wb_5x2(sD, acc, sb0, mB, nB, g4, tig, C1_LDD, 0);
        __syncthreads();
        mma_5x2(sD, sW1, acc, mB, nB, g4, tig, 8, C1_LDD, C1_LDW);
        __syncthreads();
        wb_5x2(sD, acc, sb1, mB, nB, g4, tig, C1_LDD, 1);
        __syncthreads();
        mma_5x2(sD, sW2, acc, mB, nB, g4, tig, 8, C1_LDD, C1_LDW);
        // register epilogue: per-point max over edges (rows mB..mB+79 = 4 points)
        {
            float pm[4][2][2];
#pragma unroll
            for (int p = 0; p < 4; p++)
#pragma unroll
                for (int ni = 0; ni < 2; ni++) { pm[p][ni][0] = -3.4e38f; pm[p][ni][1] = -3.4e38f; }
            bool hi = (g4 >= 4);
#pragma unroll
            for (int ni = 0; ni < 2; ni++) {
                pm[0][ni][0] = fmaxf(pm[0][ni][0], acc[0][ni][0]);
                pm[0][ni][1] = fmaxf(pm[0][ni][1], acc[0][ni][1]);
                if (!hi) { pm[0][ni][0] = fmaxf(pm[0][ni][0], acc[1][ni][0]);
                           pm[0][ni][1] = fmaxf(pm[0][ni][1], acc[1][ni][1]); }
                else     { pm[1][ni][0] = fmaxf(pm[1][ni][0], acc[1][ni][0]);
                           pm[1][ni][1] = fmaxf(pm[1][ni][1], acc[1][ni][1]); }
                pm[1][ni][0] = fmaxf(pm[1][ni][0], acc[2][ni][0]);
                pm[1][ni][1] = fmaxf(pm[1][ni][1], acc[2][ni][1]);
                pm[2][ni][0] = fmaxf(pm[2][ni][0], acc[3][ni][0]);
                pm[2][ni][1] = fmaxf(pm[2][ni][1], acc[3][ni][1]);
                pm[3][ni][0] = fmaxf(pm[3][ni][0], acc[4][ni][0]);
                pm[3][ni][1] = fmaxf(pm[3][ni][1], acc[4][ni][1]);
                pm[0][ni][0] = fmaxf(pm[0][ni][0], acc[0][ni][2]);
                pm[0][ni][1] = fmaxf(pm[0][ni][1], acc[0][ni][3]);
                pm[1][ni][0] = fmaxf(pm[1][ni][0], acc[1][ni][2]);
                pm[1][ni][1] = fmaxf(pm[1][ni][1], acc[1][ni][3]);
                pm[2][ni][0] = fmaxf(pm[2][ni][0], acc[2][ni][2]);
                pm[2][ni][1] = fmaxf(pm[2][ni][1], acc[2][ni][3]);
                if (!hi) { pm[2][ni][0] = fmaxf(pm[2][ni][0], acc[3][ni][2]);
                           pm[2][ni][1] = fmaxf(pm[2][ni][1], acc[3][ni][3]); }
                else     { pm[3][ni][0] = fmaxf(pm[3][ni][0], acc[3][ni][2]);
                           pm[3][ni][1] = fmaxf(pm[3][ni][1], acc[3][ni][3]); }
                pm[3][ni][0] = fmaxf(pm[3][ni][0], acc[4][ni][2]);
                pm[3][ni][1] = fmaxf(pm[3][ni][1], acc[4][ni][3]);
            }
#pragma unroll
            for (int off = 4; off < 32; off <<= 1)
#pragma unroll
                for (int p = 0; p < 4; p++)
#pragma unroll
                    for (int ni = 0; ni < 2; ni++) {
                        pm[p][ni][0] = fmaxf(pm[p][ni][0], __shfl_xor_sync(0xffffffff, pm[p][ni][0], off));
                        pm[p][ni][1] = fmaxf(pm[p][ni][1], __shfl_xor_sync(0xffffffff, pm[p][ni][1], off));
                    }
            if (g4 == 0) {
#pragma unroll
                for (int p = 0; p < 4; p++) {
                    int wp = wm*4 + p;
#pragma unroll
                    for (int ni = 0; ni < 2; ni++) {
                        int col = nB + ni*8 + tig*2;
                        float2 o;
                        o.x = fmaxf(pm[p][ni][0] + sb2[col],   0.f);
                        o.y = fmaxf(pm[p][ni][1] + sb2[col+1], 0.f);
                        *(float2*)&g_x1[(size_t)(ibase+wp)*64 + col] = o;
                    }
                }
            }
        }
    }
}

// ---------------- KNN over 64-D features v3: 64-wide j-tiles, 2 blocks/SM ----------------
#define KF_LDA 68
__global__ __launch_bounds__(256, 2) void knn_feat_kernel()
{
    extern __shared__ float sm[];
    float* sA   = sm;                        // 128*68  (Xi tf32)
    float* sB   = sA + 128*KF_LDA;           // 64*68   (Xj tf32)
    float* sdot = sB + 64*KF_LDA;            // 128*68
    float* sqi  = sdot + 128*KF_LDA;         // 128
    float* sqj  = sqi + 128;                 // 64

    int tid = threadIdx.x, lane = tid & 31, warp = tid >> 5;
    int g4 = lane >> 2, tig = lane & 3;
    int wm = warp >> 1, wn = warp & 1;       // 4 m-warps x 2 n-warps; tile 32x32
    int b = blockIdx.y;
    int i0 = b*PP + blockIdx.x*128;
    const float4* x1v = (const float4*)g_x1;

    for (int fi = tid; fi < 128*16; fi += 256) {
        int pt = fi >> 4, q = fi & 15;
        float4 v = x1v[(size_t)(i0+pt)*16 + q];
        *(float4*)&sA[pt*KF_LDA + q*4] =
            make_float4(tfbits(v.x), tfbits(v.y), tfbits(v.z), tfbits(v.w));
    }
    if (tid < 128) {
        float s = 0.f;
#pragma unroll
        for (int q = 0; q < 16; q++) {
            float4 v = x1v[(size_t)(i0+tid)*16 + q];
            s += v.x*v.x + v.y*v.y + v.z*v.z + v.w*v.w;
        }
        sqi[tid] = s;
    }

    float bd[KNN]; int bi[KNN];
#pragma unroll
    for (int t = 0; t < KNN; t++) { bd[t] = 3.4e38f; bi[t] = 0; }
    float mysq = 0.f;

    for (int jt = 0; jt < 16; jt++) {
        int j0 = b*PP + jt*64;
        __syncthreads();
#pragma unroll
        for (int r = 0; r < 4; r++) {
            int fi = tid + r*256;
            int pt = fi >> 4, q = fi & 15;
            float4 v = x1v[(size_t)(j0+pt)*16 + q];
            *(float4*)&sB[pt*KF_LDA + q*4] =
                make_float4(tfbits(v.x), tfbits(v.y), tfbits(v.z), tfbits(v.w));
        }
        if (tid < 64) {
            float s = 0.f;
#pragma unroll
            for (int q = 0; q < 16; q++) {
                float4 v = x1v[(size_t)(j0+tid)*16 + q];
                s += v.x*v.x + v.y*v.y + v.z*v.z + v.w*v.w;
            }
            sqj[tid] = s;
        }
        __syncthreads();
        // GEMM dot[128 i][64 j], K=64; warp tile 32x32
        float acc[2][4][4];
#pragma unroll
        for (int mi = 0; mi < 2; mi++)
#pragma unroll
            for (int ni = 0; ni < 4; ni++)
#pragma unroll
                for (int c = 0; c < 4; c++) acc[mi][ni][c] = 0.f;
#pragma unroll
        for (int ks = 0; ks < 8; ks++) {
            int k0 = ks*8;
            uint32_t A[2][4];
#pragma unroll
            for (int mi = 0; mi < 2; mi++) {
                int row = wm*32 + mi*16 + g4;
                A[mi][0] = __float_as_uint(sA[row*KF_LDA + k0 + tig]);
                A[mi][1] = __float_as_uint(sA[(row+8)*KF_LDA + k0 + tig]);
                A[mi][2] = __float_as_uint(sA[row*KF_LDA + k0 + tig + 4]);
                A[mi][3] = __float_as_uint(sA[(row+8)*KF_LDA + k0 + tig + 4]);
            }
            uint32_t Bf[4][2];
#pragma unroll
            for (int ni = 0; ni < 4; ni++) {
                int col = wn*32 + ni*8 + g4;
                Bf[ni][0] = __float_as_uint(sB[col*KF_LDA + k0 + tig]);
                Bf[ni][1] = __float_as_uint(sB[col*KF_LDA + k0 + tig + 4]);
            }
#pragma unroll
            for (int mi = 0; mi < 2; mi++)
#pragma unroll
                for (int ni = 0; ni < 4; ni++)
                    mma8(acc[mi][ni][0], acc[mi][ni][1], acc[mi][ni][2], acc[mi][ni][3],
                         A[mi][0], A[mi][1], A[mi][2], A[mi][3], Bf[ni][0], Bf[ni][1]);
        }
#pragma unroll
        for (int mi = 0; mi < 2; mi++) {
#pragma unroll
            for (int ni = 0; ni < 4; ni++) {
                int row = wm*32 + mi*16 + g4, col = wn*32 + ni*8 + tig*2;
                *(float2*)&sdot[row*KF_LDA + col]     = make_float2(acc[mi][ni][0], acc[mi][ni][1]);
                *(float2*)&sdot[(row+8)*KF_LDA + col] = make_float2(acc[mi][ni][2], acc[mi][ni][3]);
            }
        }
        __syncthreads();
        // fast selection: float4 + min early-out
        if (tid < 128) {
            if (jt == 0) mysq = sqi[tid];
            const float4* drow4 = (const float4*)(sdot + tid*KF_LDA);
            const float4* sqj4  = (const float4*)sqj;
            int jbase = jt*64;
#pragma unroll 4
            for (int j4 = 0; j4 < 16; j4++) {
                float4 dv = drow4[j4];
                float4 sv = sqj4[j4];
                float d0 = mysq + sv.x - 2.0f*dv.x;
                float d1 = mysq + sv.y - 2.0f*dv.y;
                float d2 = mysq + sv.z - 2.0f*dv.z;
                float d3 = mysq + sv.w - 2.0f*dv.w;
                float mn = fminf(fminf(d0, d1), fminf(d2, d3));
                if (mn < bd[KNN-1]) {
                    topk_insert(bd, bi, d0, jbase + 4*j4 + 0);
                    topk_insert(bd, bi, d1, jbase + 4*j4 + 1);
                    topk_insert(bd, bi, d2, jbase + 4*j4 + 2);
                    topk_insert(bd, bi, d3, jbase + 4*j4 + 3);
                }
            }
        }
    }
    if (tid < 128) {
        int gi = i0 + tid;
#pragma unroll
        for (int t = 0; t < KNN; t++) g_idx[(size_t)gi*KNN + t] = b*PP + bi[t];
    }
}

// ---------------- EdgeConv2 v5: flat parallel build + cooperative base + diff GEMM ----------------
#define C2_LDD 68
#define C2_LDW 136
#define C2_LDB 132
__global__ __launch_bounds__(256, 2) void conv2_kernel(
    const float* __restrict__ w, const float* __restrict__ bias)
{
    extern __shared__ float sm[];
    float* sWb   = sm;                        // 64*136 (W rows 64..127, tf32)
    float* sD    = sm + 64*C2_LDW;            // 160*68 diff tf32
    float* sXi   = sD + 160*C2_LDD;           // 8*68 exact fp32
    float* sBase = sXi + 8*68;                // 8*132
    float* sbias = sBase + 8*C2_LDB;          // 128
    int*   sJ    = (int*)(sbias + 128);       // 160
    int*   sP    = sJ + 160;                  // 160

    int tid = threadIdx.x, lane = tid & 31, warp = tid >> 5;
    int g4 = lane >> 2, tig = lane & 3;
    int wm = warp >> 2, wn = warp & 3;
    int mB = wm*80, nB = wn*32;

    for (int fi = tid; fi < 2048; fi += 256) {
        int kk = fi >> 5, nq = fi & 31;
        float4 v = ((const float4*)w)[(64+kk)*32 + nq];
        *(float4*)&sWb[kk*C2_LDW + nq*4] =
            make_float4(tfbits(v.x), tfbits(v.y), tfbits(v.z), tfbits(v.w));
    }
    if (tid < 128) sbias[tid] = bias[tid];

    const float4* x1v = (const float4*)g_x1;

    for (int gi = 0; gi < 4; gi++) {
        int ibase = (blockIdx.x*4 + gi) * 8;
        __syncthreads();
        if (tid < 128) {
            int p = tid >> 4, q = tid & 15;
            *(float4*)&sXi[p*68 + q*4] = x1v[(size_t)(ibase+p)*16 + q];
        }
        if (tid < 160) {
            int p = tid / 20;
            sJ[tid] = g_idx[(size_t)(ibase+p)*KNN + (tid - p*20)];
            sP[tid] = p;
        }
        __syncthreads();
        // flat parallel diff build: 2560 float4 over 256 threads
#pragma unroll
        for (int it = 0; it < 10; it++) {
            int fi = tid + it*256;
            int row = fi >> 4, q = fi & 15;
            int j = sJ[row], p = sP[row];
            float4 xj = x1v[(size_t)j*16 + q];
            float4 xi = *(const float4*)&sXi[p*68 + q*4];
            *(float4*)&sD[row*C2_LDD + q*4] =
                make_float4(tfbits(xj.x-xi.x), tfbits(xj.y-xi.y),
                            tfbits(xj.z-xi.z), tfbits(xj.w-xi.w));
        }
        // base: warp covers 16 cols for ALL 8 points
        {
            int p = lane >> 2, c4 = lane & 3;
            int colq = warp*4 + c4;
            const float* xir = &sXi[p*68];
            float4 acc4 = ((const float4*)sbias)[colq];
#pragma unroll 8
            for (int k = 0; k < 64; k++) {
                float xv = xir[k];
                float4 wv = ((const float4*)w)[k*32 + colq];
                acc4.x = fmaf(xv, wv.x, acc4.x); acc4.y = fmaf(xv, wv.y, acc4.y);
                acc4.z = fmaf(xv, wv.z, acc4.z); acc4.w = fmaf(xv, wv.w, acc4.w);
            }
            *(float4*)&sBase[p*C2_LDB + colq*4] = acc4;
        }
        __syncthreads();
        // diff GEMM: [160][64] x [64][128]; warp tile M=80, N=32, 8 k-steps
        float acc[5][4][4];
#pragma unroll
        for (int mi = 0; mi < 5; mi++)
#pragma unroll
            for (int ni = 0; ni < 4; ni++)
#pragma unroll
                for (int c = 0; c < 4; c++) acc[mi][ni][c] = 0.f;
#pragma unroll 1
        for (int ks = 0; ks < 8; ks++) {
            int k0 = ks*8;
            uint32_t A[5][4];
#pragma unroll
            for (int mi = 0; mi < 5; mi++) {
                int row = mB + mi*16 + g4;
                A[mi][0] = __float_as_uint(sD[row*C2_LDD + k0 + tig]);
                A[mi][1] = __float_as_uint(sD[(row+8)*C2_LDD + k0 + tig]);
                A[mi][2] = __float_as_uint(sD[row*C2_LDD + k0 + tig + 4]);
                A[mi][3] = __float_as_uint(sD[(row+8)*C2_LDD + k0 + tig + 4]);
            }
            uint32_t Bf[4][2];
#pragma unroll
            for (int ni = 0; ni < 4; ni++) {
                int col = nB + ni*8 + g4;
                Bf[ni][0] = __float_as_uint(sWb[(k0+tig)*C2_LDW + col]);
                Bf[ni][1] = __float_as_uint(sWb[(k0+tig+4)*C2_LDW + col]);
            }
#pragma unroll
            for (int mi = 0; mi < 5; mi++)
#pragma unroll
                for (int ni = 0; ni < 4; ni++)
                    mma8(acc[mi][ni][0], acc[mi][ni][1], acc[mi][ni][2], acc[mi][ni][3],
                         A[mi][0], A[mi][1], A[mi][2], A[mi][3], Bf[ni][0], Bf[ni][1]);
        }
        // register epilogue: per-point max over edges
        float pm[4][4][2];
#pragma unroll
        for (int p = 0; p < 4; p++)
#pragma unroll
            for (int ni = 0; ni < 4; ni++) { pm[p][ni][0] = -3.4e38f; pm[p][ni][1] = -3.4e38f; }
        bool hi = (g4 >= 4);
#pragma unroll
        for (int ni = 0; ni < 4; ni++) {
            pm[0][ni][0] = fmaxf(pm[0][ni][0], acc[0][ni][0]);
            pm[0][ni][1] = fmaxf(pm[0][ni][1], acc[0][ni][1]);
            if (!hi) { pm[0][ni][0] = fmaxf(pm[0][ni][0], acc[1][ni][0]);
                       pm[0][ni][1] = fmaxf(pm[0][ni][1], acc[1][ni][1]); }
            else     { pm[1][ni][0] = fmaxf(pm[1][ni][0], acc[1][ni][0]);
                       pm[1][ni][1] = fmaxf(pm[1][ni][1], acc[1][ni][1]); }
            pm[1][ni][0] = fmaxf(pm[1][ni][0], acc[2][ni][0]);
            pm[1][ni][1] = fmaxf(pm[1][ni][1], acc[2][ni][1]);
            pm[2][ni][0] = fmaxf(pm[2][ni][0], acc[3][ni][0]);
            pm[2][ni][1] = fmaxf(pm[2][ni][1], acc[3][ni][1]);
            pm[3][ni][0] = fmaxf(pm[3][ni][0], acc[4][ni][0]);
            pm[3][ni][1] = fmaxf(pm[3][ni][1], acc[4][ni][1]);
            pm[0][ni][0] = fmaxf(pm[0][ni][0], acc[0][ni][2]);
            pm[0][ni][1] = fmaxf(pm[0][ni][1], acc[0][ni][3]);
            pm[1][ni][0] = fmaxf(pm[1][ni][0], acc[1][ni][2]);
            pm[1][ni][1] = fmaxf(pm[1][ni][1], acc[1][ni][3]);
            pm[2][ni][0] = fmaxf(pm[2][ni][0], acc[2][ni][2]);
            pm[2][ni][1] = fmaxf(pm[2][ni][1], acc[2][ni][3]);
            if (!hi) { pm[2][ni][0] = fmaxf(pm[2][ni][0], acc[3][ni][2]);
                       pm[2][ni][1] = fmaxf(pm[2][ni][1], acc[3][ni][3]); }
            else     { pm[3][ni][0] = fmaxf(pm[3][ni][0], acc[3][ni][2]);
                       pm[3][ni][1] = fmaxf(pm[3][ni][1], acc[3][ni][3]); }
            pm[3][ni][0] = fmaxf(pm[3][ni][0], acc[4][ni][2]);
            pm[3][ni][1] = fmaxf(pm[3][ni][1], acc[4][ni][3]);
        }
#pragma unroll
        for (int off = 4; off < 32; off <<= 1)
#pragma unroll
            for (int p = 0; p < 4; p++)
#pragma unroll
                for (int ni = 0; ni < 4; ni++) {
                    pm[p][ni][0] = fmaxf(pm[p][ni][0], __shfl_xor_sync(0xffffffff, pm[p][ni][0], off));
                    pm[p][ni][1] = fmaxf(pm[p][ni][1], __shfl_xor_sync(0xffffffff, pm[p][ni][1], off));
                }
        if (g4 == 0) {
#pragma unroll
            for (int p = 0; p < 4; p++) {
                int wp = wm*4 + p;
#pragma unroll
                for (int ni = 0; ni < 4; ni++) {
                    int col = nB + ni*8 + tig*2;
                    float b0v = sBase[wp*C2_LDB + col];
                    float b1v = sBase[wp*C2_LDB + col + 1];
                    float2 o;
                    o.x = fmaxf(pm[p][ni][0] + b0v, 0.f);
                    o.y = fmaxf(pm[p][ni][1] + b1v, 0.f);
                    *(float2*)&g_x2[(size_t)(ibase+wp)*128 + col] = o;
                }
            }
        }
    }
}

// ---------------- l1 (192->1024) tf32 GEMM + fused relu + P-max ----------------
__global__ __launch_bounds__(256) void l1max_kernel(
    const float* __restrict__ w, const float* __restrict__ bias)
{
    __shared__ float sA[128*20];
    __shared__ float sB[16*136];
    __shared__ float sbias[128];
    __shared__ unsigned int sred[128];
    int tid = threadIdx.x;
    int lane = tid & 31, warp = tid >> 5;
    int g4 = lane >> 2, tig = lane & 3;
    int b = blockIdx.z;
    int n0 = blockIdx.x * 128, m0 = blockIdx.y * 128;
    int pbase = b * PP + m0;
    const float4* x1v = (const float4*)g_x1;
    const float4* x2v = (const float4*)g_x2;
    const float4* wv  = (const float4*)w;
    if (tid < 128) { sred[tid] = 0u; sbias[tid] = bias[n0 + tid]; }

    int wm = warp >> 2, wn = warp & 3;
    float acc[4][4][4];
#pragma unroll
    for (int mi = 0; mi < 4; mi++)
#pragma unroll
        for (int ni = 0; ni < 4; ni++)
#pragma unroll
            for (int c = 0; c < 4; c++) acc[mi][ni][c] = 0.f;

    for (int ks = 0; ks < 12; ks++) {
        __syncthreads();
#pragma unroll
        for (int r = 0; r < 2; r++) {
            int fi = tid*2 + r;
            int pt = fi >> 2, kq = fi & 3;
            float4 v = (ks < 4) ? x1v[(size_t)(pbase+pt)*16 + ks*4 + kq]
                                : x2v[(size_t)(pbase+pt)*32 + (ks-4)*4 + kq];
            *(float4*)&sA[pt*20 + kq*4] =
                make_float4(tfbits(v.x), tfbits(v.y), tfbits(v.z), tfbits(v.w));
        }
#pragma unroll
        for (int r = 0; r < 2; r++) {
            int fi = tid*2 + r;
            int kk = fi >> 5, nq = fi & 31;
            float4 v = wv[(size_t)(ks*16+kk)*256 + (n0>>2) + nq];
            *(float4*)&sB[kk*136 + nq*4] =
                make_float4(tfbits(v.x), tfbits(v.y), tfbits(v.z), tfbits(v.w));
        }
        __syncthreads();
#pragma unroll
        for (int kh = 0; kh < 2; kh++) {
            int k0 = kh*8;
            uint32_t A[4][4];
#pragma unroll
            for (int mi = 0; mi < 4; mi++) {
                int row = wm*64 + mi*16 + g4;
                A[mi][0] = __float_as_uint(sA[row*20 + k0 + tig]);
                A[mi][1] = __float_as_uint(sA[(row+8)*20 + k0 + tig]);
                A[mi][2] = __float_as_uint(sA[row*20 + k0 + tig + 4]);
                A[mi][3] = __float_as_uint(sA[(row+8)*20 + k0 + tig + 4]);
            }
            uint32_t Bf[4][2];
#pragma unroll
            for (int ni = 0; ni < 4; ni++) {
                int col = wn*32 + ni*8 + g4;
                Bf[ni][0] = __float_as_uint(sB[(k0+tig)*136 + col]);
                Bf[ni][1] = __float_as_uint(sB[(k0+tig+4)*136 + col]);
            }
#pragma unroll
            for (int mi = 0; mi < 4; mi++)
#pragma unroll
                for (int ni = 0; ni < 4; ni++)
                    mma8(acc[mi][ni][0], acc[mi][ni][1], acc[mi][ni][2], acc[mi][ni][3],
                         A[mi][0], A[mi][1], A[mi][2], A[mi][3], Bf[ni][0], Bf[ni][1]);
        }
    }
#pragma unroll
    for (int ni = 0; ni < 4; ni++) {
        float v0 = -3.4e38f, v1 = -3.4e38f;
#pragma unroll
        for (int mi = 0; mi < 4; mi++) {
            v0 = fmaxf(v0, fmaxf(acc[mi][ni][0], acc[mi][ni][2]));
            v1 = fmaxf(v1, fmaxf(acc[mi][ni][1], acc[mi][ni][3]));
        }
#pragma unroll
        for (int off = 4; off < 32; off <<= 1) {
            v0 = fmaxf(v0, __shfl_xor_sync(0xffffffff, v0, off));
            v1 = fmaxf(v1, __shfl_xor_sync(0xffffffff, v1, off));
        }
        if (g4 == 0) {
            int col = wn*32 + ni*8 + tig*2;
            float a0 = fmaxf(v0 + sbias[col], 0.f);
            float a1 = fmaxf(v1 + sbias[col+1], 0.f);
            atomicMax(&sred[col],   __float_as_uint(a0));
            atomicMax(&sred[col+1], __float_as_uint(a1));
        }
    }
    __syncthreads();
    if (tid < 128) atomicMax(&g_pool[b*1024 + n0 + tid], sred[tid]);
}

// ---------------- head: 1024->512 relu ->256 relu ->40 + log_softmax ----------------
__global__ __launch_bounds__(256) void head_kernel(
    const float* __restrict__ w0, const float* __restrict__ b0,
    const float* __restrict__ w1, const float* __restrict__ b1,
    const float* __restrict__ w2, const float* __restrict__ b2,
    float* __restrict__ out)
{
    __shared__ float sp[1024], sh0[512], sh1[256], sl[40], red[2];
    int b = blockIdx.x, tid = threadIdx.x;
    for (int c = tid; c < 1024; c += 256) sp[c] = __uint_as_float(g_pool[b*1024 + c]);
    __syncthreads();
    {
        float a0 = b0[2*tid], a1 = b0[2*tid+1];
        const float2* w0v = (const float2*)w0;
        for (int c = 0; c < 1024; c++) {
            float f = sp[c];
            float2 wvv = w0v[c*256 + tid];
            a0 += f * wvv.x; a1 += f * wvv.y;
        }
        sh0[2*tid]   = fmaxf(a0, 0.f);
        sh0[2*tid+1] = fmaxf(a1, 0.f);
    }
    __syncthreads();
    {
        float a = b1[tid];
        for (int c = 0; c < 512; c++) a += sh0[c] * w1[c*256 + tid];
        sh1[tid] = fmaxf(a, 0.f);
    }
    __syncthreads();
    if (tid < 40) {
        float a = b2[tid];
        for (int c = 0; c < 256; c++) a += sh1[c] * w2[c*40 + tid];
        sl[tid] = a;
    }
    __syncthreads();
    if (tid == 0) {
        float mxv = -3.4e38f;
        for (int t = 0; t < 40; t++) mxv = fmaxf(mxv, sl[t]);
        float s = 0.f;
        for (int t = 0; t < 40; t++) s += expf(sl[t] - mxv);
        red[0] = mxv; red[1] = logf(s);
    }
    __syncthreads();
    if (tid < 40) out[b*40 + tid] = sl[tid] - red[0] - red[1];
}

// ---------------- launch ----------------
extern "C" void kernel_launch(void* const* d_in, const int* in_sizes, int n_in,
                              void* d_out, int out_size)
{
    const float* pos   = (const float*)d_in[0];
    const float* c1_w0 = (const float*)d_in[2];
    const float* c1_b0 = (const float*)d_in[3];
    const float* c1_w1 = (const float*)d_in[4];
    const float* c1_b1 = (const float*)d_in[5];
    const float* c1_w2 = (const float*)d_in[6];
    const float* c1_b2 = (const float*)d_in[7];
    const float* c2_w0 = (const float*)d_in[8];
    const float* c2_b0 = (const float*)d_in[9];
    const float* l1_w  = (const float*)d_in[10];
    const float* l1_b  = (const float*)d_in[11];
    const float* m_w0  = (const float*)d_in[12];
    const float* m_b0  = (const float*)d_in[13];
    const float* m_w1  = (const float*)d_in[14];
    const float* m_b1  = (const float*)d_in[15];
    const float* m_w2  = (const float*)d_in[16];
    const float* m_b2  = (const float*)d_in[17];
    float* out = (float*)d_out;

    const int smem_conv1 = (576 + 4608 + 4608 + 192 + 160*C1_LDD) * 4;                   // 83456
    const int smem_knn2  = (128*KF_LDA + 64*KF_LDA + 128*KF_LDA + 128 + 64) * 4;         // 87808
    const int smem_conv2 = (64*C2_LDW + 160*C2_LDD + 8*68 + 8*C2_LDB + 128 + 320) * 4;   // ~86.5 KB

    cudaFuncSetAttribute(conv1_kernel,    cudaFuncAttributeMaxDynamicSharedMemorySize, smem_conv1);
    cudaFuncSetAttribute(knn_feat_kernel, cudaFuncAttributeMaxDynamicSharedMemorySize, smem_knn2);
    cudaFuncSetAttribute(conv2_kernel,    cudaFuncAttributeMaxDynamicSharedMemorySize, smem_conv2);

    knn_pos_kernel<<<dim3(4, 32), 256>>>(pos);
    conv1_kernel<<<1024, 256, smem_conv1>>>(pos, c1_w0, c1_b0, c1_w1, c1_b1, c1_w2, c1_b2);
    knn_feat_kernel<<<dim3(8, 32), 256, smem_knn2>>>();
    conv2_kernel<<<1024, 256, smem_conv2>>>(c2_w0, c2_b0);
    l1max_kernel<<<dim3(8, 8, 32), 256>>>(l1_w, l1_b);
    head_kernel<<<32, 256>>>(m_w0, m_b0, m_w1, m_b1, m_w2, m_b2, out);
}

// round 9
// speedup vs baseline: 17.6926x; 1.0423x over previous
#include <cuda_runtime.h>
#include <math.h>
#include <stdint.h>

#define BB 32
#define PP 1024
#define KNN 20
#define NPTS (BB*PP)

// ---------------- scratch (device globals; no allocs allowed) ----------------
__device__ __align__(16) float g_x1[NPTS*64];
__device__ __align__(16) float g_x2[NPTS*128];
__device__ int g_idx[NPTS*KNN];
__device__ unsigned int g_pool[BB*1024];
__device__ __align__(16) float g_h0[BB*512];

// ---------------- tf32 mma helpers ----------------
__device__ __forceinline__ uint32_t f2tf(float x) {
    uint32_t r; asm("cvt.rna.tf32.f32 %0, %1;" : "=r"(r) : "f"(x)); return r;
}
__device__ __forceinline__ float tfbits(float x) {
    return __uint_as_float(f2tf(x));
}
__device__ __forceinline__ void mma8(float& c0, float& c1, float& c2, float& c3,
                                     uint32_t a0, uint32_t a1, uint32_t a2, uint32_t a3,
                                     uint32_t b0, uint32_t b1)
{
    asm volatile("mma.sync.aligned.m16n8k8.row.col.f32.tf32.tf32.f32 "
                 "{%0,%1,%2,%3},{%4,%5,%6,%7},{%8,%9},{%0,%1,%2,%3};"
                 : "+f"(c0), "+f"(c1), "+f"(c2), "+f"(c3)
                 : "r"(a0), "r"(a1), "r"(a2), "r"(a3), "r"(b0), "r"(b1));
}

// top-k insertion (strict <, keeps earliest index on ties — matches jax top_k)
__device__ __forceinline__ void topk_insert(float* bd, int* bi, float d, int j)
{
    if (d < bd[KNN-1]) {
        bd[KNN-1] = d; bi[KNN-1] = j;
#pragma unroll
        for (int t = KNN-1; t > 0; t--) {
            if (bd[t] < bd[t-1]) {
                float td = bd[t]; bd[t] = bd[t-1]; bd[t-1] = td;
                int ti = bi[t]; bi[t] = bi[t-1]; bi[t-1] = ti;
            }
        }
    }
}

// 5 m-tiles x 2 n-tiles warp GEMM (used by conv1)
__device__ __forceinline__ void mma_5x2(
    const float* sD, const float* sW, float acc[5][2][4],
    int mB, int nB, int g4, int tig, int ksteps, int ldd, int ldw)
{
#pragma unroll
    for (int mi = 0; mi < 5; mi++)
#pragma unroll
        for (int ni = 0; ni < 2; ni++)
#pragma unroll
            for (int c = 0; c < 4; c++) acc[mi][ni][c] = 0.f;
#pragma unroll 1
    for (int ks = 0; ks < ksteps; ks++) {
        int k0 = ks * 8;
        uint32_t A[5][4];
#pragma unroll
        for (int mi = 0; mi < 5; mi++) {
            int row = mB + mi*16 + g4;
            A[mi][0] = __float_as_uint(sD[row*ldd + k0 + tig]);
            A[mi][1] = __float_as_uint(sD[(row+8)*ldd + k0 + tig]);
            A[mi][2] = __float_as_uint(sD[row*ldd + k0 + tig + 4]);
            A[mi][3] = __float_as_uint(sD[(row+8)*ldd + k0 + tig + 4]);
        }
        uint32_t Bf[2][2];
#pragma unroll
        for (int ni = 0; ni < 2; ni++) {
            int col = nB + ni*8 + g4;
            Bf[ni][0] = __float_as_uint(sW[(k0+tig)*ldw + col]);
            Bf[ni][1] = __float_as_uint(sW[(k0+tig+4)*ldw + col]);
        }
#pragma unroll
        for (int mi = 0; mi < 5; mi++)
#pragma unroll
            for (int ni = 0; ni < 2; ni++)
                mma8(acc[mi][ni][0], acc[mi][ni][1], acc[mi][ni][2], acc[mi][ni][3],
                     A[mi][0], A[mi][1], A[mi][2], A[mi][3], Bf[ni][0], Bf[ni][1]);
    }
}

__device__ __forceinline__ void wb_5x2(
    float* sD, float acc[5][2][4], const float* bias,
    int mB, int nB, int g4, int tig, int ldd, int mode)
{
#pragma unroll
    for (int mi = 0; mi < 5; mi++) {
#pragma unroll
        for (int ni = 0; ni < 2; ni++) {
            int row = mB + mi*16 + g4, col = nB + ni*8 + tig*2;
            float v0 = acc[mi][ni][0], v1 = acc[mi][ni][1];
            float v2 = acc[mi][ni][2], v3 = acc[mi][ni][3];
            float ba = bias[col], bb = bias[col+1];
            v0 += ba; v1 += bb; v2 += ba; v3 += bb;
            if (mode == 1) {
                v0 = fmaxf(v0, 0.f); v1 = fmaxf(v1, 0.f);
                v2 = fmaxf(v2, 0.f); v3 = fmaxf(v3, 0.f);
            }
            v0 = tfbits(v0); v1 = tfbits(v1); v2 = tfbits(v2); v3 = tfbits(v3);
            sD[row*ldd + col] = v0;     sD[row*ldd + col + 1] = v1;
            sD[(row+8)*ldd + col] = v2; sD[(row+8)*ldd + col + 1] = v3;
        }
    }
}

// ---------------- KNN over 3-D positions (exact fp32) + pool zero ----------------
__global__ __launch_bounds__(256) void knn_pos_kernel(const float* __restrict__ pos)
{
    __shared__ float4 spos[PP];   // (x, y, z, |x|^2)
    int b = blockIdx.y;
    g_pool[(blockIdx.y*4 + blockIdx.x)*256 + threadIdx.x] = 0u;
    const float* p = pos + (size_t)b * PP * 3;
    for (int j = threadIdx.x; j < PP; j += 256) {
        float x = p[3*j], y = p[3*j+1], z = p[3*j+2];
        spos[j] = make_float4(x, y, z, x*x + y*y + z*z);
    }
    __syncthreads();
    int il = blockIdx.x * 256 + threadIdx.x;
    float4 me = spos[il];
    float xi = me.x, yi = me.y, zi = me.z, sqi = me.w;
    float bd[KNN]; int bi[KNN];
#pragma unroll
    for (int t = 0; t < KNN; t++) { bd[t] = 3.4e38f; bi[t] = 0; }
    for (int j4 = 0; j4 < PP/4; j4++) {
        float4 v0 = spos[4*j4+0], v1 = spos[4*j4+1], v2 = spos[4*j4+2], v3 = spos[4*j4+3];
        float d0 = sqi + v0.w - 2.0f*(xi*v0.x + yi*v0.y + zi*v0.z);
        float d1 = sqi + v1.w - 2.0f*(xi*v1.x + yi*v1.y + zi*v1.z);
        float d2 = sqi + v2.w - 2.0f*(xi*v2.x + yi*v2.y + zi*v2.z);
        float d3 = sqi + v3.w - 2.0f*(xi*v3.x + yi*v3.y + zi*v3.z);
        float mn = fminf(fminf(d0, d1), fminf(d2, d3));
        if (mn < bd[KNN-1]) {
            topk_insert(bd, bi, d0, 4*j4+0);
            topk_insert(bd, bi, d1, 4*j4+1);
            topk_insert(bd, bi, d2, 4*j4+2);
            topk_insert(bd, bi, d3, 4*j4+3);
        }
    }
    int gi = b * PP + il;
#pragma unroll
    for (int t = 0; t < KNN; t++) g_idx[gi*KNN + t] = b * PP + bi[t];
}

// ---------------- EdgeConv1: tf32 tensor cores, register max epilogue ----------------
#define C1_LDD 68
#define C1_LDW 72
__global__ __launch_bounds__(256, 2) void conv1_kernel(
    const float* __restrict__ pos,
    const float* __restrict__ w0, const float* __restrict__ b0,
    const float* __restrict__ w1, const float* __restrict__ b1,
    const float* __restrict__ w2, const float* __restrict__ b2)
{
    extern __shared__ float sm[];
    float* sW0 = sm;
    float* sW1 = sm + 576;
    float* sW2 = sm + 5184;
    float* sb0 = sm + 9792;
    float* sb1 = sm + 9856;
    float* sb2 = sm + 9920;
    float* sD  = sm + 9984;     // 160*68

    int tid = threadIdx.x, lane = tid & 31, warp = tid >> 5;
    int g4 = lane >> 2, tig = lane & 3;
    int wm = warp >> 2, wn = warp & 3;
    int mB = wm * 80, nB = wn * 16;

    for (int fi = tid; fi < 512; fi += 256) {
        int kk = fi >> 6, o = fi & 63;
        sW0[kk*C1_LDW + o] = (kk < 6) ? tfbits(w0[kk*64 + o]) : 0.f;
    }
    for (int fi = tid; fi < 4096; fi += 256) {
        int kk = fi >> 6, o = fi & 63;
        sW1[kk*C1_LDW + o] = tfbits(w1[fi]);
        sW2[kk*C1_LDW + o] = tfbits(w2[fi]);
    }
    if (tid < 64) { sb0[tid] = b0[tid]; sb1[tid] = b1[tid]; sb2[tid] = b2[tid]; }

    float acc[5][2][4];
    for (int gi = 0; gi < 4; gi++) {
        int ibase = (blockIdx.x*4 + gi) * 8;
        __syncthreads();
        if (tid < 160) {
            int p = tid / 20, e = tid - p*20;
            int i = ibase + p;
            int j = g_idx[i*KNN + e];
            float xx = pos[i*3], xy = pos[i*3+1], xz = pos[i*3+2];
            float jx = pos[j*3], jy = pos[j*3+1], jz = pos[j*3+2];
            float* dr = sD + tid*C1_LDD;
            dr[0] = tfbits(xx); dr[1] = tfbits(xy); dr[2] = tfbits(xz);
            dr[3] = tfbits(jx-xx); dr[4] = tfbits(jy-xy); dr[5] = tfbits(jz-xz);
            dr[6] = 0.f; dr[7] = 0.f;
        }
        __syncthreads();
        mma_5x2(sD, sW0, acc, mB, nB, g4, tig, 1, C1_LDD, C1_LDW);
        __syncthreads();
        wb_5x2(sD, acc, sb0, mB, nB, g4, tig, C1_LDD, 0);
        __syncthreads();
        mma_5x2(sD, sW1, acc, mB, nB, g4, tig, 8, C1_LDD, C1_LDW);
        __syncthreads();
        wb_5x2(sD, acc, sb1, mB, nB, g4, tig, C1_LDD, 1);
        __syncthreads();
        mma_5x2(sD, sW2, acc, mB, nB, g4, tig, 8, C1_LDD, C1_LDW);
        // register epilogue: per-point max over edges (rows mB..mB+79 = 4 points)
        {
            float pm[4][2][2];
#pragma unroll
            for (int p = 0; p < 4; p++)
#pragma unroll
                for (int ni = 0; ni < 2; ni++) { pm[p][ni][0] = -3.4e38f; pm[p][ni][1] = -3.4e38f; }
            bool hi = (g4 >= 4);
#pragma unroll
            for (int ni = 0; ni < 2; ni++) {
                pm[0][ni][0] = fmaxf(pm[0][ni][0], acc[0][ni][0]);
                pm[0][ni][1] = fmaxf(pm[0][ni][1], acc[0][ni][1]);
                if (!hi) { pm[0][ni][0] = fmaxf(pm[0][ni][0], acc[1][ni][0]);
                           pm[0][ni][1] = fmaxf(pm[0][ni][1], acc[1][ni][1]); }
                else     { pm[1][ni][0] = fmaxf(pm[1][ni][0], acc[1][ni][0]);
                           pm[1][ni][1] = fmaxf(pm[1][ni][1], acc[1][ni][1]); }
                pm[1][ni][0] = fmaxf(pm[1][ni][0], acc[2][ni][0]);
                pm[1][ni][1] = fmaxf(pm[1][ni][1], acc[2][ni][1]);
                pm[2][ni][0] = fmaxf(pm[2][ni][0], acc[3][ni][0]);
                pm[2][ni][1] = fmaxf(pm[2][ni][1], acc[3][ni][1]);
                pm[3][ni][0] = fmaxf(pm[3][ni][0], acc[4][ni][0]);
                pm[3][ni][1] = fmaxf(pm[3][ni][1], acc[4][ni][1]);
                pm[0][ni][0] = fmaxf(pm[0][ni][0], acc[0][ni][2]);
                pm[0][ni][1] = fmaxf(pm[0][ni][1], acc[0][ni][3]);
                pm[1][ni][0] = fmaxf(pm[1][ni][0], acc[1][ni][2]);
                pm[1][ni][1] = fmaxf(pm[1][ni][1], acc[1][ni][3]);
                pm[2][ni][0] = fmaxf(pm[2][ni][0], acc[2][ni][2]);
                pm[2][ni][1] = fmaxf(pm[2][ni][1], acc[2][ni][3]);
                if (!hi) { pm[2][ni][0] = fmaxf(pm[2][ni][0], acc[3][ni][2]);
                           pm[2][ni][1] = fmaxf(pm[2][ni][1], acc[3][ni][3]); }
                else     { pm[3][ni][0] = fmaxf(pm[3][ni][0], acc[3][ni][2]);
                           pm[3][ni][1] = fmaxf(pm[3][ni][1], acc[3][ni][3]); }
                pm[3][ni][0] = fmaxf(pm[3][ni][0], acc[4][ni][2]);
                pm[3][ni][1] = fmaxf(pm[3][ni][1], acc[4][ni][3]);
            }
#pragma unroll
            for (int off = 4; off < 32; off <<= 1)
#pragma unroll
                for (int p = 0; p < 4; p++)
#pragma unroll
                    for (int ni = 0; ni < 2; ni++) {
                        pm[p][ni][0] = fmaxf(pm[p][ni][0], __shfl_xor_sync(0xffffffff, pm[p][ni][0], off));
                        pm[p][ni][1] = fmaxf(pm[p][ni][1], __shfl_xor_sync(0xffffffff, pm[p][ni][1], off));
                    }
            if (g4 == 0) {
#pragma unroll
                for (int p = 0; p < 4; p++) {
                    int wp = wm*4 + p;
#pragma unroll
                    for (int ni = 0; ni < 2; ni++) {
                        int col = nB + ni*8 + tig*2;
                        float2 o;
                        o.x = fmaxf(pm[p][ni][0] + sb2[col],   0.f);
                        o.y = fmaxf(pm[p][ni][1] + sb2[col+1], 0.f);
                        *(float2*)&g_x1[(size_t)(ibase+wp)*64 + col] = o;
                    }
                }
            }
        }
    }
}

// ---------------- KNN over 64-D features v3: 64-wide j-tiles, 2 blocks/SM ----------------
#define KF_LDA 68
__global__ __launch_bounds__(256, 2) void knn_feat_kernel()
{
    extern __shared__ float sm[];
    float* sA   = sm;                        // 128*68  (Xi tf32)
    float* sB   = sA + 128*KF_LDA;           // 64*68   (Xj tf32)
    float* sdot = sB + 64*KF_LDA;            // 128*68
    float* sqi  = sdot + 128*KF_LDA;         // 128
    float* sqj  = sqi + 128;                 // 64

    int tid = threadIdx.x, lane = tid & 31, warp = tid >> 5;
    int g4 = lane >> 2, tig = lane & 3;
    int wm = warp >> 1, wn = warp & 1;       // 4 m-warps x 2 n-warps; tile 32x32
    int b = blockIdx.y;
    int i0 = b*PP + blockIdx.x*128;
    const float4* x1v = (const float4*)g_x1;

    for (int fi = tid; fi < 128*16; fi += 256) {
        int pt = fi >> 4, q = fi & 15;
        float4 v = x1v[(size_t)(i0+pt)*16 + q];
        *(float4*)&sA[pt*KF_LDA + q*4] =
            make_float4(tfbits(v.x), tfbits(v.y), tfbits(v.z), tfbits(v.w));
    }
    if (tid < 128) {
        float s = 0.f;
#pragma unroll
        for (int q = 0; q < 16; q++) {
            float4 v = x1v[(size_t)(i0+tid)*16 + q];
            s += v.x*v.x + v.y*v.y + v.z*v.z + v.w*v.w;
        }
        sqi[tid] = s;
    }

    float bd[KNN]; int bi[KNN];
#pragma unroll
    for (int t = 0; t < KNN; t++) { bd[t] = 3.4e38f; bi[t] = 0; }
    float mysq = 0.f;

    for (int jt = 0; jt < 16; jt++) {
        int j0 = b*PP + jt*64;
        __syncthreads();
#pragma unroll
        for (int r = 0; r < 4; r++) {
            int fi = tid + r*256;
            int pt = fi >> 4, q = fi & 15;
            float4 v = x1v[(size_t)(j0+pt)*16 + q];
            *(float4*)&sB[pt*KF_LDA + q*4] =
                make_float4(tfbits(v.x), tfbits(v.y), tfbits(v.z), tfbits(v.w));
        }
        if (tid < 64) {
            float s = 0.f;
#pragma unroll
            for (int q = 0; q < 16; q++) {
                float4 v = x1v[(size_t)(j0+tid)*16 + q];
                s += v.x*v.x + v.y*v.y + v.z*v.z + v.w*v.w;
            }
            sqj[tid] = s;
        }
        __syncthreads();
        // GEMM dot[128 i][64 j], K=64; warp tile 32x32
        float acc[2][4][4];
#pragma unroll
        for (int mi = 0; mi < 2; mi++)
#pragma unroll
            for (int ni = 0; ni < 4; ni++)
#pragma unroll
                for (int c = 0; c < 4; c++) acc[mi][ni][c] = 0.f;
#pragma unroll
        for (int ks = 0; ks < 8; ks++) {
            int k0 = ks*8;
            uint32_t A[2][4];
#pragma unroll
            for (int mi = 0; mi < 2; mi++) {
                int row = wm*32 + mi*16 + g4;
                A[mi][0] = __float_as_uint(sA[row*KF_LDA + k0 + tig]);
                A[mi][1] = __float_as_uint(sA[(row+8)*KF_LDA + k0 + tig]);
                A[mi][2] = __float_as_uint(sA[row*KF_LDA + k0 + tig + 4]);
                A[mi][3] = __float_as_uint(sA[(row+8)*KF_LDA + k0 + tig + 4]);
            }
            uint32_t Bf[4][2];
#pragma unroll
            for (int ni = 0; ni < 4; ni++) {
                int col = wn*32 + ni*8 + g4;
                Bf[ni][0] = __float_as_uint(sB[col*KF_LDA + k0 + tig]);
                Bf[ni][1] = __float_as_uint(sB[col*KF_LDA + k0 + tig + 4]);
            }
#pragma unroll
            for (int mi = 0; mi < 2; mi++)
#pragma unroll
                for (int ni = 0; ni < 4; ni++)
                    mma8(acc[mi][ni][0], acc[mi][ni][1], acc[mi][ni][2], acc[mi][ni][3],
                         A[mi][0], A[mi][1], A[mi][2], A[mi][3], Bf[ni][0], Bf[ni][1]);
        }
#pragma unroll
        for (int mi = 0; mi < 2; mi++) {
#pragma unroll
            for (int ni = 0; ni < 4; ni++) {
                int row = wm*32 + mi*16 + g4, col = wn*32 + ni*8 + tig*2;
                *(float2*)&sdot[row*KF_LDA + col]     = make_float2(acc[mi][ni][0], acc[mi][ni][1]);
                *(float2*)&sdot[(row+8)*KF_LDA + col] = make_float2(acc[mi][ni][2], acc[mi][ni][3]);
            }
        }
        __syncthreads();
        // fast selection: float4 + min early-out
        if (tid < 128) {
            if (jt == 0) mysq = sqi[tid];
            const float4* drow4 = (const float4*)(sdot + tid*KF_LDA);
            const float4* sqj4  = (const float4*)sqj;
            int jbase = jt*64;
#pragma unroll 4
            for (int j4 = 0; j4 < 16; j4++) {
                float4 dv = drow4[j4];
                float4 sv = sqj4[j4];
                float d0 = mysq + sv.x - 2.0f*dv.x;
                float d1 = mysq + sv.y - 2.0f*dv.y;
                float d2 = mysq + sv.z - 2.0f*dv.z;
                float d3 = mysq + sv.w - 2.0f*dv.w;
                float mn = fminf(fminf(d0, d1), fminf(d2, d3));
                if (mn < bd[KNN-1]) {
                    topk_insert(bd, bi, d0, jbase + 4*j4 + 0);
                    topk_insert(bd, bi, d1, jbase + 4*j4 + 1);
                    topk_insert(bd, bi, d2, jbase + 4*j4 + 2);
                    topk_insert(bd, bi, d3, jbase + 4*j4 + 3);
                }
            }
        }
    }
    if (tid < 128) {
        int gi = i0 + tid;
#pragma unroll
        for (int t = 0; t < KNN; t++) g_idx[(size_t)gi*KNN + t] = b*PP + bi[t];
    }
}

// ---------------- EdgeConv2 v5: flat parallel build + cooperative base + diff GEMM ----------------
#define C2_LDD 68
#define C2_LDW 136
#define C2_LDB 132
__global__ __launch_bounds__(256, 2) void conv2_kernel(
    const float* __restrict__ w, const float* __restrict__ bias)
{
    extern __shared__ float sm[];
    float* sWb   = sm;                        // 64*136 (W rows 64..127, tf32)
    float* sD    = sm + 64*C2_LDW;            // 160*68 diff tf32
    float* sXi   = sD + 160*C2_LDD;           // 8*68 exact fp32
    float* sBase = sXi + 8*68;                // 8*132
    float* sbias = sBase + 8*C2_LDB;          // 128
    int*   sJ    = (int*)(sbias + 128);       // 160
    int*   sP    = sJ + 160;                  // 160

    int tid = threadIdx.x, lane = tid & 31, warp = tid >> 5;
    int g4 = lane >> 2, tig = lane & 3;
    int wm = warp >> 2, wn = warp & 3;
    int mB = wm*80, nB = wn*32;

    for (int fi = tid; fi < 2048; fi += 256) {
        int kk = fi >> 5, nq = fi & 31;
        float4 v = ((const float4*)w)[(64+kk)*32 + nq];
        *(float4*)&sWb[kk*C2_LDW + nq*4] =
            make_float4(tfbits(v.x), tfbits(v.y), tfbits(v.z), tfbits(v.w));
    }
    if (tid < 128) sbias[tid] = bias[tid];

    const float4* x1v = (const float4*)g_x1;

    for (int gi = 0; gi < 4; gi++) {
        int ibase = (blockIdx.x*4 + gi) * 8;
        __syncthreads();
        if (tid < 128) {
            int p = tid >> 4, q = tid & 15;
            *(float4*)&sXi[p*68 + q*4] = x1v[(size_t)(ibase+p)*16 + q];
        }
        if (tid < 160) {
            int p = tid / 20;
            sJ[tid] = g_idx[(size_t)(ibase+p)*KNN + (tid - p*20)];
            sP[tid] = p;
        }
        __syncthreads();
        // flat parallel diff build: 2560 float4 over 256 threads
#pragma unroll
        for (int it = 0; it < 10; it++) {
            int fi = tid + it*256;
            int row = fi >> 4, q = fi & 15;
            int j = sJ[row], p = sP[row];
            float4 xj = x1v[(size_t)j*16 + q];
            float4 xi = *(const float4*)&sXi[p*68 + q*4];
            *(float4*)&sD[row*C2_LDD + q*4] =
                make_float4(tfbits(xj.x-xi.x), tfbits(xj.y-xi.y),
                            tfbits(xj.z-xi.z), tfbits(xj.w-xi.w));
        }
        // base: warp covers 16 cols for ALL 8 points
        {
            int p = lane >> 2, c4 = lane & 3;
            int colq = warp*4 + c4;
            const float* xir = &sXi[p*68];
            float4 acc4 = ((const float4*)sbias)[colq];
#pragma unroll 8
            for (int k = 0; k < 64; k++) {
                float xv = xir[k];
                float4 wv = ((const float4*)w)[k*32 + colq];
                acc4.x = fmaf(xv, wv.x, acc4.x); acc4.y = fmaf(xv, wv.y, acc4.y);
                acc4.z = fmaf(xv, wv.z, acc4.z); acc4.w = fmaf(xv, wv.w, acc4.w);
            }
            *(float4*)&sBase[p*C2_LDB + colq*4] = acc4;
        }
        __syncthreads();
        // diff GEMM: [160][64] x [64][128]; warp tile M=80, N=32, 8 k-steps
        float acc[5][4][4];
#pragma unroll
        for (int mi = 0; mi < 5; mi++)
#pragma unroll
            for (int ni = 0; ni < 4; ni++)
#pragma unroll
                for (int c = 0; c < 4; c++) acc[mi][ni][c] = 0.f;
#pragma unroll 1
        for (int ks = 0; ks < 8; ks++) {
            int k0 = ks*8;
            uint32_t A[5][4];
#pragma unroll
            for (int mi = 0; mi < 5; mi++) {
                int row = mB + mi*16 + g4;
                A[mi][0] = __float_as_uint(sD[row*C2_LDD + k0 + tig]);
                A[mi][1] = __float_as_uint(sD[(row+8)*C2_LDD + k0 + tig]);
                A[mi][2] = __float_as_uint(sD[row*C2_LDD + k0 + tig + 4]);
                A[mi][3] = __float_as_uint(sD[(row+8)*C2_LDD + k0 + tig + 4]);
            }
            uint32_t Bf[4][2];
#pragma unroll
            for (int ni = 0; ni < 4; ni++) {
                int col = nB + ni*8 + g4;
                Bf[ni][0] = __float_as_uint(sWb[(k0+tig)*C2_LDW + col]);
                Bf[ni][1] = __float_as_uint(sWb[(k0+tig+4)*C2_LDW + col]);
            }
#pragma unroll
            for (int mi = 0; mi < 5; mi++)
#pragma unroll
                for (int ni = 0; ni < 4; ni++)
                    mma8(acc[mi][ni][0], acc[mi][ni][1], acc[mi][ni][2], acc[mi][ni][3],
                         A[mi][0], A[mi][1], A[mi][2], A[mi][3], Bf[ni][0], Bf[ni][1]);
        }
        // register epilogue: per-point max over edges
        float pm[4][4][2];
#pragma unroll
        for (int p = 0; p < 4; p++)
#pragma unroll
            for (int ni = 0; ni < 4; ni++) { pm[p][ni][0] = -3.4e38f; pm[p][ni][1] = -3.4e38f; }
        bool hi = (g4 >= 4);
#pragma unroll
        for (int ni = 0; ni < 4; ni++) {
            pm[0][ni][0] = fmaxf(pm[0][ni][0], acc[0][ni][0]);
            pm[0][ni][1] = fmaxf(pm[0][ni][1], acc[0][ni][1]);
            if (!hi) { pm[0][ni][0] = fmaxf(pm[0][ni][0], acc[1][ni][0]);
                       pm[0][ni][1] = fmaxf(pm[0][ni][1], acc[1][ni][1]); }
            else     { pm[1][ni][0] = fmaxf(pm[1][ni][0], acc[1][ni][0]);
                       pm[1][ni][1] = fmaxf(pm[1][ni][1], acc[1][ni][1]); }
            pm[1][ni][0] = fmaxf(pm[1][ni][0], acc[2][ni][0]);
            pm[1][ni][1] = fmaxf(pm[1][ni][1], acc[2][ni][1]);
            pm[2][ni][0] = fmaxf(pm[2][ni][0], acc[3][ni][0]);
            pm[2][ni][1] = fmaxf(pm[2][ni][1], acc[3][ni][1]);
            pm[3][ni][0] = fmaxf(pm[3][ni][0], acc[4][ni][0]);
            pm[3][ni][1] = fmaxf(pm[3][ni][1], acc[4][ni][1]);
            pm[0][ni][0] = fmaxf(pm[0][ni][0], acc[0][ni][2]);
            pm[0][ni][1] = fmaxf(pm[0][ni][1], acc[0][ni][3]);
            pm[1][ni][0] = fmaxf(pm[1][ni][0], acc[1][ni][2]);
            pm[1][ni][1] = fmaxf(pm[1][ni][1], acc[1][ni][3]);
            pm[2][ni][0] = fmaxf(pm[2][ni][0], acc[2][ni][2]);
            pm[2][ni][1] = fmaxf(pm[2][ni][1], acc[2][ni][3]);
            if (!hi) { pm[2][ni][0] = fmaxf(pm[2][ni][0], acc[3][ni][2]);
                       pm[2][ni][1] = fmaxf(pm[2][ni][1], acc[3][ni][3]); }
            else     { pm[3][ni][0] = fmaxf(pm[3][ni][0], acc[3][ni][2]);
                       pm[3][ni][1] = fmaxf(pm[3][ni][1], acc[3][ni][3]); }
            pm[3][ni][0] = fmaxf(pm[3][ni][0], acc[4][ni][2]);
            pm[3][ni][1] = fmaxf(pm[3][ni][1], acc[4][ni][3]);
        }
#pragma unroll
        for (int off = 4; off < 32; off <<= 1)
#pragma unroll
            for (int p = 0; p < 4; p++)
#pragma unroll
                for (int ni = 0; ni < 4; ni++) {
                    pm[p][ni][0] = fmaxf(pm[p][ni][0], __shfl_xor_sync(0xffffffff, pm[p][ni][0], off));
                    pm[p][ni][1] = fmaxf(pm[p][ni][1], __shfl_xor_sync(0xffffffff, pm[p][ni][1], off));
                }
        if (g4 == 0) {
#pragma unroll
            for (int p = 0; p < 4; p++) {
                int wp = wm*4 + p;
#pragma unroll
                for (int ni = 0; ni < 4; ni++) {
                    int col = nB + ni*8 + tig*2;
                    float b0v = sBase[wp*C2_LDB + col];
                    float b1v = sBase[wp*C2_LDB + col + 1];
                    float2 o;
                    o.x = fmaxf(pm[p][ni][0] + b0v, 0.f);
                    o.y = fmaxf(pm[p][ni][1] + b1v, 0.f);
                    *(float2*)&g_x2[(size_t)(ibase+wp)*128 + col] = o;
                }
            }
        }
    }
}

// ---------------- l1 (192->1024) tf32 GEMM, k-chunk 32, + fused relu + P-max ----------------
#define L1_LDA 36
__global__ __launch_bounds__(256) void l1max_kernel(
    const float* __restrict__ w, const float* __restrict__ bias)
{
    __shared__ float sA[128*L1_LDA];
    __shared__ float sB[32*136];
    __shared__ float sbias[128];
    __shared__ unsigned int sred[128];
    int tid = threadIdx.x;
    int lane = tid & 31, warp = tid >> 5;
    int g4 = lane >> 2, tig = lane & 3;
    int b = blockIdx.z;
    int n0 = blockIdx.x * 128, m0 = blockIdx.y * 128;
    int pbase = b * PP + m0;
    const float4* x1v = (const float4*)g_x1;
    const float4* x2v = (const float4*)g_x2;
    const float4* wv  = (const float4*)w;
    if (tid < 128) { sred[tid] = 0u; sbias[tid] = bias[n0 + tid]; }

    int wm = warp >> 2, wn = warp & 3;
    float acc[4][4][4];
#pragma unroll
    for (int mi = 0; mi < 4; mi++)
#pragma unroll
        for (int ni = 0; ni < 4; ni++)
#pragma unroll
            for (int c = 0; c < 4; c++) acc[mi][ni][c] = 0.f;

    for (int ks = 0; ks < 6; ks++) {
        __syncthreads();
#pragma unroll
        for (int r = 0; r < 4; r++) {          // A chunk: 128 pts x 32 k
            int fi = tid + r*256;
            int pt = fi >> 3, kq = fi & 7;
            float4 v = (ks < 2) ? x1v[(size_t)(pbase+pt)*16 + ks*8 + kq]
                                : x2v[(size_t)(pbase+pt)*32 + (ks-2)*8 + kq];
            *(float4*)&sA[pt*L1_LDA + kq*4] =
                make_float4(tfbits(v.x), tfbits(v.y), tfbits(v.z), tfbits(v.w));
        }
#pragma unroll
        for (int r = 0; r < 4; r++) {          // B chunk: 32 k x 128 out
            int fi = tid + r*256;
            int kk = fi >> 5, nq = fi & 31;
            float4 v = wv[(size_t)(ks*32+kk)*256 + (n0>>2) + nq];
            *(float4*)&sB[kk*136 + nq*4] =
                make_float4(tfbits(v.x), tfbits(v.y), tfbits(v.z), tfbits(v.w));
        }
        __syncthreads();
#pragma unroll
        for (int kh = 0; kh < 4; kh++) {
            int k0 = kh*8;
            uint32_t A[4][4];
#pragma unroll
            for (int mi = 0; mi < 4; mi++) {
                int row = wm*64 + mi*16 + g4;
                A[mi][0] = __float_as_uint(sA[row*L1_LDA + k0 + tig]);
                A[mi][1] = __float_as_uint(sA[(row+8)*L1_LDA + k0 + tig]);
                A[mi][2] = __float_as_uint(sA[row*L1_LDA + k0 + tig + 4]);
                A[mi][3] = __float_as_uint(sA[(row+8)*L1_LDA + k0 + tig + 4]);
            }
            uint32_t Bf[4][2];
#pragma unroll
            for (int ni = 0; ni < 4; ni++) {
                int col = wn*32 + ni*8 + g4;
                Bf[ni][0] = __float_as_uint(sB[(k0+tig)*136 + col]);
                Bf[ni][1] = __float_as_uint(sB[(k0+tig+4)*136 + col]);
            }
#pragma unroll
            for (int mi = 0; mi < 4; mi++)
#pragma unroll
                for (int ni = 0; ni < 4; ni++)
                    mma8(acc[mi][ni][0], acc[mi][ni][1], acc[mi][ni][2], acc[mi][ni][3],
                         A[mi][0], A[mi][1], A[mi][2], A[mi][3], Bf[ni][0], Bf[ni][1]);
        }
    }
#pragma unroll
    for (int ni = 0; ni < 4; ni++) {
        float v0 = -3.4e38f, v1 = -3.4e38f;
#pragma unroll
        for (int mi = 0; mi < 4; mi++) {
            v0 = fmaxf(v0, fmaxf(acc[mi][ni][0], acc[mi][ni][2]));
            v1 = fmaxf(v1, fmaxf(acc[mi][ni][1], acc[mi][ni][3]));
        }
#pragma unroll
        for (int off = 4; off < 32; off <<= 1) {
            v0 = fmaxf(v0, __shfl_xor_sync(0xffffffff, v0, off));
            v1 = fmaxf(v1, __shfl_xor_sync(0xffffffff, v1, off));
        }
        if (g4 == 0) {
            int col = wn*32 + ni*8 + tig*2;
            float a0 = fmaxf(v0 + sbias[col], 0.f);
            float a1 = fmaxf(v1 + sbias[col+1], 0.f);
            atomicMax(&sred[col],   __float_as_uint(a0));
            atomicMax(&sred[col+1], __float_as_uint(a1));
        }
    }
    __syncthreads();
    if (tid < 128) atomicMax(&g_pool[b*1024 + n0 + tid], sred[tid]);
}

// ---------------- head0: h0 = relu(pool @ m_w0 + b0), grid (2, 32) ----------------
__global__ __launch_bounds__(256) void head0_kernel(
    const float* __restrict__ w0, const float* __restrict__ b0)
{
    __shared__ float sp[1024];
    int b = blockIdx.y, tid = threadIdx.x;
    int o = blockIdx.x * 256 + tid;
    for (int c = tid; c < 1024; c += 256) sp[c] = __uint_as_float(g_pool[b*1024 + c]);
    __syncthreads();
    float a0 = 0.f, a1 = 0.f, a2 = 0.f, a3 = 0.f;
    for (int c = 0; c < 1024; c += 4) {
        a0 = fmaf(sp[c+0], w0[(size_t)(c+0)*512 + o], a0);
        a1 = fmaf(sp[c+1], w0[(size_t)(c+1)*512 + o], a1);
        a2 = fmaf(sp[c+2], w0[(size_t)(c+2)*512 + o], a2);
        a3 = fmaf(sp[c+3], w0[(size_t)(c+3)*512 + o], a3);
    }
    g_h0[b*512 + o] = fmaxf(((a0 + a1) + (a2 + a3)) + b0[o], 0.f);
}

// ---------------- head1: 512->256 relu ->40 + log_softmax, grid 32 ----------------
__global__ __launch_bounds__(256) void head1_kernel(
    const float* __restrict__ w1, const float* __restrict__ b1,
    const float* __restrict__ w2, const float* __restrict__ b2,
    float* __restrict__ out)
{
    __shared__ float sh0[512], sh1[256], sl[40], red[2];
    int b = blockIdx.x, tid = threadIdx.x;
    for (int c = tid; c < 512; c += 256) sh0[c] = g_h0[b*512 + c];
    __syncthreads();
    {
        float a0 = 0.f, a1 = 0.f;
        for (int c = 0; c < 512; c += 2) {
            a0 = fmaf(sh0[c],   w1[(size_t)c*256 + tid],     a0);
            a1 = fmaf(sh0[c+1], w1[(size_t)(c+1)*256 + tid], a1);
        }
        sh1[tid] = fmaxf(a0 + a1 + b1[tid], 0.f);
    }
    __syncthreads();
    if (tid < 40) {
        float a = b2[tid];
        for (int c = 0; c < 256; c++) a += sh1[c] * w2[c*40 + tid];
        sl[tid] = a;
    }
    __syncthreads();
    if (tid == 0) {
        float mxv = -3.4e38f;
        for (int t = 0; t < 40; t++) mxv = fmaxf(mxv, sl[t]);
        float s = 0.f;
        for (int t = 0; t < 40; t++) s += expf(sl[t] - mxv);
        red[0] = mxv; red[1] = logf(s);
    }
    __syncthreads();
    if (tid < 40) out[b*40 + tid] = sl[tid] - red[0] - red[1];
}

// ---------------- launch ----------------
extern "C" void kernel_launch(void* const* d_in, const int* in_sizes, int n_in,
                              void* d_out, int out_size)
{
    const float* pos   = (const float*)d_in[0];
    const float* c1_w0 = (const float*)d_in[2];
    const float* c1_b0 = (const float*)d_in[3];
    const float* c1_w1 = (const float*)d_in[4];
    const float* c1_b1 = (const float*)d_in[5];
    const float* c1_w2 = (const float*)d_in[6];
    const float* c1_b2 = (const float*)d_in[7];
    const float* c2_w0 = (const float*)d_in[8];
    const float* c2_b0 = (const float*)d_in[9];
    const float* l1_w  = (const float*)d_in[10];
    const float* l1_b  = (const float*)d_in[11];
    const float* m_w0  = (const float*)d_in[12];
    const float* m_b0  = (const float*)d_in[13];
    const float* m_w1  = (const float*)d_in[14];
    const float* m_b1  = (const float*)d_in[15];
    const float* m_w2  = (const float*)d_in[16];
    const float* m_b2  = (const float*)d_in[17];
    float* out = (float*)d_out;

    const int smem_conv1 = (576 + 4608 + 4608 + 192 + 160*C1_LDD) * 4;                   // 83456
    const int smem_knn2  = (128*KF_LDA + 64*KF_LDA + 128*KF_LDA + 128 + 64) * 4;         // 87808
    const int smem_conv2 = (64*C2_LDW + 160*C2_LDD + 8*68 + 8*C2_LDB + 128 + 320) * 4;   // ~86.5 KB

    cudaFuncSetAttribute(conv1_kernel,    cudaFuncAttributeMaxDynamicSharedMemorySize, smem_conv1);
    cudaFuncSetAttribute(knn_feat_kernel, cudaFuncAttributeMaxDynamicSharedMemorySize, smem_knn2);
    cudaFuncSetAttribute(conv2_kernel,    cudaFuncAttributeMaxDynamicSharedMemorySize, smem_conv2);

    knn_pos_kernel<<<dim3(4, 32), 256>>>(pos);
    conv1_kernel<<<1024, 256, smem_conv1>>>(pos, c1_w0, c1_b0, c1_w1, c1_b1, c1_w2, c1_b2);
    knn_feat_kernel<<<dim3(8, 32), 256, smem_knn2>>>();
    conv2_kernel<<<1024, 256, smem_conv2>>>(c2_w0, c2_b0);
    l1max_kernel<<<dim3(8, 8, 32), 256>>>(l1_w, l1_b);
    head0_kernel<<<dim3(2, 32), 256>>>(m_w0, m_b0);
    head1_kernel<<<32, 256>>>(m_w1, m_b1, m_w2, m_b2, out);
}

// round 10
// speedup vs baseline: 18.4772x; 1.0443x over previous
#include <cuda_runtime.h>
#include <math.h>
#include <stdint.h>

#define BB 32
#define PP 1024
#define KNN 20
#define NPTS (BB*PP)

// ---------------- scratch (device globals; no allocs allowed) ----------------
__device__ __align__(16) float g_x1[NPTS*64];
__device__ __align__(16) float g_x2[NPTS*128];
__device__ int g_idx[NPTS*KNN];
__device__ unsigned int g_pool[BB*1024];
__device__ __align__(16) float g_h0[BB*512];

// ---------------- tf32 mma helpers ----------------
__device__ __forceinline__ uint32_t f2tf(float x) {
    uint32_t r; asm("cvt.rna.tf32.f32 %0, %1;" : "=r"(r) : "f"(x)); return r;
}
__device__ __forceinline__ float tfbits(float x) {
    return __uint_as_float(f2tf(x));
}
__device__ __forceinline__ void mma8(float& c0, float& c1, float& c2, float& c3,
                                     uint32_t a0, uint32_t a1, uint32_t a2, uint32_t a3,
                                     uint32_t b0, uint32_t b1)
{
    asm volatile("mma.sync.aligned.m16n8k8.row.col.f32.tf32.tf32.f32 "
                 "{%0,%1,%2,%3},{%4,%5,%6,%7},{%8,%9},{%0,%1,%2,%3};"
                 : "+f"(c0), "+f"(c1), "+f"(c2), "+f"(c3)
                 : "r"(a0), "r"(a1), "r"(a2), "r"(a3), "r"(b0), "r"(b1));
}

// top-k insertion (strict <, keeps earliest index on ties — matches jax top_k)
__device__ __forceinline__ void topk_insert(float* bd, int* bi, float d, int j)
{
    if (d < bd[KNN-1]) {
        bd[KNN-1] = d; bi[KNN-1] = j;
#pragma unroll
        for (int t = KNN-1; t > 0; t--) {
            if (bd[t] < bd[t-1]) {
                float td = bd[t]; bd[t] = bd[t-1]; bd[t-1] = td;
                int ti = bi[t]; bi[t] = bi[t-1]; bi[t-1] = ti;
            }
        }
    }
}

// 5 m-tiles x 2 n-tiles warp GEMM (used by conv1)
__device__ __forceinline__ void mma_5x2(
    const float* sD, const float* sW, float acc[5][2][4],
    int mB, int nB, int g4, int tig, int ksteps, int ldd, int ldw)
{
#pragma unroll
    for (int mi = 0; mi < 5; mi++)
#pragma unroll
        for (int ni = 0; ni < 2; ni++)
#pragma unroll
            for (int c = 0; c < 4; c++) acc[mi][ni][c] = 0.f;
#pragma unroll 1
    for (int ks = 0; ks < ksteps; ks++) {
        int k0 = ks * 8;
        uint32_t A[5][4];
#pragma unroll
        for (int mi = 0; mi < 5; mi++) {
            int row = mB + mi*16 + g4;
            A[mi][0] = __float_as_uint(sD[row*ldd + k0 + tig]);
            A[mi][1] = __float_as_uint(sD[(row+8)*ldd + k0 + tig]);
            A[mi][2] = __float_as_uint(sD[row*ldd + k0 + tig + 4]);
            A[mi][3] = __float_as_uint(sD[(row+8)*ldd + k0 + tig + 4]);
        }
        uint32_t Bf[2][2];
#pragma unroll
        for (int ni = 0; ni < 2; ni++) {
            int col = nB + ni*8 + g4;
            Bf[ni][0] = __float_as_uint(sW[(k0+tig)*ldw + col]);
            Bf[ni][1] = __float_as_uint(sW[(k0+tig+4)*ldw + col]);
        }
#pragma unroll
        for (int mi = 0; mi < 5; mi++)
#pragma unroll
            for (int ni = 0; ni < 2; ni++)
                mma8(acc[mi][ni][0], acc[mi][ni][1], acc[mi][ni][2], acc[mi][ni][3],
                     A[mi][0], A[mi][1], A[mi][2], A[mi][3], Bf[ni][0], Bf[ni][1]);
    }
}

__device__ __forceinline__ void wb_5x2(
    float* sD, float acc[5][2][4], const float* bias,
    int mB, int nB, int g4, int tig, int ldd, int mode)
{
#pragma unroll
    for (int mi = 0; mi < 5; mi++) {
#pragma unroll
        for (int ni = 0; ni < 2; ni++) {
            int row = mB + mi*16 + g4, col = nB + ni*8 + tig*2;
            float v0 = acc[mi][ni][0], v1 = acc[mi][ni][1];
            float v2 = acc[mi][ni][2], v3 = acc[mi][ni][3];
            float ba = bias[col], bb = bias[col+1];
            v0 += ba; v1 += bb; v2 += ba; v3 += bb;
            if (mode == 1) {
                v0 = fmaxf(v0, 0.f); v1 = fmaxf(v1, 0.f);
                v2 = fmaxf(v2, 0.f); v3 = fmaxf(v3, 0.f);
            }
            v0 = tfbits(v0); v1 = tfbits(v1); v2 = tfbits(v2); v3 = tfbits(v3);
            sD[row*ldd + col] = v0;     sD[row*ldd + col + 1] = v1;
            sD[(row+8)*ldd + col] = v2; sD[(row+8)*ldd + col + 1] = v3;
        }
    }
}

// ---------------- KNN over 3-D positions: split-scan (2 threads/point) + pool zero ----------------
__global__ __launch_bounds__(512) void knn_pos_kernel(const float* __restrict__ pos)
{
    extern __shared__ float smk[];
    float4* spos = (float4*)smk;                     // 1024 float4
    float*  sbd  = smk + 4096;                       // 256*20
    int*    sbi  = (int*)(smk + 4096 + 5120);        // 256*20
    int tid = threadIdx.x;
    int lb = blockIdx.y*4 + blockIdx.x;
    if (tid < 256) g_pool[lb*256 + tid] = 0u;
    int b = blockIdx.y;
    const float* p = pos + (size_t)b * PP * 3;
    for (int j = tid; j < PP; j += 512) {
        float x = p[3*j], y = p[3*j+1], z = p[3*j+2];
        spos[j] = make_float4(x, y, z, x*x + y*y + z*z);
    }
    __syncthreads();
    int pt = tid & 255, s = tid >> 8;        // scanner s ∈ {0,1}
    int il = blockIdx.x * 256 + pt;
    float4 me = spos[il];
    float xi = me.x, yi = me.y, zi = me.z, sqi = me.w;
    float bd[KNN]; int bi[KNN];
#pragma unroll
    for (int t = 0; t < KNN; t++) { bd[t] = 3.4e38f; bi[t] = 0; }
    int j4base = s * 128;
    for (int j4 = j4base; j4 < j4base + 128; j4++) {
        float4 v0 = spos[4*j4+0], v1 = spos[4*j4+1], v2 = spos[4*j4+2], v3 = spos[4*j4+3];
        float d0 = sqi + v0.w - 2.0f*(xi*v0.x + yi*v0.y + zi*v0.z);
        float d1 = sqi + v1.w - 2.0f*(xi*v1.x + yi*v1.y + zi*v1.z);
        float d2 = sqi + v2.w - 2.0f*(xi*v2.x + yi*v2.y + zi*v2.z);
        float d3 = sqi + v3.w - 2.0f*(xi*v3.x + yi*v3.y + zi*v3.z);
        float mn = fminf(fminf(d0, d1), fminf(d2, d3));
        if (mn < bd[KNN-1]) {
            topk_insert(bd, bi, d0, 4*j4+0);
            topk_insert(bd, bi, d1, 4*j4+1);
            topk_insert(bd, bi, d2, 4*j4+2);
            topk_insert(bd, bi, d3, 4*j4+3);
        }
    }
    if (s == 1) {
#pragma unroll
        for (int t = 0; t < KNN; t++) { sbd[pt*KNN + t] = bd[t]; sbi[pt*KNN + t] = bi[t]; }
    }
    __syncthreads();
    if (s == 0) {
        // merge scanner1's sorted list; scanner1 j's are all > scanner0's, so strict < keeps ties stable
        for (int t = 0; t < KNN; t++) {
            float d = sbd[pt*KNN + t];
            if (!(d < bd[KNN-1])) break;
            topk_insert(bd, bi, d, sbi[pt*KNN + t]);
        }
        int gi = b * PP + il;
#pragma unroll
        for (int t = 0; t < KNN; t++) g_idx[gi*KNN + t] = b * PP + bi[t];
    }
}

// ---------------- EdgeConv1: tf32 tensor cores, persistent grid-stride ----------------
#define C1_LDD 68
#define C1_LDW 72
__global__ __launch_bounds__(256, 2) void conv1_kernel(
    const float* __restrict__ pos,
    const float* __restrict__ w0, const float* __restrict__ b0,
    const float* __restrict__ w1, const float* __restrict__ b1,
    const float* __restrict__ w2, const float* __restrict__ b2)
{
    extern __shared__ float sm[];
    float* sW0 = sm;
    float* sW1 = sm + 576;
    float* sW2 = sm + 5184;
    float* sb0 = sm + 9792;
    float* sb1 = sm + 9856;
    float* sb2 = sm + 9920;
    float* sD  = sm + 9984;     // 160*68

    int tid = threadIdx.x, lane = tid & 31, warp = tid >> 5;
    int g4 = lane >> 2, tig = lane & 3;
    int wm = warp >> 2, wn = warp & 3;
    int mB = wm * 80, nB = wn * 16;

    for (int fi = tid; fi < 512; fi += 256) {
        int kk = fi >> 6, o = fi & 63;
        sW0[kk*C1_LDW + o] = (kk < 6) ? tfbits(w0[kk*64 + o]) : 0.f;
    }
    for (int fi = tid; fi < 4096; fi += 256) {
        int kk = fi >> 6, o = fi & 63;
        sW1[kk*C1_LDW + o] = tfbits(w1[fi]);
        sW2[kk*C1_LDW + o] = tfbits(w2[fi]);
    }
    if (tid < 64) { sb0[tid] = b0[tid]; sb1[tid] = b1[tid]; sb2[tid] = b2[tid]; }

    float acc[5][2][4];
    for (int g = blockIdx.x; g < 4096; g += gridDim.x) {
        int ibase = g * 8;
        __syncthreads();
        if (tid < 160) {
            int p = tid / 20, e = tid - p*20;
            int i = ibase + p;
            int j = g_idx[i*KNN + e];
            float xx = pos[i*3], xy = pos[i*3+1], xz = pos[i*3+2];
            float jx = pos[j*3], jy = pos[j*3+1], jz = pos[j*3+2];
            float* dr = sD + tid*C1_LDD;
            dr[0] = tfbits(xx); dr[1] = tfbits(xy); dr[2] = tfbits(xz);
            dr[3] = tfbits(jx-xx); dr[4] = tfbits(jy-xy); dr[5] = tfbits(jz-xz);
            dr[6] = 0.f; dr[7] = 0.f;
        }
        __syncthreads();
        mma_5x2(sD, sW0, acc, mB, nB, g4, tig, 1, C1_LDD, C1_LDW);
        __syncthreads();
        wb_5x2(sD, acc, sb0, mB, nB, g4, tig, C1_LDD, 0);
        __syncthreads();
        mma_5x2(sD, sW1, acc, mB, nB, g4, tig, 8, C1_LDD, C1_LDW);
        __syncthreads();
        wb_5x2(sD, acc, sb1, mB, nB, g4, tig, C1_LDD, 1);
        __syncthreads();
        mma_5x2(sD, sW2, acc, mB, nB, g4, tig, 8, C1_LDD, C1_LDW);
        // register epilogue: per-point max over edges (rows mB..mB+79 = 4 points)
        {
            float pm[4][2][2];
#pragma unroll
            for (int p = 0; p < 4; p++)
#pragma unroll
                for (int ni = 0; ni < 2; ni++) { pm[p][ni][0] = -3.4e38f; pm[p][ni][1] = -3.4e38f; }
            bool hi = (g4 >= 4);
#pragma unroll
            for (int ni = 0; ni < 2; ni++) {
                pm[0][ni][0] = fmaxf(pm[0][ni][0], acc[0][ni][0]);
                pm[0][ni][1] = fmaxf(pm[0][ni][1], acc[0][ni][1]);
                if (!hi) { pm[0][ni][0] = fmaxf(pm[0][ni][0], acc[1][ni][0]);
                           pm[0][ni][1] = fmaxf(pm[0][ni][1], acc[1][ni][1]); }
                else     { pm[1][ni][0] = fmaxf(pm[1][ni][0], acc[1][ni][0]);
                           pm[1][ni][1] = fmaxf(pm[1][ni][1], acc[1][ni][1]); }
                pm[1][ni][0] = fmaxf(pm[1][ni][0], acc[2][ni][0]);
                pm[1][ni][1] = fmaxf(pm[1][ni][1], acc[2][ni][1]);
                pm[2][ni][0] = fmaxf(pm[2][ni][0], acc[3][ni][0]);
                pm[2][ni][1] = fmaxf(pm[2][ni][1], acc[3][ni][1]);
                pm[3][ni][0] = fmaxf(pm[3][ni][0], acc[4][ni][0]);
                pm[3][ni][1] = fmaxf(pm[3][ni][1], acc[4][ni][1]);
                pm[0][ni][0] = fmaxf(pm[0][ni][0], acc[0][ni][2]);
                pm[0][ni][1] = fmaxf(pm[0][ni][1], acc[0][ni][3]);
                pm[1][ni][0] = fmaxf(pm[1][ni][0], acc[1][ni][2]);
                pm[1][ni][1] = fmaxf(pm[1][ni][1], acc[1][ni][3]);
                pm[2][ni][0] = fmaxf(pm[2][ni][0], acc[2][ni][2]);
                pm[2][ni][1] = fmaxf(pm[2][ni][1], acc[2][ni][3]);
                if (!hi) { pm[2][ni][0] = fmaxf(pm[2][ni][0], acc[3][ni][2]);
                           pm[2][ni][1] = fmaxf(pm[2][ni][1], acc[3][ni][3]); }
                else     { pm[3][ni][0] = fmaxf(pm[3][ni][0], acc[3][ni][2]);
                           pm[3][ni][1] = fmaxf(pm[3][ni][1], acc[3][ni][3]); }
                pm[3][ni][0] = fmaxf(pm[3][ni][0], acc[4][ni][2]);
                pm[3][ni][1] = fmaxf(pm[3][ni][1], acc[4][ni][3]);
            }
#pragma unroll
            for (int off = 4; off < 32; off <<= 1)
#pragma unroll
                for (int p = 0; p < 4; p++)
#pragma unroll
                    for (int ni = 0; ni < 2; ni++) {
                        pm[p][ni][0] = fmaxf(pm[p][ni][0], __shfl_xor_sync(0xffffffff, pm[p][ni][0], off));
                        pm[p][ni][1] = fmaxf(pm[p][ni][1], __shfl_xor_sync(0xffffffff, pm[p][ni][1], off));
                    }
            if (g4 == 0) {
#pragma unroll
                for (int p = 0; p < 4; p++) {
                    int wp = wm*4 + p;
#pragma unroll
                    for (int ni = 0; ni < 2; ni++) {
                        int col = nB + ni*8 + tig*2;
                        float2 o;
                        o.x = fmaxf(pm[p][ni][0] + sb2[col],   0.f);
                        o.y = fmaxf(pm[p][ni][1] + sb2[col+1], 0.f);
                        *(float2*)&g_x1[(size_t)(ibase+wp)*64 + col] = o;
                    }
                }
            }
        }
    }
}

// ---------------- KNN over 64-D features v3: 64-wide j-tiles, 2 blocks/SM ----------------
#define KF_LDA 68
__global__ __launch_bounds__(256, 2) void knn_feat_kernel()
{
    extern __shared__ float sm[];
    float* sA   = sm;                        // 128*68  (Xi tf32)
    float* sB   = sA + 128*KF_LDA;           // 64*68   (Xj tf32)
    float* sdot = sB + 64*KF_LDA;            // 128*68
    float* sqi  = sdot + 128*KF_LDA;         // 128
    float* sqj  = sqi + 128;                 // 64

    int tid = threadIdx.x, lane = tid & 31, warp = tid >> 5;
    int g4 = lane >> 2, tig = lane & 3;
    int wm = warp >> 1, wn = warp & 1;       // 4 m-warps x 2 n-warps; tile 32x32
    int b = blockIdx.y;
    int i0 = b*PP + blockIdx.x*128;
    const float4* x1v = (const float4*)g_x1;

    for (int fi = tid; fi < 128*16; fi += 256) {
        int pt = fi >> 4, q = fi & 15;
        float4 v = x1v[(size_t)(i0+pt)*16 + q];
        *(float4*)&sA[pt*KF_LDA + q*4] =
            make_float4(tfbits(v.x), tfbits(v.y), tfbits(v.z), tfbits(v.w));
    }
    if (tid < 128) {
        float s = 0.f;
#pragma unroll
        for (int q = 0; q < 16; q++) {
            float4 v = x1v[(size_t)(i0+tid)*16 + q];
            s += v.x*v.x + v.y*v.y + v.z*v.z + v.w*v.w;
        }
        sqi[tid] = s;
    }

    float bd[KNN]; int bi[KNN];
#pragma unroll
    for (int t = 0; t < KNN; t++) { bd[t] = 3.4e38f; bi[t] = 0; }
    float mysq = 0.f;

    for (int jt = 0; jt < 16; jt++) {
        int j0 = b*PP + jt*64;
        __syncthreads();
#pragma unroll
        for (int r = 0; r < 4; r++) {
            int fi = tid + r*256;
            int pt = fi >> 4, q = fi & 15;
            float4 v = x1v[(size_t)(j0+pt)*16 + q];
            *(float4*)&sB[pt*KF_LDA + q*4] =
                make_float4(tfbits(v.x), tfbits(v.y), tfbits(v.z), tfbits(v.w));
        }
        if (tid < 64) {
            float s = 0.f;
#pragma unroll
            for (int q = 0; q < 16; q++) {
                float4 v = x1v[(size_t)(j0+tid)*16 + q];
                s += v.x*v.x + v.y*v.y + v.z*v.z + v.w*v.w;
            }
            sqj[tid] = s;
        }
        __syncthreads();
        // GEMM dot[128 i][64 j], K=64; warp tile 32x32
        float acc[2][4][4];
#pragma unroll
        for (int mi = 0; mi < 2; mi++)
#pragma unroll
            for (int ni = 0; ni < 4; ni++)
#pragma unroll
                for (int c = 0; c < 4; c++) acc[mi][ni][c] = 0.f;
#pragma unroll
        for (int ks = 0; ks < 8; ks++) {
            int k0 = ks*8;
            uint32_t A[2][4];
#pragma unroll
            for (int mi = 0; mi < 2; mi++) {
                int row = wm*32 + mi*16 + g4;
                A[mi][0] = __float_as_uint(sA[row*KF_LDA + k0 + tig]);
                A[mi][1] = __float_as_uint(sA[(row+8)*KF_LDA + k0 + tig]);
                A[mi][2] = __float_as_uint(sA[row*KF_LDA + k0 + tig + 4]);
                A[mi][3] = __float_as_uint(sA[(row+8)*KF_LDA + k0 + tig + 4]);
            }
            uint32_t Bf[4][2];
#pragma unroll
            for (int ni = 0; ni < 4; ni++) {
                int col = wn*32 + ni*8 + g4;
                Bf[ni][0] = __float_as_uint(sB[col*KF_LDA + k0 + tig]);
                Bf[ni][1] = __float_as_uint(sB[col*KF_LDA + k0 + tig + 4]);
            }
#pragma unroll
            for (int mi = 0; mi < 2; mi++)
#pragma unroll
                for (int ni = 0; ni < 4; ni++)
                    mma8(acc[mi][ni][0], acc[mi][ni][1], acc[mi][ni][2], acc[mi][ni][3],
                         A[mi][0], A[mi][1], A[mi][2], A[mi][3], Bf[ni][0], Bf[ni][1]);
        }
#pragma unroll
        for (int mi = 0; mi < 2; mi++) {
#pragma unroll
            for (int ni = 0; ni < 4; ni++) {
                int row = wm*32 + mi*16 + g4, col = wn*32 + ni*8 + tig*2;
                *(float2*)&sdot[row*KF_LDA + col]     = make_float2(acc[mi][ni][0], acc[mi][ni][1]);
                *(float2*)&sdot[(row+8)*KF_LDA + col] = make_float2(acc[mi][ni][2], acc[mi][ni][3]);
            }
        }
        __syncthreads();
        // fast selection: float4 + min early-out
        if (tid < 128) {
            if (jt == 0) mysq = sqi[tid];
            const float4* drow4 = (const float4*)(sdot + tid*KF_LDA);
            const float4* sqj4  = (const float4*)sqj;
            int jbase = jt*64;
#pragma unroll 4
            for (int j4 = 0; j4 < 16; j4++) {
                float4 dv = drow4[j4];
                float4 sv = sqj4[j4];
                float d0 = mysq + sv.x - 2.0f*dv.x;
                float d1 = mysq + sv.y - 2.0f*dv.y;
                float d2 = mysq + sv.z - 2.0f*dv.z;
                float d3 = mysq + sv.w - 2.0f*dv.w;
                float mn = fminf(fminf(d0, d1), fminf(d2, d3));
                if (mn < bd[KNN-1]) {
                    topk_insert(bd, bi, d0, jbase + 4*j4 + 0);
                    topk_insert(bd, bi, d1, jbase + 4*j4 + 1);
                    topk_insert(bd, bi, d2, jbase + 4*j4 + 2);
                    topk_insert(bd, bi, d3, jbase + 4*j4 + 3);
                }
            }
        }
    }
    if (tid < 128) {
        int gi = i0 + tid;
#pragma unroll
        for (int t = 0; t < KNN; t++) g_idx[(size_t)gi*KNN + t] = b*PP + bi[t];
    }
}

// ---------------- EdgeConv2 v6: persistent grid-stride + flat build + coop base + diff GEMM ----------------
#define C2_LDD 68
#define C2_LDW 136
#define C2_LDB 132
__global__ __launch_bounds__(256, 2) void conv2_kernel(
    const float* __restrict__ w, const float* __restrict__ bias)
{
    extern __shared__ float sm[];
    float* sWb   = sm;                        // 64*136 (W rows 64..127, tf32)
    float* sD    = sm + 64*C2_LDW;            // 160*68 diff tf32
    float* sXi   = sD + 160*C2_LDD;           // 8*68 exact fp32
    float* sBase = sXi + 8*68;                // 8*132
    float* sbias = sBase + 8*C2_LDB;          // 128
    int*   sJ    = (int*)(sbias + 128);       // 160
    int*   sP    = sJ + 160;                  // 160

    int tid = threadIdx.x, lane = tid & 31, warp = tid >> 5;
    int g4 = lane >> 2, tig = lane & 3;
    int wm = warp >> 2, wn = warp & 3;
    int mB = wm*80, nB = wn*32;

    for (int fi = tid; fi < 2048; fi += 256) {
        int kk = fi >> 5, nq = fi & 31;
        float4 v = ((const float4*)w)[(64+kk)*32 + nq];
        *(float4*)&sWb[kk*C2_LDW + nq*4] =
            make_float4(tfbits(v.x), tfbits(v.y), tfbits(v.z), tfbits(v.w));
    }
    if (tid < 128) sbias[tid] = bias[tid];

    const float4* x1v = (const float4*)g_x1;

    for (int g = blockIdx.x; g < 4096; g += gridDim.x) {
        int ibase = g * 8;
        __syncthreads();
        if (tid < 128) {
            int p = tid >> 4, q = tid & 15;
            *(float4*)&sXi[p*68 + q*4] = x1v[(size_t)(ibase+p)*16 + q];
        }
        if (tid < 160) {
            int p = tid / 20;
            sJ[tid] = g_idx[(size_t)(ibase+p)*KNN + (tid - p*20)];
            sP[tid] = p;
        }
        __syncthreads();
        // flat parallel diff build: 2560 float4 over 256 threads
#pragma unroll
        for (int it = 0; it < 10; it++) {
            int fi = tid + it*256;
            int row = fi >> 4, q = fi & 15;
            int j = sJ[row], p = sP[row];
            float4 xj = x1v[(size_t)j*16 + q];
            float4 xi = *(const float4*)&sXi[p*68 + q*4];
            *(float4*)&sD[row*C2_LDD + q*4] =
                make_float4(tfbits(xj.x-xi.x), tfbits(xj.y-xi.y),
                            tfbits(xj.z-xi.z), tfbits(xj.w-xi.w));
        }
        // base: warp covers 16 cols for ALL 8 points
        {
            int p = lane >> 2, c4 = lane & 3;
            int colq = warp*4 + c4;
            const float* xir = &sXi[p*68];
            float4 acc4 = ((const float4*)sbias)[colq];
#pragma unroll 8
            for (int k = 0; k < 64; k++) {
                float xv = xir[k];
                float4 wv = ((const float4*)w)[k*32 + colq];
                acc4.x = fmaf(xv, wv.x, acc4.x); acc4.y = fmaf(xv, wv.y, acc4.y);
                acc4.z = fmaf(xv, wv.z, acc4.z); acc4.w = fmaf(xv, wv.w, acc4.w);
            }
            *(float4*)&sBase[p*C2_LDB + colq*4] = acc4;
        }
        __syncthreads();
        // diff GEMM: [160][64] x [64][128]; warp tile M=80, N=32, 8 k-steps
        float acc[5][4][4];
#pragma unroll
        for (int mi = 0; mi < 5; mi++)
#pragma unroll
            for (int ni = 0; ni < 4; ni++)
#pragma unroll
                for (int c = 0; c < 4; c++) acc[mi][ni][c] = 0.f;
#pragma unroll 1
        for (int ks = 0; ks < 8; ks++) {
            int k0 = ks*8;
            uint32_t A[5][4];
#pragma unroll
            for (int mi = 0; mi < 5; mi++) {
                int row = mB + mi*16 + g4;
                A[mi][0] = __float_as_uint(sD[row*C2_LDD + k0 + tig]);
                A[mi][1] = __float_as_uint(sD[(row+8)*C2_LDD + k0 + tig]);
                A[mi][2] = __float_as_uint(sD[row*C2_LDD + k0 + tig + 4]);
                A[mi][3] = __float_as_uint(sD[(row+8)*C2_LDD + k0 + tig + 4]);
            }
            uint32_t Bf[4][2];
#pragma unroll
            for (int ni = 0; ni < 4; ni++) {
                int col = nB + ni*8 + g4;
                Bf[ni][0] = __float_as_uint(sWb[(k0+tig)*C2_LDW + col]);
                Bf[ni][1] = __float_as_uint(sWb[(k0+tig+4)*C2_LDW + col]);
            }
#pragma unroll
            for (int mi = 0; mi < 5; mi++)
#pragma unroll
                for (int ni = 0; ni < 4; ni++)
                    mma8(acc[mi][ni][0], acc[mi][ni][1], acc[mi][ni][2], acc[mi][ni][3],
                         A[mi][0], A[mi][1], A[mi][2], A[mi][3], Bf[ni][0], Bf[ni][1]);
        }
        // register epilogue: per-point max over edges
        float pm[4][4][2];
#pragma unroll
        for (int p = 0; p < 4; p++)
#pragma unroll
            for (int ni = 0; ni < 4; ni++) { pm[p][ni][0] = -3.4e38f; pm[p][ni][1] = -3.4e38f; }
        bool hi = (g4 >= 4);
#pragma unroll
        for (int ni = 0; ni < 4; ni++) {
            pm[0][ni][0] = fmaxf(pm[0][ni][0], acc[0][ni][0]);
            pm[0][ni][1] = fmaxf(pm[0][ni][1], acc[0][ni][1]);
            if (!hi) { pm[0][ni][0] = fmaxf(pm[0][ni][0], acc[1][ni][0]);
                       pm[0][ni][1] = fmaxf(pm[0][ni][1], acc[1][ni][1]); }
            else     { pm[1][ni][0] = fmaxf(pm[1][ni][0], acc[1][ni][0]);
                       pm[1][ni][1] = fmaxf(pm[1][ni][1], acc[1][ni][1]); }
            pm[1][ni][0] = fmaxf(pm[1][ni][0], acc[2][ni][0]);
            pm[1][ni][1] = fmaxf(pm[1][ni][1], acc[2][ni][1]);
            pm[2][ni][0] = fmaxf(pm[2][ni][0], acc[3][ni][0]);
            pm[2][ni][1] = fmaxf(pm[2][ni][1], acc[3][ni][1]);
            pm[3][ni][0] = fmaxf(pm[3][ni][0], acc[4][ni][0]);
            pm[3][ni][1] = fmaxf(pm[3][ni][1], acc[4][ni][1]);
            pm[0][ni][0] = fmaxf(pm[0][ni][0], acc[0][ni][2]);
            pm[0][ni][1] = fmaxf(pm[0][ni][1], acc[0][ni][3]);
            pm[1][ni][0] = fmaxf(pm[1][ni][0], acc[1][ni][2]);
            pm[1][ni][1] = fmaxf(pm[1][ni][1], acc[1][ni][3]);
            pm[2][ni][0] = fmaxf(pm[2][ni][0], acc[2][ni][2]);
            pm[2][ni][1] = fmaxf(pm[2][ni][1], acc[2][ni][3]);
            if (!hi) { pm[2][ni][0] = fmaxf(pm[2][ni][0], acc[3][ni][2]);
                       pm[2][ni][1] = fmaxf(pm[2][ni][1], acc[3][ni][3]); }
            else     { pm[3][ni][0] = fmaxf(pm[3][ni][0], acc[3][ni][2]);
                       pm[3][ni][1] = fmaxf(pm[3][ni][1], acc[3][ni][3]); }
            pm[3][ni][0] = fmaxf(pm[3][ni][0], acc[4][ni][2]);
            pm[3][ni][1] = fmaxf(pm[3][ni][1], acc[4][ni][3]);
        }
#pragma unroll
        for (int off = 4; off < 32; off <<= 1)
#pragma unroll
            for (int p = 0; p < 4; p++)
#pragma unroll
                for (int ni = 0; ni < 4; ni++) {
                    pm[p][ni][0] = fmaxf(pm[p][ni][0], __shfl_xor_sync(0xffffffff, pm[p][ni][0], off));
                    pm[p][ni][1] = fmaxf(pm[p][ni][1], __shfl_xor_sync(0xffffffff, pm[p][ni][1], off));
                }
        if (g4 == 0) {
#pragma unroll
            for (int p = 0; p < 4; p++) {
                int wp = wm*4 + p;
#pragma unroll
                for (int ni = 0; ni < 4; ni++) {
                    int col = nB + ni*8 + tig*2;
                    float b0v = sBase[wp*C2_LDB + col];
                    float b1v = sBase[wp*C2_LDB + col + 1];
                    float2 o;
                    o.x = fmaxf(pm[p][ni][0] + b0v, 0.f);
                    o.y = fmaxf(pm[p][ni][1] + b1v, 0.f);
                    *(float2*)&g_x2[(size_t)(ibase+wp)*128 + col] = o;
                }
            }
        }
    }
}

// ---------------- l1 (192->1024) tf32 GEMM, k-chunk 32, + fused relu + P-max ----------------
#define L1_LDA 36
__global__ __launch_bounds__(256) void l1max_kernel(
    const float* __restrict__ w, const float* __restrict__ bias)
{
    __shared__ float sA[128*L1_LDA];
    __shared__ float sB[32*136];
    __shared__ float sbias[128];
    __shared__ unsigned int sred[128];
    int tid = threadIdx.x;
    int lane = tid & 31, warp = tid >> 5;
    int g4 = lane >> 2, tig = lane & 3;
    int b = blockIdx.z;
    int n0 = blockIdx.x * 128, m0 = blockIdx.y * 128;
    int pbase = b * PP + m0;
    const float4* x1v = (const float4*)g_x1;
    const float4* x2v = (const float4*)g_x2;
    const float4* wv  = (const float4*)w;
    if (tid < 128) { sred[tid] = 0u; sbias[tid] = bias[n0 + tid]; }

    int wm = warp >> 2, wn = warp & 3;
    float acc[4][4][4];
#pragma unroll
    for (int mi = 0; mi < 4; mi++)
#pragma unroll
        for (int ni = 0; ni < 4; ni++)
#pragma unroll
            for (int c = 0; c < 4; c++) acc[mi][ni][c] = 0.f;

    for (int ks = 0; ks < 6; ks++) {
        __syncthreads();
#pragma unroll
        for (int r = 0; r < 4; r++) {          // A chunk: 128 pts x 32 k
            int fi = tid + r*256;
            int pt = fi >> 3, kq = fi & 7;
            float4 v = (ks < 2) ? x1v[(size_t)(pbase+pt)*16 + ks*8 + kq]
                                : x2v[(size_t)(pbase+pt)*32 + (ks-2)*8 + kq];
            *(float4*)&sA[pt*L1_LDA + kq*4] =
                make_float4(tfbits(v.x), tfbits(v.y), tfbits(v.z), tfbits(v.w));
        }
#pragma unroll
        for (int r = 0; r < 4; r++) {          // B chunk: 32 k x 128 out
            int fi = tid + r*256;
            int kk = fi >> 5, nq = fi & 31;
            float4 v = wv[(size_t)(ks*32+kk)*256 + (n0>>2) + nq];
            *(float4*)&sB[kk*136 + nq*4] =
                make_float4(tfbits(v.x), tfbits(v.y), tfbits(v.z), tfbits(v.w));
        }
        __syncthreads();
#pragma unroll
        for (int kh = 0; kh < 4; kh++) {
            int k0 = kh*8;
            uint32_t A[4][4];
#pragma unroll
            for (int mi = 0; mi < 4; mi++) {
                int row = wm*64 + mi*16 + g4;
                A[mi][0] = __float_as_uint(sA[row*L1_LDA + k0 + tig]);
                A[mi][1] = __float_as_uint(sA[(row+8)*L1_LDA + k0 + tig]);
                A[mi][2] = __float_as_uint(sA[row*L1_LDA + k0 + tig + 4]);
                A[mi][3] = __float_as_uint(sA[(row+8)*L1_LDA + k0 + tig + 4]);
            }
            uint32_t Bf[4][2];
#pragma unroll
            for (int ni = 0; ni < 4; ni++) {
                int col = wn*32 + ni*8 + g4;
                Bf[ni][0] = __float_as_uint(sB[(k0+tig)*136 + col]);
                Bf[ni][1] = __float_as_uint(sB[(k0+tig+4)*136 + col]);
            }
#pragma unroll
            for (int mi = 0; mi < 4; mi++)
#pragma unroll
                for (int ni = 0; ni < 4; ni++)
                    mma8(acc[mi][ni][0], acc[mi][ni][1], acc[mi][ni][2], acc[mi][ni][3],
                         A[mi][0], A[mi][1], A[mi][2], A[mi][3], Bf[ni][0], Bf[ni][1]);
        }
    }
#pragma unroll
    for (int ni = 0; ni < 4; ni++) {
        float v0 = -3.4e38f, v1 = -3.4e38f;
#pragma unroll
        for (int mi = 0; mi < 4; mi++) {
            v0 = fmaxf(v0, fmaxf(acc[mi][ni][0], acc[mi][ni][2]));
            v1 = fmaxf(v1, fmaxf(acc[mi][ni][1], acc[mi][ni][3]));
        }
#pragma unroll
        for (int off = 4; off < 32; off <<= 1) {
            v0 = fmaxf(v0, __shfl_xor_sync(0xffffffff, v0, off));
            v1 = fmaxf(v1, __shfl_xor_sync(0xffffffff, v1, off));
        }
        if (g4 == 0) {
            int col = wn*32 + ni*8 + tig*2;
            float a0 = fmaxf(v0 + sbias[col], 0.f);
            float a1 = fmaxf(v1 + sbias[col+1], 0.f);
            atomicMax(&sred[col],   __float_as_uint(a0));
            atomicMax(&sred[col+1], __float_as_uint(a1));
        }
    }
    __syncthreads();
    if (tid < 128) atomicMax(&g_pool[b*1024 + n0 + tid], sred[tid]);
}

// ---------------- head0: h0 = relu(pool @ m_w0 + b0), grid (2, 32) ----------------
__global__ __launch_bounds__(256) void head0_kernel(
    const float* __restrict__ w0, const float* __restrict__ b0)
{
    __shared__ float sp[1024];
    int b = blockIdx.y, tid = threadIdx.x;
    int o = blockIdx.x * 256 + tid;
    for (int c = tid; c < 1024; c += 256) sp[c] = __uint_as_float(g_pool[b*1024 + c]);
    __syncthreads();
    float a0 = 0.f, a1 = 0.f, a2 = 0.f, a3 = 0.f;
    for (int c = 0; c < 1024; c += 4) {
        a0 = fmaf(sp[c+0], w0[(size_t)(c+0)*512 + o], a0);
        a1 = fmaf(sp[c+1], w0[(size_t)(c+1)*512 + o], a1);
        a2 = fmaf(sp[c+2], w0[(size_t)(c+2)*512 + o], a2);
        a3 = fmaf(sp[c+3], w0[(size_t)(c+3)*512 + o], a3);
    }
    g_h0[b*512 + o] = fmaxf(((a0 + a1) + (a2 + a3)) + b0[o], 0.f);
}

// ---------------- head1: 512->256 relu ->40 + log_softmax, grid 32 ----------------
__global__ __launch_bounds__(256) void head1_kernel(
    const float* __restrict__ w1, const float* __restrict__ b1,
    const float* __restrict__ w2, const float* __restrict__ b2,
    float* __restrict__ out)
{
    __shared__ float sh0[512], sh1[256], sl[40], red[2];
    int b = blockIdx.x, tid = threadIdx.x;
    for (int c = tid; c < 512; c += 256) sh0[c] = g_h0[b*512 + c];
    __syncthreads();
    {
        float a0 = 0.f, a1 = 0.f;
        for (int c = 0; c < 512; c += 2) {
            a0 = fmaf(sh0[c],   w1[(size_t)c*256 + tid],     a0);
            a1 = fmaf(sh0[c+1], w1[(size_t)(c+1)*256 + tid], a1);
        }
        sh1[tid] = fmaxf(a0 + a1 + b1[tid], 0.f);
    }
    __syncthreads();
    if (tid < 40) {
        float a = b2[tid];
        for (int c = 0; c < 256; c++) a += sh1[c] * w2[c*40 + tid];
        sl[tid] = a;
    }
    __syncthreads();
    if (tid == 0) {
        float mxv = -3.4e38f;
        for (int t = 0; t < 40; t++) mxv = fmaxf(mxv, sl[t]);
        float s = 0.f;
        for (int t = 0; t < 40; t++) s += expf(sl[t] - mxv);
        red[0] = mxv; red[1] = logf(s);
    }
    __syncthreads();
    if (tid < 40) out[b*40 + tid] = sl[tid] - red[0] - red[1];
}

// ---------------- launch ----------------
extern "C" void kernel_launch(void* const* d_in, const int* in_sizes, int n_in,
                              void* d_out, int out_size)
{
    const float* pos   = (const float*)d_in[0];
    const float* c1_w0 = (const float*)d_in[2];
    const float* c1_b0 = (const float*)d_in[3];
    const float* c1_w1 = (const float*)d_in[4];
    const float* c1_b1 = (const float*)d_in[5];
    const float* c1_w2 = (const float*)d_in[6];
    const float* c1_b2 = (const float*)d_in[7];
    const float* c2_w0 = (const float*)d_in[8];
    const float* c2_b0 = (const float*)d_in[9];
    const float* l1_w  = (const float*)d_in[10];
    const float* l1_b  = (const float*)d_in[11];
    const float* m_w0  = (const float*)d_in[12];
    const float* m_b0  = (const float*)d_in[13];
    const float* m_w1  = (const float*)d_in[14];
    const float* m_b1  = (const float*)d_in[15];
    const float* m_w2  = (const float*)d_in[16];
    const float* m_b2  = (const float*)d_in[17];
    float* out = (float*)d_out;

    const int smem_kpos  = 4096*4 + 5120*4 + 5120*4;                                     // 57344
    const int smem_conv1 = (576 + 4608 + 4608 + 192 + 160*C1_LDD) * 4;                   // 83456
    const int smem_knn2  = (128*KF_LDA + 64*KF_LDA + 128*KF_LDA + 128 + 64) * 4;         // 87808
    const int smem_conv2 = (64*C2_LDW + 160*C2_LDD + 8*68 + 8*C2_LDB + 128 + 320) * 4;   // ~86.5 KB

    cudaFuncSetAttribute(knn_pos_kernel,  cudaFuncAttributeMaxDynamicSharedMemorySize, smem_kpos);
    cudaFuncSetAttribute(conv1_kernel,    cudaFuncAttributeMaxDynamicSharedMemorySize, smem_conv1);
    cudaFuncSetAttribute(knn_feat_kernel, cudaFuncAttributeMaxDynamicSharedMemorySize, smem_knn2);
    cudaFuncSetAttribute(conv2_kernel,    cudaFuncAttributeMaxDynamicSharedMemorySize, smem_conv2);

    knn_pos_kernel<<<dim3(4, 32), 512, smem_kpos>>>(pos);
    conv1_kernel<<<296, 256, smem_conv1>>>(pos, c1_w0, c1_b0, c1_w1, c1_b1, c1_w2, c1_b2);
    knn_feat_kernel<<<dim3(8, 32), 256, smem_knn2>>>();
    conv2_kernel<<<296, 256, smem_conv2>>>(c2_w0, c2_b0);
    l1max_kernel<<<dim3(8, 8, 32), 256>>>(l1_w, l1_b);
    head0_kernel<<<dim3(2, 32), 256>>>(m_w0, m_b0);
    head1_kernel<<<32, 256>>>(m_w1, m_b1, m_w2, m_b2, out);
}

// round 11
// speedup vs baseline: 19.1277x; 1.0352x over previous
#include <cuda_runtime.h>
#include <math.h>
#include <stdint.h>

#define BB 32
#define PP 1024
#define KNN 20
#define NPTS (BB*PP)

// ---------------- scratch (device globals; no allocs allowed) ----------------
__device__ __align__(16) float g_x1[NPTS*64];
__device__ __align__(16) float g_x2[NPTS*128];
__device__ int g_idx[NPTS*KNN];
__device__ unsigned int g_pool[BB*1024];
__device__ __align__(16) float g_h0[BB*512];
__device__ __align__(16) float g_w01[8*64];
__device__ __align__(16) float g_b01[64];

// ---------------- tf32 mma helpers ----------------
__device__ __forceinline__ uint32_t f2tf(float x) {
    uint32_t r; asm("cvt.rna.tf32.f32 %0, %1;" : "=r"(r) : "f"(x)); return r;
}
__device__ __forceinline__ float tfbits(float x) {
    return __uint_as_float(f2tf(x));
}
__device__ __forceinline__ void mma8(float& c0, float& c1, float& c2, float& c3,
                                     uint32_t a0, uint32_t a1, uint32_t a2, uint32_t a3,
                                     uint32_t b0, uint32_t b1)
{
    asm volatile("mma.sync.aligned.m16n8k8.row.col.f32.tf32.tf32.f32 "
                 "{%0,%1,%2,%3},{%4,%5,%6,%7},{%8,%9},{%0,%1,%2,%3};"
                 : "+f"(c0), "+f"(c1), "+f"(c2), "+f"(c3)
                 : "r"(a0), "r"(a1), "r"(a2), "r"(a3), "r"(b0), "r"(b1));
}

// top-k insertion (strict <, keeps earliest index on ties — matches jax top_k)
__device__ __forceinline__ void topk_insert(float* bd, int* bi, float d, int j)
{
    if (d < bd[KNN-1]) {
        bd[KNN-1] = d; bi[KNN-1] = j;
#pragma unroll
        for (int t = KNN-1; t > 0; t--) {
            if (bd[t] < bd[t-1]) {
                float td = bd[t]; bd[t] = bd[t-1]; bd[t-1] = td;
                int ti = bi[t]; bi[t] = bi[t-1]; bi[t-1] = ti;
            }
        }
    }
}

// 5 m-tiles x 2 n-tiles warp GEMM (used by conv1)
__device__ __forceinline__ void mma_5x2(
    const float* sD, const float* sW, float acc[5][2][4],
    int mB, int nB, int g4, int tig, int ksteps, int ldd, int ldw)
{
#pragma unroll
    for (int mi = 0; mi < 5; mi++)
#pragma unroll
        for (int ni = 0; ni < 2; ni++)
#pragma unroll
            for (int c = 0; c < 4; c++) acc[mi][ni][c] = 0.f;
#pragma unroll 1
    for (int ks = 0; ks < ksteps; ks++) {
        int k0 = ks * 8;
        uint32_t A[5][4];
#pragma unroll
        for (int mi = 0; mi < 5; mi++) {
            int row = mB + mi*16 + g4;
            A[mi][0] = __float_as_uint(sD[row*ldd + k0 + tig]);
            A[mi][1] = __float_as_uint(sD[(row+8)*ldd + k0 + tig]);
            A[mi][2] = __float_as_uint(sD[row*ldd + k0 + tig + 4]);
            A[mi][3] = __float_as_uint(sD[(row+8)*ldd + k0 + tig + 4]);
        }
        uint32_t Bf[2][2];
#pragma unroll
        for (int ni = 0; ni < 2; ni++) {
            int col = nB + ni*8 + g4;
            Bf[ni][0] = __float_as_uint(sW[(k0+tig)*ldw + col]);
            Bf[ni][1] = __float_as_uint(sW[(k0+tig+4)*ldw + col]);
        }
#pragma unroll
        for (int mi = 0; mi < 5; mi++)
#pragma unroll
            for (int ni = 0; ni < 2; ni++)
                mma8(acc[mi][ni][0], acc[mi][ni][1], acc[mi][ni][2], acc[mi][ni][3],
                     A[mi][0], A[mi][1], A[mi][2], A[mi][3], Bf[ni][0], Bf[ni][1]);
    }
}

__device__ __forceinline__ void wb_5x2(
    float* sD, float acc[5][2][4], const float* bias,
    int mB, int nB, int g4, int tig, int ldd, int mode)
{
#pragma unroll
    for (int mi = 0; mi < 5; mi++) {
#pragma unroll
        for (int ni = 0; ni < 2; ni++) {
            int row = mB + mi*16 + g4, col = nB + ni*8 + tig*2;
            float v0 = acc[mi][ni][0], v1 = acc[mi][ni][1];
            float v2 = acc[mi][ni][2], v3 = acc[mi][ni][3];
            float ba = bias[col], bb = bias[col+1];
            v0 += ba; v1 += bb; v2 += ba; v3 += bb;
            if (mode == 1) {
                v0 = fmaxf(v0, 0.f); v1 = fmaxf(v1, 0.f);
                v2 = fmaxf(v2, 0.f); v3 = fmaxf(v3, 0.f);
            }
            v0 = tfbits(v0); v1 = tfbits(v1); v2 = tfbits(v2); v3 = tfbits(v3);
            sD[row*ldd + col] = v0;     sD[row*ldd + col + 1] = v1;
            sD[(row+8)*ldd + col] = v2; sD[(row+8)*ldd + col + 1] = v3;
        }
    }
}

// ---------------- prologue: W01 = W0 @ W1, b01 = b0 @ W1 + b1 (exact fp32) ----------------
__global__ __launch_bounds__(512) void fuse_w01_kernel(
    const float* __restrict__ w0, const float* __restrict__ b0,
    const float* __restrict__ w1, const float* __restrict__ b1)
{
    int tid = threadIdx.x;
    if (tid < 384) {
        int c = tid >> 6, o = tid & 63;
        float s = 0.f;
        for (int h = 0; h < 64; h++) s = fmaf(w0[c*64 + h], w1[h*64 + o], s);
        g_w01[c*64 + o] = s;
    } else if (tid < 448) {
        int o = tid - 384;
        float s = b1[o];
        for (int h = 0; h < 64; h++) s = fmaf(b0[h], w1[h*64 + o], s);
        g_b01[o] = s;
    }
}

// ---------------- KNN over 3-D positions: split-scan (2 threads/point) + pool zero ----------------
__global__ __launch_bounds__(512) void knn_pos_kernel(const float* __restrict__ pos)
{
    extern __shared__ float smk[];
    float4* spos = (float4*)smk;                     // 1024 float4
    float*  sbd  = smk + 4096;                       // 256*20
    int*    sbi  = (int*)(smk + 4096 + 5120);        // 256*20
    int tid = threadIdx.x;
    int lb = blockIdx.y*4 + blockIdx.x;
    if (tid < 256) g_pool[lb*256 + tid] = 0u;
    int b = blockIdx.y;
    const float* p = pos + (size_t)b * PP * 3;
    for (int j = tid; j < PP; j += 512) {
        float x = p[3*j], y = p[3*j+1], z = p[3*j+2];
        spos[j] = make_float4(x, y, z, x*x + y*y + z*z);
    }
    __syncthreads();
    int pt = tid & 255, s = tid >> 8;        // scanner s ∈ {0,1}
    int il = blockIdx.x * 256 + pt;
    float4 me = spos[il];
    float xi = me.x, yi = me.y, zi = me.z, sqi = me.w;
    float bd[KNN]; int bi[KNN];
#pragma unroll
    for (int t = 0; t < KNN; t++) { bd[t] = 3.4e38f; bi[t] = 0; }
    int j4base = s * 128;
    for (int j4 = j4base; j4 < j4base + 128; j4++) {
        float4 v0 = spos[4*j4+0], v1 = spos[4*j4+1], v2 = spos[4*j4+2], v3 = spos[4*j4+3];
        float d0 = sqi + v0.w - 2.0f*(xi*v0.x + yi*v0.y + zi*v0.z);
        float d1 = sqi + v1.w - 2.0f*(xi*v1.x + yi*v1.y + zi*v1.z);
        float d2 = sqi + v2.w - 2.0f*(xi*v2.x + yi*v2.y + zi*v2.z);
        float d3 = sqi + v3.w - 2.0f*(xi*v3.x + yi*v3.y + zi*v3.z);
        float mn = fminf(fminf(d0, d1), fminf(d2, d3));
        if (mn < bd[KNN-1]) {
            topk_insert(bd, bi, d0, 4*j4+0);
            topk_insert(bd, bi, d1, 4*j4+1);
            topk_insert(bd, bi, d2, 4*j4+2);
            topk_insert(bd, bi, d3, 4*j4+3);
        }
    }
    if (s == 1) {
#pragma unroll
        for (int t = 0; t < KNN; t++) { sbd[pt*KNN + t] = bd[t]; sbi[pt*KNN + t] = bi[t]; }
    }
    __syncthreads();
    if (s == 0) {
        for (int t = 0; t < KNN; t++) {
            float d = sbd[pt*KNN + t];
            if (!(d < bd[KNN-1])) break;
            topk_insert(bd, bi, d, sbi[pt*KNN + t]);
        }
        int gi = b * PP + il;
#pragma unroll
        for (int t = 0; t < KNN; t++) g_idx[gi*KNN + t] = b * PP + bi[t];
    }
}

// ---------------- EdgeConv1 v2: fused W01 (layer0+1 collapsed), persistent ----------------
#define C1_LDD 68
#define C1_LDW 72
__global__ __launch_bounds__(256, 2) void conv1_kernel(
    const float* __restrict__ pos,
    const float* __restrict__ w2, const float* __restrict__ b2)
{
    extern __shared__ float sm[];
    float* sW01 = sm;             // 8*72
    float* sW2  = sm + 576;       // 64*72
    float* sb01 = sm + 5184;      // 64
    float* sb2  = sm + 5248;      // 64
    float* sD   = sm + 5312;      // 160*68

    int tid = threadIdx.x, lane = tid & 31, warp = tid >> 5;
    int g4 = lane >> 2, tig = lane & 3;
    int wm = warp >> 2, wn = warp & 3;
    int mB = wm * 80, nB = wn * 16;

    for (int fi = tid; fi < 512; fi += 256) {
        int kk = fi >> 6, o = fi & 63;
        sW01[kk*C1_LDW + o] = (kk < 6) ? tfbits(g_w01[kk*64 + o]) : 0.f;
    }
    for (int fi = tid; fi < 4096; fi += 256) {
        int kk = fi >> 6, o = fi & 63;
        sW2[kk*C1_LDW + o] = tfbits(w2[fi]);
    }
    if (tid < 64) { sb01[tid] = g_b01[tid]; sb2[tid] = b2[tid]; }

    float acc[5][2][4];
    for (int g = blockIdx.x; g < 4096; g += gridDim.x) {
        int ibase = g * 8;
        __syncthreads();
        if (tid < 160) {
            int p = tid / 20, e = tid - p*20;
            int i = ibase + p;
            int j = g_idx[i*KNN + e];
            float xx = pos[i*3], xy = pos[i*3+1], xz = pos[i*3+2];
            float jx = pos[j*3], jy = pos[j*3+1], jz = pos[j*3+2];
            float* dr = sD + tid*C1_LDD;
            dr[0] = tfbits(xx); dr[1] = tfbits(xy); dr[2] = tfbits(xz);
            dr[3] = tfbits(jx-xx); dr[4] = tfbits(jy-xy); dr[5] = tfbits(jz-xz);
            dr[6] = 0.f; dr[7] = 0.f;
        }
        __syncthreads();
        // fused layer01: h1 = relu(E @ W01 + b01), single k-step
        mma_5x2(sD, sW01, acc, mB, nB, g4, tig, 1, C1_LDD, C1_LDW);
        __syncthreads();
        wb_5x2(sD, acc, sb01, mB, nB, g4, tig, C1_LDD, 1);
        __syncthreads();
        // layer2: h2 = h1 @ W2 (bias/relu in epilogue)
        mma_5x2(sD, sW2, acc, mB, nB, g4, tig, 8, C1_LDD, C1_LDW);
        // register epilogue: per-point max over edges (rows mB..mB+79 = 4 points)
        {
            float pm[4][2][2];
#pragma unroll
            for (int p = 0; p < 4; p++)
#pragma unroll
                for (int ni = 0; ni < 2; ni++) { pm[p][ni][0] = -3.4e38f; pm[p][ni][1] = -3.4e38f; }
            bool hi = (g4 >= 4);
#pragma unroll
            for (int ni = 0; ni < 2; ni++) {
                pm[0][ni][0] = fmaxf(pm[0][ni][0], acc[0][ni][0]);
                pm[0][ni][1] = fmaxf(pm[0][ni][1], acc[0][ni][1]);
                if (!hi) { pm[0][ni][0] = fmaxf(pm[0][ni][0], acc[1][ni][0]);
                           pm[0][ni][1] = fmaxf(pm[0][ni][1], acc[1][ni][1]); }
                else     { pm[1][ni][0] = fmaxf(pm[1][ni][0], acc[1][ni][0]);
                           pm[1][ni][1] = fmaxf(pm[1][ni][1], acc[1][ni][1]); }
                pm[1][ni][0] = fmaxf(pm[1][ni][0], acc[2][ni][0]);
                pm[1][ni][1] = fmaxf(pm[1][ni][1], acc[2][ni][1]);
                pm[2][ni][0] = fmaxf(pm[2][ni][0], acc[3][ni][0]);
                pm[2][ni][1] = fmaxf(pm[2][ni][1], acc[3][ni][1]);
                pm[3][ni][0] = fmaxf(pm[3][ni][0], acc[4][ni][0]);
                pm[3][ni][1] = fmaxf(pm[3][ni][1], acc[4][ni][1]);
                pm[0][ni][0] = fmaxf(pm[0][ni][0], acc[0][ni][2]);
                pm[0][ni][1] = fmaxf(pm[0][ni][1], acc[0][ni][3]);
                pm[1][ni][0] = fmaxf(pm[1][ni][0], acc[1][ni][2]);
                pm[1][ni][1] = fmaxf(pm[1][ni][1], acc[1][ni][3]);
                pm[2][ni][0] = fmaxf(pm[2][ni][0], acc[2][ni][2]);
                pm[2][ni][1] = fmaxf(pm[2][ni][1], acc[2][ni][3]);
                if (!hi) { pm[2][ni][0] = fmaxf(pm[2][ni][0], acc[3][ni][2]);
                           pm[2][ni][1] = fmaxf(pm[2][ni][1], acc[3][ni][3]); }
                else     { pm[3][ni][0] = fmaxf(pm[3][ni][0], acc[3][ni][2]);
                           pm[3][ni][1] = fmaxf(pm[3][ni][1], acc[3][ni][3]); }
                pm[3][ni][0] = fmaxf(pm[3][ni][0], acc[4][ni][2]);
                pm[3][ni][1] = fmaxf(pm[3][ni][1], acc[4][ni][3]);
            }
#pragma unroll
            for (int off = 4; off < 32; off <<= 1)
#pragma unroll
                for (int p = 0; p < 4; p++)
#pragma unroll
                    for (int ni = 0; ni < 2; ni++) {
                        pm[p][ni][0] = fmaxf(pm[p][ni][0], __shfl_xor_sync(0xffffffff, pm[p][ni][0], off));
                        pm[p][ni][1] = fmaxf(pm[p][ni][1], __shfl_xor_sync(0xffffffff, pm[p][ni][1], off));
                    }
            if (g4 == 0) {
#pragma unroll
                for (int p = 0; p < 4; p++) {
                    int wp = wm*4 + p;
#pragma unroll
                    for (int ni = 0; ni < 2; ni++) {
                        int col = nB + ni*8 + tig*2;
                        float2 o;
                        o.x = fmaxf(pm[p][ni][0] + sb2[col],   0.f);
                        o.y = fmaxf(pm[p][ni][1] + sb2[col+1], 0.f);
                        *(float2*)&g_x1[(size_t)(ibase+wp)*64 + col] = o;
                    }
                }
            }
        }
    }
}

// ---------------- KNN over 64-D features v3: 64-wide j-tiles, 2 blocks/SM ----------------
#define KF_LDA 68
__global__ __launch_bounds__(256, 2) void knn_feat_kernel()
{
    extern __shared__ float sm[];
    float* sA   = sm;                        // 128*68  (Xi tf32)
    float* sB   = sA + 128*KF_LDA;           // 64*68   (Xj tf32)
    float* sdot = sB + 64*KF_LDA;            // 128*68
    float* sqi  = sdot + 128*KF_LDA;         // 128
    float* sqj  = sqi + 128;                 // 64

    int tid = threadIdx.x, lane = tid & 31, warp = tid >> 5;
    int g4 = lane >> 2, tig = lane & 3;
    int wm = warp >> 1, wn = warp & 1;       // 4 m-warps x 2 n-warps; tile 32x32
    int b = blockIdx.y;
    int i0 = b*PP + blockIdx.x*128;
    const float4* x1v = (const float4*)g_x1;

    for (int fi = tid; fi < 128*16; fi += 256) {
        int pt = fi >> 4, q = fi & 15;
        float4 v = x1v[(size_t)(i0+pt)*16 + q];
        *(float4*)&sA[pt*KF_LDA + q*4] =
            make_float4(tfbits(v.x), tfbits(v.y), tfbits(v.z), tfbits(v.w));
    }
    if (tid < 128) {
        float s = 0.f;
#pragma unroll
        for (int q = 0; q < 16; q++) {
            float4 v = x1v[(size_t)(i0+tid)*16 + q];
            s += v.x*v.x + v.y*v.y + v.z*v.z + v.w*v.w;
        }
        sqi[tid] = s;
    }

    float bd[KNN]; int bi[KNN];
#pragma unroll
    for (int t = 0; t < KNN; t++) { bd[t] = 3.4e38f; bi[t] = 0; }
    float mysq = 0.f;

    for (int jt = 0; jt < 16; jt++) {
        int j0 = b*PP + jt*64;
        __syncthreads();
#pragma unroll
        for (int r = 0; r < 4; r++) {
            int fi = tid + r*256;
            int pt = fi >> 4, q = fi & 15;
            float4 v = x1v[(size_t)(j0+pt)*16 + q];
            *(float4*)&sB[pt*KF_LDA + q*4] =
                make_float4(tfbits(v.x), tfbits(v.y), tfbits(v.z), tfbits(v.w));
        }
        if (tid < 64) {
            float s = 0.f;
#pragma unroll
            for (int q = 0; q < 16; q++) {
                float4 v = x1v[(size_t)(j0+tid)*16 + q];
                s += v.x*v.x + v.y*v.y + v.z*v.z + v.w*v.w;
            }
            sqj[tid] = s;
        }
        __syncthreads();
        float acc[2][4][4];
#pragma unroll
        for (int mi = 0; mi < 2; mi++)
#pragma unroll
            for (int ni = 0; ni < 4; ni++)
#pragma unroll
                for (int c = 0; c < 4; c++) acc[mi][ni][c] = 0.f;
#pragma unroll
        for (int ks = 0; ks < 8; ks++) {
            int k0 = ks*8;
            uint32_t A[2][4];
#pragma unroll
            for (int mi = 0; mi < 2; mi++) {
                int row = wm*32 + mi*16 + g4;
                A[mi][0] = __float_as_uint(sA[row*KF_LDA + k0 + tig]);
                A[mi][1] = __float_as_uint(sA[(row+8)*KF_LDA + k0 + tig]);
                A[mi][2] = __float_as_uint(sA[row*KF_LDA + k0 + tig + 4]);
                A[mi][3] = __float_as_uint(sA[(row+8)*KF_LDA + k0 + tig + 4]);
            }
            uint32_t Bf[4][2];
#pragma unroll
            for (int ni = 0; ni < 4; ni++) {
                int col = wn*32 + ni*8 + g4;
                Bf[ni][0] = __float_as_uint(sB[col*KF_LDA + k0 + tig]);
                Bf[ni][1] = __float_as_uint(sB[col*KF_LDA + k0 + tig + 4]);
            }
#pragma unroll
            for (int mi = 0; mi < 2; mi++)
#pragma unroll
                for (int ni = 0; ni < 4; ni++)
                    mma8(acc[mi][ni][0], acc[mi][ni][1], acc[mi][ni][2], acc[mi][ni][3],
                         A[mi][0], A[mi][1], A[mi][2], A[mi][3], Bf[ni][0], Bf[ni][1]);
        }
#pragma unroll
        for (int mi = 0; mi < 2; mi++) {
#pragma unroll
            for (int ni = 0; ni < 4; ni++) {
                int row = wm*32 + mi*16 + g4, col = wn*32 + ni*8 + tig*2;
                *(float2*)&sdot[row*KF_LDA + col]     = make_float2(acc[mi][ni][0], acc[mi][ni][1]);
                *(float2*)&sdot[(row+8)*KF_LDA + col] = make_float2(acc[mi][ni][2], acc[mi][ni][3]);
            }
        }
        __syncthreads();
        if (tid < 128) {
            if (jt == 0) mysq = sqi[tid];
            const float4* drow4 = (const float4*)(sdot + tid*KF_LDA);
            const float4* sqj4  = (const float4*)sqj;
            int jbase = jt*64;
#pragma unroll 4
            for (int j4 = 0; j4 < 16; j4++) {
                float4 dv = drow4[j4];
                float4 sv = sqj4[j4];
                float d0 = mysq + sv.x - 2.0f*dv.x;
                float d1 = mysq + sv.y - 2.0f*dv.y;
                float d2 = mysq + sv.z - 2.0f*dv.z;
                float d3 = mysq + sv.w - 2.0f*dv.w;
                float mn = fminf(fminf(d0, d1), fminf(d2, d3));
                if (mn < bd[KNN-1]) {
                    topk_insert(bd, bi, d0, jbase + 4*j4 + 0);
                    topk_insert(bd, bi, d1, jbase + 4*j4 + 1);
                    topk_insert(bd, bi, d2, jbase + 4*j4 + 2);
                    topk_insert(bd, bi, d3, jbase + 4*j4 + 3);
                }
            }
        }
    }
    if (tid < 128) {
        int gi = i0 + tid;
#pragma unroll
        for (int t = 0; t < KNN; t++) g_idx[(size_t)gi*KNN + t] = b*PP + bi[t];
    }
}

// ---------------- EdgeConv2 v6: persistent grid-stride + flat build + coop base + diff GEMM ----------------
#define C2_LDD 68
#define C2_LDW 136
#define C2_LDB 132
__global__ __launch_bounds__(256, 2) void conv2_kernel(
    const float* __restrict__ w, const float* __restrict__ bias)
{
    extern __shared__ float sm[];
    float* sWb   = sm;                        // 64*136 (W rows 64..127, tf32)
    float* sD    = sm + 64*C2_LDW;            // 160*68 diff tf32
    float* sXi   = sD + 160*C2_LDD;           // 8*68 exact fp32
    float* sBase = sXi + 8*68;                // 8*132
    float* sbias = sBase + 8*C2_LDB;          // 128
    int*   sJ    = (int*)(sbias + 128);       // 160
    int*   sP    = sJ + 160;                  // 160

    int tid = threadIdx.x, lane = tid & 31, warp = tid >> 5;
    int g4 = lane >> 2, tig = lane & 3;
    int wm = warp >> 2, wn = warp & 3;
    int mB = wm*80, nB = wn*32;

    for (int fi = tid; fi < 2048; fi += 256) {
        int kk = fi >> 5, nq = fi & 31;
        float4 v = ((const float4*)w)[(64+kk)*32 + nq];
        *(float4*)&sWb[kk*C2_LDW + nq*4] =
            make_float4(tfbits(v.x), tfbits(v.y), tfbits(v.z), tfbits(v.w));
    }
    if (tid < 128) sbias[tid] = bias[tid];

    const float4* x1v = (const float4*)g_x1;

    for (int g = blockIdx.x; g < 4096; g += gridDim.x) {
        int ibase = g * 8;
        __syncthreads();
        if (tid < 128) {
            int p = tid >> 4, q = tid & 15;
            *(float4*)&sXi[p*68 + q*4] = x1v[(size_t)(ibase+p)*16 + q];
        }
        if (tid < 160) {
            int p = tid / 20;
            sJ[tid] = g_idx[(size_t)(ibase+p)*KNN + (tid - p*20)];
            sP[tid] = p;
        }
        __syncthreads();
#pragma unroll
        for (int it = 0; it < 10; it++) {
            int fi = tid + it*256;
            int row = fi >> 4, q = fi & 15;
            int j = sJ[row], p = sP[row];
            float4 xj = x1v[(size_t)j*16 + q];
            float4 xi = *(const float4*)&sXi[p*68 + q*4];
            *(float4*)&sD[row*C2_LDD + q*4] =
                make_float4(tfbits(xj.x-xi.x), tfbits(xj.y-xi.y),
                            tfbits(xj.z-xi.z), tfbits(xj.w-xi.w));
        }
        {
            int p = lane >> 2, c4 = lane & 3;
            int colq = warp*4 + c4;
            const float* xir = &sXi[p*68];
            float4 acc4 = ((const float4*)sbias)[colq];
#pragma unroll 8
            for (int k = 0; k < 64; k++) {
                float xv = xir[k];
                float4 wv = ((const float4*)w)[k*32 + colq];
                acc4.x = fmaf(xv, wv.x, acc4.x); acc4.y = fmaf(xv, wv.y, acc4.y);
                acc4.z = fmaf(xv, wv.z, acc4.z); acc4.w = fmaf(xv, wv.w, acc4.w);
            }
            *(float4*)&sBase[p*C2_LDB + colq*4] = acc4;
        }
        __syncthreads();
        float acc[5][4][4];
#pragma unroll
        for (int mi = 0; mi < 5; mi++)
#pragma unroll
            for (int ni = 0; ni < 4; ni++)
#pragma unroll
                for (int c = 0; c < 4; c++) acc[mi][ni][c] = 0.f;
#pragma unroll 1
        for (int ks = 0; ks < 8; ks++) {
            int k0 = ks*8;
            uint32_t A[5][4];
#pragma unroll
            for (int mi = 0; mi < 5; mi++) {
                int row = mB + mi*16 + g4;
                A[mi][0] = __float_as_uint(sD[row*C2_LDD + k0 + tig]);
                A[mi][1] = __float_as_uint(sD[(row+8)*C2_LDD + k0 + tig]);
                A[mi][2] = __float_as_uint(sD[row*C2_LDD + k0 + tig + 4]);
                A[mi][3] = __float_as_uint(sD[(row+8)*C2_LDD + k0 + tig + 4]);
            }
            uint32_t Bf[4][2];
#pragma unroll
            for (int ni = 0; ni < 4; ni++) {
                int col = nB + ni*8 + g4;
                Bf[ni][0] = __float_as_uint(sWb[(k0+tig)*C2_LDW + col]);
                Bf[ni][1] = __float_as_uint(sWb[(k0+tig+4)*C2_LDW + col]);
            }
#pragma unroll
            for (int mi = 0; mi < 5; mi++)
#pragma unroll
                for (int ni = 0; ni < 4; ni++)
                    mma8(acc[mi][ni][0], acc[mi][ni][1], acc[mi][ni][2], acc[mi][ni][3],
                         A[mi][0], A[mi][1], A[mi][2], A[mi][3], Bf[ni][0], Bf[ni][1]);
        }
        float pm[4][4][2];
#pragma unroll
        for (int p = 0; p < 4; p++)
#pragma unroll
            for (int ni = 0; ni < 4; ni++) { pm[p][ni][0] = -3.4e38f; pm[p][ni][1] = -3.4e38f; }
        bool hi = (g4 >= 4);
#pragma unroll
        for (int ni = 0; ni < 4; ni++) {
            pm[0][ni][0] = fmaxf(pm[0][ni][0], acc[0][ni][0]);
            pm[0][ni][1] = fmaxf(pm[0][ni][1], acc[0][ni][1]);
            if (!hi) { pm[0][ni][0] = fmaxf(pm[0][ni][0], acc[1][ni][0]);
                       pm[0][ni][1] = fmaxf(pm[0][ni][1], acc[1][ni][1]); }
            else     { pm[1][ni][0] = fmaxf(pm[1][ni][0], acc[1][ni][0]);
                       pm[1][ni][1] = fmaxf(pm[1][ni][1], acc[1][ni][1]); }
            pm[1][ni][0] = fmaxf(pm[1][ni][0], acc[2][ni][0]);
            pm[1][ni][1] = fmaxf(pm[1][ni][1], acc[2][ni][1]);
            pm[2][ni][0] = fmaxf(pm[2][ni][0], acc[3][ni][0]);
            pm[2][ni][1] = fmaxf(pm[2][ni][1], acc[3][ni][1]);
            pm[3][ni][0] = fmaxf(pm[3][ni][0], acc[4][ni][0]);
            pm[3][ni][1] = fmaxf(pm[3][ni][1], acc[4][ni][1]);
            pm[0][ni][0] = fmaxf(pm[0][ni][0], acc[0][ni][2]);
            pm[0][ni][1] = fmaxf(pm[0][ni][1], acc[0][ni][3]);
            pm[1][ni][0] = fmaxf(pm[1][ni][0], acc[1][ni][2]);
            pm[1][ni][1] = fmaxf(pm[1][ni][1], acc[1][ni][3]);
            pm[2][ni][0] = fmaxf(pm[2][ni][0], acc[2][ni][2]);
            pm[2][ni][1] = fmaxf(pm[2][ni][1], acc[2][ni][3]);
            if (!hi) { pm[2][ni][0] = fmaxf(pm[2][ni][0], acc[3][ni][2]);
                       pm[2][ni][1] = fmaxf(pm[2][ni][1], acc[3][ni][3]); }
            else     { pm[3][ni][0] = fmaxf(pm[3][ni][0], acc[3][ni][2]);
                       pm[3][ni][1] = fmaxf(pm[3][ni][1], acc[3][ni][3]); }
            pm[3][ni][0] = fmaxf(pm[3][ni][0], acc[4][ni][2]);
            pm[3][ni][1] = fmaxf(pm[3][ni][1], acc[4][ni][3]);
        }
#pragma unroll
        for (int off = 4; off < 32; off <<= 1)
#pragma unroll
            for (int p = 0; p < 4; p++)
#pragma unroll
                for (int ni = 0; ni < 4; ni++) {
                    pm[p][ni][0] = fmaxf(pm[p][ni][0], __shfl_xor_sync(0xffffffff, pm[p][ni][0], off));
                    pm[p][ni][1] = fmaxf(pm[p][ni][1], __shfl_xor_sync(0xffffffff, pm[p][ni][1], off));
                }
        if (g4 == 0) {
#pragma unroll
            for (int p = 0; p < 4; p++) {
                int wp = wm*4 + p;
#pragma unroll
                for (int ni = 0; ni < 4; ni++) {
                    int col = nB + ni*8 + tig*2;
                    float b0v = sBase[wp*C2_LDB + col];
                    float b1v = sBase[wp*C2_LDB + col + 1];
                    float2 o;
                    o.x = fmaxf(pm[p][ni][0] + b0v, 0.f);
                    o.y = fmaxf(pm[p][ni][1] + b1v, 0.f);
                    *(float2*)&g_x2[(size_t)(ibase+wp)*128 + col] = o;
                }
            }
        }
    }
}

// ---------------- l1 (192->1024) tf32 GEMM, k-chunk 32, + fused relu + P-max ----------------
#define L1_LDA 36
__global__ __launch_bounds__(256) void l1max_kernel(
    const float* __restrict__ w, const float* __restrict__ bias)
{
    __shared__ float sA[128*L1_LDA];
    __shared__ float sB[32*136];
    __shared__ float sbias[128];
    __shared__ unsigned int sred[128];
    int tid = threadIdx.x;
    int lane = tid & 31, warp = tid >> 5;
    int g4 = lane >> 2, tig = lane & 3;
    int b = blockIdx.z;
    int n0 = blockIdx.x * 128, m0 = blockIdx.y * 128;
    int pbase = b * PP + m0;
    const float4* x1v = (const float4*)g_x1;
    const float4* x2v = (const float4*)g_x2;
    const float4* wv  = (const float4*)w;
    if (tid < 128) { sred[tid] = 0u; sbias[tid] = bias[n0 + tid]; }

    int wm = warp >> 2, wn = warp & 3;
    float acc[4][4][4];
#pragma unroll
    for (int mi = 0; mi < 4; mi++)
#pragma unroll
        for (int ni = 0; ni < 4; ni++)
#pragma unroll
            for (int c = 0; c < 4; c++) acc[mi][ni][c] = 0.f;

    for (int ks = 0; ks < 6; ks++) {
        __syncthreads();
#pragma unroll
        for (int r = 0; r < 4; r++) {
            int fi = tid + r*256;
            int pt = fi >> 3, kq = fi & 7;
            float4 v = (ks < 2) ? x1v[(size_t)(pbase+pt)*16 + ks*8 + kq]
                                : x2v[(size_t)(pbase+pt)*32 + (ks-2)*8 + kq];
            *(float4*)&sA[pt*L1_LDA + kq*4] =
                make_float4(tfbits(v.x), tfbits(v.y), tfbits(v.z), tfbits(v.w));
        }
#pragma unroll
        for (int r = 0; r < 4; r++) {
            int fi = tid + r*256;
            int kk = fi >> 5, nq = fi & 31;
            float4 v = wv[(size_t)(ks*32+kk)*256 + (n0>>2) + nq];
            *(float4*)&sB[kk*136 + nq*4] =
                make_float4(tfbits(v.x), tfbits(v.y), tfbits(v.z), tfbits(v.w));
        }
        __syncthreads();
#pragma unroll
        for (int kh = 0; kh < 4; kh++) {
            int k0 = kh*8;
            uint32_t A[4][4];
#pragma unroll
            for (int mi = 0; mi < 4; mi++) {
                int row = wm*64 + mi*16 + g4;
                A[mi][0] = __float_as_uint(sA[row*L1_LDA + k0 + tig]);
                A[mi][1] = __float_as_uint(sA[(row+8)*L1_LDA + k0 + tig]);
                A[mi][2] = __float_as_uint(sA[row*L1_LDA + k0 + tig + 4]);
                A[mi][3] = __float_as_uint(sA[(row+8)*L1_LDA + k0 + tig + 4]);
            }
            uint32_t Bf[4][2];
#pragma unroll
            for (int ni = 0; ni < 4; ni++) {
                int col = wn*32 + ni*8 + g4;
                Bf[ni][0] = __float_as_uint(sB[(k0+tig)*136 + col]);
                Bf[ni][1] = __float_as_uint(sB[(k0+tig+4)*136 + col]);
            }
#pragma unroll
            for (int mi = 0; mi < 4; mi++)
#pragma unroll
                for (int ni = 0; ni < 4; ni++)
                    mma8(acc[mi][ni][0], acc[mi][ni][1], acc[mi][ni][2], acc[mi][ni][3],
                         A[mi][0], A[mi][1], A[mi][2], A[mi][3], Bf[ni][0], Bf[ni][1]);
        }
    }
#pragma unroll
    for (int ni = 0; ni < 4; ni++) {
        float v0 = -3.4e38f, v1 = -3.4e38f;
#pragma unroll
        for (int mi = 0; mi < 4; mi++) {
            v0 = fmaxf(v0, fmaxf(acc[mi][ni][0], acc[mi][ni][2]));
            v1 = fmaxf(v1, fmaxf(acc[mi][ni][1], acc[mi][ni][3]));
        }
#pragma unroll
        for (int off = 4; off < 32; off <<= 1) {
            v0 = fmaxf(v0, __shfl_xor_sync(0xffffffff, v0, off));
            v1 = fmaxf(v1, __shfl_xor_sync(0xffffffff, v1, off));
        }
        if (g4 == 0) {
            int col = wn*32 + ni*8 + tig*2;
            float a0 = fmaxf(v0 + sbias[col], 0.f);
            float a1 = fmaxf(v1 + sbias[col+1], 0.f);
            atomicMax(&sred[col],   __float_as_uint(a0));
            atomicMax(&sred[col+1], __float_as_uint(a1));
        }
    }
    __syncthreads();
    if (tid < 128) atomicMax(&g_pool[b*1024 + n0 + tid], sred[tid]);
}

// ---------------- head0: h0 = relu(pool @ m_w0 + b0), grid (2, 32) ----------------
__global__ __launch_bounds__(256) void head0_kernel(
    const float* __restrict__ w0, const float* __restrict__ b0)
{
    __shared__ float sp[1024];
    int b = blockIdx.y, tid = threadIdx.x;
    int o = blockIdx.x * 256 + tid;
    for (int c = tid; c < 1024; c += 256) sp[c] = __uint_as_float(g_pool[b*1024 + c]);
    __syncthreads();
    float a0 = 0.f, a1 = 0.f, a2 = 0.f, a3 = 0.f;
    for (int c = 0; c < 1024; c += 4) {
        a0 = fmaf(sp[c+0], w0[(size_t)(c+0)*512 + o], a0);
        a1 = fmaf(sp[c+1], w0[(size_t)(c+1)*512 + o], a1);
        a2 = fmaf(sp[c+2], w0[(size_t)(c+2)*512 + o], a2);
        a3 = fmaf(sp[c+3], w0[(size_t)(c+3)*512 + o], a3);
    }
    g_h0[b*512 + o] = fmaxf(((a0 + a1) + (a2 + a3)) + b0[o], 0.f);
}

// ---------------- head1: 512->256 relu ->40 + log_softmax, grid 32 ----------------
__global__ __launch_bounds__(256) void head1_kernel(
    const float* __restrict__ w1, const float* __restrict__ b1,
    const float* __restrict__ w2, const float* __restrict__ b2,
    float* __restrict__ out)
{
    __shared__ float sh0[512], sh1[256], sl[40], red[2];
    int b = blockIdx.x, tid = threadIdx.x;
    for (int c = tid; c < 512; c += 256) sh0[c] = g_h0[b*512 + c];
    __syncthreads();
    {
        float a0 = 0.f, a1 = 0.f;
        for (int c = 0; c < 512; c += 2) {
            a0 = fmaf(sh0[c],   w1[(size_t)c*256 + tid],     a0);
            a1 = fmaf(sh0[c+1], w1[(size_t)(c+1)*256 + tid], a1);
        }
        sh1[tid] = fmaxf(a0 + a1 + b1[tid], 0.f);
    }
    __syncthreads();
    if (tid < 40) {
        float a = b2[tid];
        for (int c = 0; c < 256; c++) a += sh1[c] * w2[c*40 + tid];
        sl[tid] = a;
    }
    __syncthreads();
    if (tid == 0) {
        float mxv = -3.4e38f;
        for (int t = 0; t < 40; t++) mxv = fmaxf(mxv, sl[t]);
        float s = 0.f;
        for (int t = 0; t < 40; t++) s += expf(sl[t] - mxv);
        red[0] = mxv; red[1] = logf(s);
    }
    __syncthreads();
    if (tid < 40) out[b*40 + tid] = sl[tid] - red[0] - red[1];
}

// ---------------- launch ----------------
extern "C" void kernel_launch(void* const* d_in, const int* in_sizes, int n_in,
                              void* d_out, int out_size)
{
    const float* pos   = (const float*)d_in[0];
    const float* c1_w0 = (const float*)d_in[2];
    const float* c1_b0 = (const float*)d_in[3];
    const float* c1_w1 = (const float*)d_in[4];
    const float* c1_b1 = (const float*)d_in[5];
    const float* c1_w2 = (const float*)d_in[6];
    const float* c1_b2 = (const float*)d_in[7];
    const float* c2_w0 = (const float*)d_in[8];
    const float* c2_b0 = (const float*)d_in[9];
    const float* l1_w  = (const float*)d_in[10];
    const float* l1_b  = (const float*)d_in[11];
    const float* m_w0  = (const float*)d_in[12];
    const float* m_b0  = (const float*)d_in[13];
    const float* m_w1  = (const float*)d_in[14];
    const float* m_b1  = (const float*)d_in[15];
    const float* m_w2  = (const float*)d_in[16];
    const float* m_b2  = (const float*)d_in[17];
    float* out = (float*)d_out;

    const int smem_kpos  = 4096*4 + 5120*4 + 5120*4;                                     // 57344
    const int smem_conv1 = (576 + 4608 + 128 + 160*C1_LDD) * 4;                          // 64768
    const int smem_knn2  = (128*KF_LDA + 64*KF_LDA + 128*KF_LDA + 128 + 64) * 4;         // 87808
    const int smem_conv2 = (64*C2_LDW + 160*C2_LDD + 8*68 + 8*C2_LDB + 128 + 320) * 4;   // ~86.5 KB

    cudaFuncSetAttribute(knn_pos_kernel,  cudaFuncAttributeMaxDynamicSharedMemorySize, smem_kpos);
    cudaFuncSetAttribute(conv1_kernel,    cudaFuncAttributeMaxDynamicSharedMemorySize, smem_conv1);
    cudaFuncSetAttribute(knn_feat_kernel, cudaFuncAttributeMaxDynamicSharedMemorySize, smem_knn2);
    cudaFuncSetAttribute(conv2_kernel,    cudaFuncAttributeMaxDynamicSharedMemorySize, smem_conv2);

    fuse_w01_kernel<<<1, 512>>>(c1_w0, c1_b0, c1_w1, c1_b1);
    knn_pos_kernel<<<dim3(4, 32), 512, smem_kpos>>>(pos);
    conv1_kernel<<<296, 256, smem_conv1>>>(pos, c1_w2, c1_b2);
    knn_feat_kernel<<<dim3(8, 32), 256, smem_knn2>>>();
    conv2_kernel<<<296, 256, smem_conv2>>>(c2_w0, c2_b0);
    l1max_kernel<<<dim3(8, 8, 32), 256>>>(l1_w, l1_b);
    head0_kernel<<<dim3(2, 32), 256>>>(m_w0, m_b0);
    head1_kernel<<<32, 256>>>(m_w1, m_b1, m_w2, m_b2, out);
}

// round 12
// speedup vs baseline: 21.4162x; 1.1196x over previous
#include <cuda_runtime.h>
#include <math.h>
#include <stdint.h>

#define BB 32
#define PP 1024
#define KNN 20
#define NPTS (BB*PP)

// ---------------- scratch (device globals; no allocs allowed) ----------------
__device__ __align__(16) float g_x1[NPTS*64];
__device__ __align__(16) float g_x2[NPTS*128];
__device__ int g_idx[NPTS*KNN];
__device__ unsigned int g_pool[BB*1024];
__device__ __align__(16) float g_h0[BB*512];
__device__ __align__(16) float g_w01[8*64];
__device__ __align__(16) float g_b01[64];

// ---------------- tf32 mma helpers ----------------
__device__ __forceinline__ uint32_t f2tf(float x) {
    uint32_t r; asm("cvt.rna.tf32.f32 %0, %1;" : "=r"(r) : "f"(x)); return r;
}
__device__ __forceinline__ float tfbits(float x) {
    return __uint_as_float(f2tf(x));
}
__device__ __forceinline__ void mma8(float& c0, float& c1, float& c2, float& c3,
                                     uint32_t a0, uint32_t a1, uint32_t a2, uint32_t a3,
                                     uint32_t b0, uint32_t b1)
{
    asm volatile("mma.sync.aligned.m16n8k8.row.col.f32.tf32.tf32.f32 "
                 "{%0,%1,%2,%3},{%4,%5,%6,%7},{%8,%9},{%0,%1,%2,%3};"
                 : "+f"(c0), "+f"(c1), "+f"(c2), "+f"(c3)
                 : "r"(a0), "r"(a1), "r"(a2), "r"(a3), "r"(b0), "r"(b1));
}

// top-k insertion (strict <, keeps earliest index on ties — matches jax top_k)
__device__ __forceinline__ void topk_insert(float* bd, int* bi, float d, int j)
{
    if (d < bd[KNN-1]) {
        bd[KNN-1] = d; bi[KNN-1] = j;
#pragma unroll
        for (int t = KNN-1; t > 0; t--) {
            if (bd[t] < bd[t-1]) {
                float td = bd[t]; bd[t] = bd[t-1]; bd[t-1] = td;
                int ti = bi[t]; bi[t] = bi[t-1]; bi[t-1] = ti;
            }
        }
    }
}

// 5 m-tiles x 2 n-tiles warp GEMM (used by conv1)
__device__ __forceinline__ void mma_5x2(
    const float* sD, const float* sW, float acc[5][2][4],
    int mB, int nB, int g4, int tig, int ksteps, int ldd, int ldw)
{
#pragma unroll
    for (int mi = 0; mi < 5; mi++)
#pragma unroll
        for (int ni = 0; ni < 2; ni++)
#pragma unroll
            for (int c = 0; c < 4; c++) acc[mi][ni][c] = 0.f;
#pragma unroll 1
    for (int ks = 0; ks < ksteps; ks++) {
        int k0 = ks * 8;
        uint32_t A[5][4];
#pragma unroll
        for (int mi = 0; mi < 5; mi++) {
            int row = mB + mi*16 + g4;
            A[mi][0] = __float_as_uint(sD[row*ldd + k0 + tig]);
            A[mi][1] = __float_as_uint(sD[(row+8)*ldd + k0 + tig]);
            A[mi][2] = __float_as_uint(sD[row*ldd + k0 + tig + 4]);
            A[mi][3] = __float_as_uint(sD[(row+8)*ldd + k0 + tig + 4]);
        }
        uint32_t Bf[2][2];
#pragma unroll
        for (int ni = 0; ni < 2; ni++) {
            int col = nB + ni*8 + g4;
            Bf[ni][0] = __float_as_uint(sW[(k0+tig)*ldw + col]);
            Bf[ni][1] = __float_as_uint(sW[(k0+tig+4)*ldw + col]);
        }
#pragma unroll
        for (int mi = 0; mi < 5; mi++)
#pragma unroll
            for (int ni = 0; ni < 2; ni++)
                mma8(acc[mi][ni][0], acc[mi][ni][1], acc[mi][ni][2], acc[mi][ni][3],
                     A[mi][0], A[mi][1], A[mi][2], A[mi][3], Bf[ni][0], Bf[ni][1]);
    }
}

__device__ __forceinline__ void wb_5x2(
    float* sD, float acc[5][2][4], const float* bias,
    int mB, int nB, int g4, int tig, int ldd, int mode)
{
#pragma unroll
    for (int mi = 0; mi < 5; mi++) {
#pragma unroll
        for (int ni = 0; ni < 2; ni++) {
            int row = mB + mi*16 + g4, col = nB + ni*8 + tig*2;
            float v0 = acc[mi][ni][0], v1 = acc[mi][ni][1];
            float v2 = acc[mi][ni][2], v3 = acc[mi][ni][3];
            float ba = bias[col], bb = bias[col+1];
            v0 += ba; v1 += bb; v2 += ba; v3 += bb;
            if (mode == 1) {
                v0 = fmaxf(v0, 0.f); v1 = fmaxf(v1, 0.f);
                v2 = fmaxf(v2, 0.f); v3 = fmaxf(v3, 0.f);
            }
            v0 = tfbits(v0); v1 = tfbits(v1); v2 = tfbits(v2); v3 = tfbits(v3);
            sD[row*ldd + col] = v0;     sD[row*ldd + col + 1] = v1;
            sD[(row+8)*ldd + col] = v2; sD[(row+8)*ldd + col + 1] = v3;
        }
    }
}

// ---------------- prologue: W01 = W0 @ W1, b01 = b0 @ W1 + b1 (exact fp32) ----------------
__global__ __launch_bounds__(512) void fuse_w01_kernel(
    const float* __restrict__ w0, const float* __restrict__ b0,
    const float* __restrict__ w1, const float* __restrict__ b1)
{
    int tid = threadIdx.x;
    if (tid < 384) {
        int c = tid >> 6, o = tid & 63;
        float s = 0.f;
        for (int h = 0; h < 64; h++) s = fmaf(w0[c*64 + h], w1[h*64 + o], s);
        g_w01[c*64 + o] = s;
    } else if (tid < 448) {
        int o = tid - 384;
        float s = b1[o];
        for (int h = 0; h < 64; h++) s = fmaf(b0[h], w1[h*64 + o], s);
        g_b01[o] = s;
    }
}

// ---------------- KNN over 3-D positions: split-scan (2 threads/point) + pool zero ----------------
__global__ __launch_bounds__(512) void knn_pos_kernel(const float* __restrict__ pos)
{
    extern __shared__ float smk[];
    float4* spos = (float4*)smk;                     // 1024 float4
    float*  sbd  = smk + 4096;                       // 256*20
    int*    sbi  = (int*)(smk + 4096 + 5120);        // 256*20
    int tid = threadIdx.x;
    int lb = blockIdx.y*4 + blockIdx.x;
    if (tid < 256) g_pool[lb*256 + tid] = 0u;
    int b = blockIdx.y;
    const float* p = pos + (size_t)b * PP * 3;
    for (int j = tid; j < PP; j += 512) {
        float x = p[3*j], y = p[3*j+1], z = p[3*j+2];
        spos[j] = make_float4(x, y, z, x*x + y*y + z*z);
    }
    __syncthreads();
    int pt = tid & 255, s = tid >> 8;
    int il = blockIdx.x * 256 + pt;
    float4 me = spos[il];
    float xi = me.x, yi = me.y, zi = me.z, sqi = me.w;
    float bd[KNN]; int bi[KNN];
#pragma unroll
    for (int t = 0; t < KNN; t++) { bd[t] = 3.4e38f; bi[t] = 0; }
    int j4base = s * 128;
    for (int j4 = j4base; j4 < j4base + 128; j4++) {
        float4 v0 = spos[4*j4+0], v1 = spos[4*j4+1], v2 = spos[4*j4+2], v3 = spos[4*j4+3];
        float d0 = sqi + v0.w - 2.0f*(xi*v0.x + yi*v0.y + zi*v0.z);
        float d1 = sqi + v1.w - 2.0f*(xi*v1.x + yi*v1.y + zi*v1.z);
        float d2 = sqi + v2.w - 2.0f*(xi*v2.x + yi*v2.y + zi*v2.z);
        float d3 = sqi + v3.w - 2.0f*(xi*v3.x + yi*v3.y + zi*v3.z);
        float mn = fminf(fminf(d0, d1), fminf(d2, d3));
        if (mn < bd[KNN-1]) {
            topk_insert(bd, bi, d0, 4*j4+0);
            topk_insert(bd, bi, d1, 4*j4+1);
            topk_insert(bd, bi, d2, 4*j4+2);
            topk_insert(bd, bi, d3, 4*j4+3);
        }
    }
    if (s == 1) {
#pragma unroll
        for (int t = 0; t < KNN; t++) { sbd[pt*KNN + t] = bd[t]; sbi[pt*KNN + t] = bi[t]; }
    }
    __syncthreads();
    if (s == 0) {
        for (int t = 0; t < KNN; t++) {
            float d = sbd[pt*KNN + t];
            if (!(d < bd[KNN-1])) break;
            topk_insert(bd, bi, d, sbi[pt*KNN + t]);
        }
        int gi = b * PP + il;
#pragma unroll
        for (int t = 0; t < KNN; t++) g_idx[gi*KNN + t] = b * PP + bi[t];
    }
}

// ---------------- EdgeConv1 v2: fused W01, persistent ----------------
#define C1_LDD 68
#define C1_LDW 72
__global__ __launch_bounds__(256, 2) void conv1_kernel(
    const float* __restrict__ pos,
    const float* __restrict__ w2, const float* __restrict__ b2)
{
    extern __shared__ float sm[];
    float* sW01 = sm;             // 8*72
    float* sW2  = sm + 576;       // 64*72
    float* sb01 = sm + 5184;      // 64
    float* sb2  = sm + 5248;      // 64
    float* sD   = sm + 5312;      // 160*68

    int tid = threadIdx.x, lane = tid & 31, warp = tid >> 5;
    int g4 = lane >> 2, tig = lane & 3;
    int wm = warp >> 2, wn = warp & 3;
    int mB = wm * 80, nB = wn * 16;

    for (int fi = tid; fi < 512; fi += 256) {
        int kk = fi >> 6, o = fi & 63;
        sW01[kk*C1_LDW + o] = (kk < 6) ? tfbits(g_w01[kk*64 + o]) : 0.f;
    }
    for (int fi = tid; fi < 4096; fi += 256) {
        int kk = fi >> 6, o = fi & 63;
        sW2[kk*C1_LDW + o] = tfbits(w2[fi]);
    }
    if (tid < 64) { sb01[tid] = g_b01[tid]; sb2[tid] = b2[tid]; }

    float acc[5][2][4];
    for (int g = blockIdx.x; g < 4096; g += gridDim.x) {
        int ibase = g * 8;
        __syncthreads();
        if (tid < 160) {
            int p = tid / 20, e = tid - p*20;
            int i = ibase + p;
            int j = g_idx[i*KNN + e];
            float xx = pos[i*3], xy = pos[i*3+1], xz = pos[i*3+2];
            float jx = pos[j*3], jy = pos[j*3+1], jz = pos[j*3+2];
            float* dr = sD + tid*C1_LDD;
            dr[0] = tfbits(xx); dr[1] = tfbits(xy); dr[2] = tfbits(xz);
            dr[3] = tfbits(jx-xx); dr[4] = tfbits(jy-xy); dr[5] = tfbits(jz-xz);
            dr[6] = 0.f; dr[7] = 0.f;
        }
        __syncthreads();
        mma_5x2(sD, sW01, acc, mB, nB, g4, tig, 1, C1_LDD, C1_LDW);
        __syncthreads();
        wb_5x2(sD, acc, sb01, mB, nB, g4, tig, C1_LDD, 1);
        __syncthreads();
        mma_5x2(sD, sW2, acc, mB, nB, g4, tig, 8, C1_LDD, C1_LDW);
        {
            float pm[4][2][2];
#pragma unroll
            for (int p = 0; p < 4; p++)
#pragma unroll
                for (int ni = 0; ni < 2; ni++) { pm[p][ni][0] = -3.4e38f; pm[p][ni][1] = -3.4e38f; }
            bool hi = (g4 >= 4);
#pragma unroll
            for (int ni = 0; ni < 2; ni++) {
                pm[0][ni][0] = fmaxf(pm[0][ni][0], acc[0][ni][0]);
                pm[0][ni][1] = fmaxf(pm[0][ni][1], acc[0][ni][1]);
                if (!hi) { pm[0][ni][0] = fmaxf(pm[0][ni][0], acc[1][ni][0]);
                           pm[0][ni][1] = fmaxf(pm[0][ni][1], acc[1][ni][1]); }
                else     { pm[1][ni][0] = fmaxf(pm[1][ni][0], acc[1][ni][0]);
                           pm[1][ni][1] = fmaxf(pm[1][ni][1], acc[1][ni][1]); }
                pm[1][ni][0] = fmaxf(pm[1][ni][0], acc[2][ni][0]);
                pm[1][ni][1] = fmaxf(pm[1][ni][1], acc[2][ni][1]);
                pm[2][ni][0] = fmaxf(pm[2][ni][0], acc[3][ni][0]);
                pm[2][ni][1] = fmaxf(pm[2][ni][1], acc[3][ni][1]);
                pm[3][ni][0] = fmaxf(pm[3][ni][0], acc[4][ni][0]);
                pm[3][ni][1] = fmaxf(pm[3][ni][1], acc[4][ni][1]);
                pm[0][ni][0] = fmaxf(pm[0][ni][0], acc[0][ni][2]);
                pm[0][ni][1] = fmaxf(pm[0][ni][1], acc[0][ni][3]);
                pm[1][ni][0] = fmaxf(pm[1][ni][0], acc[1][ni][2]);
                pm[1][ni][1] = fmaxf(pm[1][ni][1], acc[1][ni][3]);
                pm[2][ni][0] = fmaxf(pm[2][ni][0], acc[2][ni][2]);
                pm[2][ni][1] = fmaxf(pm[2][ni][1], acc[2][ni][3]);
                if (!hi) { pm[2][ni][0] = fmaxf(pm[2][ni][0], acc[3][ni][2]);
                           pm[2][ni][1] = fmaxf(pm[2][ni][1], acc[3][ni][3]); }
                else     { pm[3][ni][0] = fmaxf(pm[3][ni][0], acc[3][ni][2]);
                           pm[3][ni][1] = fmaxf(pm[3][ni][1], acc[3][ni][3]); }
                pm[3][ni][0] = fmaxf(pm[3][ni][0], acc[4][ni][2]);
                pm[3][ni][1] = fmaxf(pm[3][ni][1], acc[4][ni][3]);
            }
#pragma unroll
            for (int off = 4; off < 32; off <<= 1)
#pragma unroll
                for (int p = 0; p < 4; p++)
#pragma unroll
                    for (int ni = 0; ni < 2; ni++) {
                        pm[p][ni][0] = fmaxf(pm[p][ni][0], __shfl_xor_sync(0xffffffff, pm[p][ni][0], off));
                        pm[p][ni][1] = fmaxf(pm[p][ni][1], __shfl_xor_sync(0xffffffff, pm[p][ni][1], off));
                    }
            if (g4 == 0) {
#pragma unroll
                for (int p = 0; p < 4; p++) {
                    int wp = wm*4 + p;
#pragma unroll
                    for (int ni = 0; ni < 2; ni++) {
                        int col = nB + ni*8 + tig*2;
                        float2 o;
                        o.x = fmaxf(pm[p][ni][0] + sb2[col],   0.f);
                        o.y = fmaxf(pm[p][ni][1] + sb2[col+1], 0.f);
                        *(float2*)&g_x1[(size_t)(ibase+wp)*64 + col] = o;
                    }
                }
            }
        }
    }
}

// ---------------- KNN over 64-D features v4: split-scan selection (all 256 threads) ----------------
#define KF_LDA 68
__global__ __launch_bounds__(256, 2) void knn_feat_kernel()
{
    extern __shared__ float sm[];
    float* sA   = sm;                        // 128*68  (Xi tf32)
    float* sB   = sA + 128*KF_LDA;           // 64*68   (Xj tf32)
    float* sdot = sB + 64*KF_LDA;            // 128*68
    float* sqi  = sdot + 128*KF_LDA;         // 128
    float* sqj  = sqi + 128;                 // 64
    float* sbd  = sqj + 64;                  // 128*20
    int*   sbi  = (int*)(sbd + 128*KNN);     // 128*20

    int tid = threadIdx.x, lane = tid & 31, warp = tid >> 5;
    int g4 = lane >> 2, tig = lane & 3;
    int wm = warp >> 1, wn = warp & 1;       // 4 m-warps x 2 n-warps; tile 32x32
    int b = blockIdx.y;
    int i0 = b*PP + blockIdx.x*128;
    const float4* x1v = (const float4*)g_x1;

    for (int fi = tid; fi < 128*16; fi += 256) {
        int pt = fi >> 4, q = fi & 15;
        float4 v = x1v[(size_t)(i0+pt)*16 + q];
        *(float4*)&sA[pt*KF_LDA + q*4] =
            make_float4(tfbits(v.x), tfbits(v.y), tfbits(v.z), tfbits(v.w));
    }
    if (tid < 128) {
        float s = 0.f;
#pragma unroll
        for (int q = 0; q < 16; q++) {
            float4 v = x1v[(size_t)(i0+tid)*16 + q];
            s += v.x*v.x + v.y*v.y + v.z*v.z + v.w*v.w;
        }
        sqi[tid] = s;
    }

    int spt = tid & 127, ssc = tid >> 7;     // selection: point, scanner half
    float bd[KNN]; int bi[KNN];
#pragma unroll
    for (int t = 0; t < KNN; t++) { bd[t] = 3.4e38f; bi[t] = 0; }
    float mysq = 0.f;

    for (int jt = 0; jt < 16; jt++) {
        int j0 = b*PP + jt*64;
        __syncthreads();
#pragma unroll
        for (int r = 0; r < 4; r++) {
            int fi = tid + r*256;
            int pt = fi >> 4, q = fi & 15;
            float4 v = x1v[(size_t)(j0+pt)*16 + q];
            *(float4*)&sB[pt*KF_LDA + q*4] =
                make_float4(tfbits(v.x), tfbits(v.y), tfbits(v.z), tfbits(v.w));
        }
        if (tid < 64) {
            float s = 0.f;
#pragma unroll
            for (int q = 0; q < 16; q++) {
                float4 v = x1v[(size_t)(j0+tid)*16 + q];
                s += v.x*v.x + v.y*v.y + v.z*v.z + v.w*v.w;
            }
            sqj[tid] = s;
        }
        __syncthreads();
        // GEMM dot[128 i][64 j], K=64; warp tile 32x32
        float acc[2][4][4];
#pragma unroll
        for (int mi = 0; mi < 2; mi++)
#pragma unroll
            for (int ni = 0; ni < 4; ni++)
#pragma unroll
                for (int c = 0; c < 4; c++) acc[mi][ni][c] = 0.f;
#pragma unroll
        for (int ks = 0; ks < 8; ks++) {
            int k0 = ks*8;
            uint32_t A[2][4];
#pragma unroll
            for (int mi = 0; mi < 2; mi++) {
                int row = wm*32 + mi*16 + g4;
                A[mi][0] = __float_as_uint(sA[row*KF_LDA + k0 + tig]);
                A[mi][1] = __float_as_uint(sA[(row+8)*KF_LDA + k0 + tig]);
                A[mi][2] = __float_as_uint(sA[row*KF_LDA + k0 + tig + 4]);
                A[mi][3] = __float_as_uint(sA[(row+8)*KF_LDA + k0 + tig + 4]);
            }
            uint32_t Bf[4][2];
#pragma unroll
            for (int ni = 0; ni < 4; ni++) {
                int col = wn*32 + ni*8 + g4;
                Bf[ni][0] = __float_as_uint(sB[col*KF_LDA + k0 + tig]);
                Bf[ni][1] = __float_as_uint(sB[col*KF_LDA + k0 + tig + 4]);
            }
#pragma unroll
            for (int mi = 0; mi < 2; mi++)
#pragma unroll
                for (int ni = 0; ni < 4; ni++)
                    mma8(acc[mi][ni][0], acc[mi][ni][1], acc[mi][ni][2], acc[mi][ni][3],
                         A[mi][0], A[mi][1], A[mi][2], A[mi][3], Bf[ni][0], Bf[ni][1]);
        }
#pragma unroll
        for (int mi = 0; mi < 2; mi++) {
#pragma unroll
            for (int ni = 0; ni < 4; ni++) {
                int row = wm*32 + mi*16 + g4, col = wn*32 + ni*8 + tig*2;
                *(float2*)&sdot[row*KF_LDA + col]     = make_float2(acc[mi][ni][0], acc[mi][ni][1]);
                *(float2*)&sdot[(row+8)*KF_LDA + col] = make_float2(acc[mi][ni][2], acc[mi][ni][3]);
            }
        }
        __syncthreads();
        // split selection: scanner ssc covers j-cols [ssc*32, ssc*32+32)
        {
            if (jt == 0) mysq = sqi[spt];
            const float4* drow4 = (const float4*)(sdot + spt*KF_LDA) + ssc*8;
            const float4* sqj4  = (const float4*)sqj + ssc*8;
            int jbase = jt*64 + ssc*32;
#pragma unroll 4
            for (int j4 = 0; j4 < 8; j4++) {
                float4 dv = drow4[j4];
                float4 sv = sqj4[j4];
                float d0 = mysq + sv.x - 2.0f*dv.x;
                float d1 = mysq + sv.y - 2.0f*dv.y;
                float d2 = mysq + sv.z - 2.0f*dv.z;
                float d3 = mysq + sv.w - 2.0f*dv.w;
                float mn = fminf(fminf(d0, d1), fminf(d2, d3));
                if (mn < bd[KNN-1]) {
                    topk_insert(bd, bi, d0, jbase + 4*j4 + 0);
                    topk_insert(bd, bi, d1, jbase + 4*j4 + 1);
                    topk_insert(bd, bi, d2, jbase + 4*j4 + 2);
                    topk_insert(bd, bi, d3, jbase + 4*j4 + 3);
                }
            }
        }
    }
    __syncthreads();
    if (ssc == 1) {
#pragma unroll
        for (int t = 0; t < KNN; t++) { sbd[spt*KNN + t] = bd[t]; sbi[spt*KNN + t] = bi[t]; }
    }
    __syncthreads();
    if (ssc == 0) {
        for (int t = 0; t < KNN; t++) {
            float d = sbd[spt*KNN + t];
            if (!(d < bd[KNN-1])) break;
            topk_insert(bd, bi, d, sbi[spt*KNN + t]);
        }
        int gi = i0 + spt;
#pragma unroll
        for (int t = 0; t < KNN; t++) g_idx[(size_t)gi*KNN + t] = b*PP + bi[t];
    }
}

// ---------------- EdgeConv2 v6: persistent grid-stride + flat build + coop base + diff GEMM ----------------
#define C2_LDD 68
#define C2_LDW 136
#define C2_LDB 132
__global__ __launch_bounds__(256, 2) void conv2_kernel(
    const float* __restrict__ w, const float* __restrict__ bias)
{
    extern __shared__ float sm[];
    float* sWb   = sm;                        // 64*136
    float* sD    = sm + 64*C2_LDW;            // 160*68
    float* sXi   = sD + 160*C2_LDD;           // 8*68
    float* sBase = sXi + 8*68;                // 8*132
    float* sbias = sBase + 8*C2_LDB;          // 128
    int*   sJ    = (int*)(sbias + 128);       // 160
    int*   sP    = sJ + 160;                  // 160

    int tid = threadIdx.x, lane = tid & 31, warp = tid >> 5;
    int g4 = lane >> 2, tig = lane & 3;
    int wm = warp >> 2, wn = warp & 3;
    int mB = wm*80, nB = wn*32;

    for (int fi = tid; fi < 2048; fi += 256) {
        int kk = fi >> 5, nq = fi & 31;
        float4 v = ((const float4*)w)[(64+kk)*32 + nq];
        *(float4*)&sWb[kk*C2_LDW + nq*4] =
            make_float4(tfbits(v.x), tfbits(v.y), tfbits(v.z), tfbits(v.w));
    }
    if (tid < 128) sbias[tid] = bias[tid];

    const float4* x1v = (const float4*)g_x1;

    for (int g = blockIdx.x; g < 4096; g += gridDim.x) {
        int ibase = g * 8;
        __syncthreads();
        if (tid < 128) {
            int p = tid >> 4, q = tid & 15;
            *(float4*)&sXi[p*68 + q*4] = x1v[(size_t)(ibase+p)*16 + q];
        }
        if (tid < 160) {
            int p = tid / 20;
            sJ[tid] = g_idx[(size_t)(ibase+p)*KNN + (tid - p*20)];
            sP[tid] = p;
        }
        __syncthreads();
#pragma unroll
        for (int it = 0; it < 10; it++) {
            int fi = tid + it*256;
            int row = fi >> 4, q = fi & 15;
            int j = sJ[row], p = sP[row];
            float4 xj = x1v[(size_t)j*16 + q];
            float4 xi = *(const float4*)&sXi[p*68 + q*4];
            *(float4*)&sD[row*C2_LDD + q*4] =
                make_float4(tfbits(xj.x-xi.x), tfbits(xj.y-xi.y),
                            tfbits(xj.z-xi.z), tfbits(xj.w-xi.w));
        }
        {
            int p = lane >> 2, c4 = lane & 3;
            int colq = warp*4 + c4;
            const float* xir = &sXi[p*68];
            float4 acc4 = ((const float4*)sbias)[colq];
#pragma unroll 8
            for (int k = 0; k < 64; k++) {
                float xv = xir[k];
                float4 wv = ((const float4*)w)[k*32 + colq];
                acc4.x = fmaf(xv, wv.x, acc4.x); acc4.y = fmaf(xv, wv.y, acc4.y);
                acc4.z = fmaf(xv, wv.z, acc4.z); acc4.w = fmaf(xv, wv.w, acc4.w);
            }
            *(float4*)&sBase[p*C2_LDB + colq*4] = acc4;
        }
        __syncthreads();
        float acc[5][4][4];
#pragma unroll
        for (int mi = 0; mi < 5; mi++)
#pragma unroll
            for (int ni = 0; ni < 4; ni++)
#pragma unroll
                for (int c = 0; c < 4; c++) acc[mi][ni][c] = 0.f;
#pragma unroll 1
        for (int ks = 0; ks < 8; ks++) {
            int k0 = ks*8;
            uint32_t A[5][4];
#pragma unroll
            for (int mi = 0; mi < 5; mi++) {
                int row = mB + mi*16 + g4;
                A[mi][0] = __float_as_uint(sD[row*C2_LDD + k0 + tig]);
                A[mi][1] = __float_as_uint(sD[(row+8)*C2_LDD + k0 + tig]);
                A[mi][2] = __float_as_uint(sD[row*C2_LDD + k0 + tig + 4]);
                A[mi][3] = __float_as_uint(sD[(row+8)*C2_LDD + k0 + tig + 4]);
            }
            uint32_t Bf[4][2];
#pragma unroll
            for (int ni = 0; ni < 4; ni++) {
                int col = nB + ni*8 + g4;
                Bf[ni][0] = __float_as_uint(sWb[(k0+tig)*C2_LDW + col]);
                Bf[ni][1] = __float_as_uint(sWb[(k0+tig+4)*C2_LDW + col]);
            }
#pragma unroll
            for (int mi = 0; mi < 5; mi++)
#pragma unroll
                for (int ni = 0; ni < 4; ni++)
                    mma8(acc[mi][ni][0], acc[mi][ni][1], acc[mi][ni][2], acc[mi][ni][3],
                         A[mi][0], A[mi][1], A[mi][2], A[mi][3], Bf[ni][0], Bf[ni][1]);
        }
        float pm[4][4][2];
#pragma unroll
        for (int p = 0; p < 4; p++)
#pragma unroll
            for (int ni = 0; ni < 4; ni++) { pm[p][ni][0] = -3.4e38f; pm[p][ni][1] = -3.4e38f; }
        bool hi = (g4 >= 4);
#pragma unroll
        for (int ni = 0; ni < 4; ni++) {
            pm[0][ni][0] = fmaxf(pm[0][ni][0], acc[0][ni][0]);
            pm[0][ni][1] = fmaxf(pm[0][ni][1], acc[0][ni][1]);
            if (!hi) { pm[0][ni][0] = fmaxf(pm[0][ni][0], acc[1][ni][0]);
                       pm[0][ni][1] = fmaxf(pm[0][ni][1], acc[1][ni][1]); }
            else     { pm[1][ni][0] = fmaxf(pm[1][ni][0], acc[1][ni][0]);
                       pm[1][ni][1] = fmaxf(pm[1][ni][1], acc[1][ni][1]); }
            pm[1][ni][0] = fmaxf(pm[1][ni][0], acc[2][ni][0]);
            pm[1][ni][1] = fmaxf(pm[1][ni][1], acc[2][ni][1]);
            pm[2][ni][0] = fmaxf(pm[2][ni][0], acc[3][ni][0]);
            pm[2][ni][1] = fmaxf(pm[2][ni][1], acc[3][ni][1]);
            pm[3][ni][0] = fmaxf(pm[3][ni][0], acc[4][ni][0]);
            pm[3][ni][1] = fmaxf(pm[3][ni][1], acc[4][ni][1]);
            pm[0][ni][0] = fmaxf(pm[0][ni][0], acc[0][ni][2]);
            pm[0][ni][1] = fmaxf(pm[0][ni][1], acc[0][ni][3]);
            pm[1][ni][0] = fmaxf(pm[1][ni][0], acc[1][ni][2]);
            pm[1][ni][1] = fmaxf(pm[1][ni][1], acc[1][ni][3]);
            pm[2][ni][0] = fmaxf(pm[2][ni][0], acc[2][ni][2]);
            pm[2][ni][1] = fmaxf(pm[2][ni][1], acc[2][ni][3]);
            if (!hi) { pm[2][ni][0] = fmaxf(pm[2][ni][0], acc[3][ni][2]);
                       pm[2][ni][1] = fmaxf(pm[2][ni][1], acc[3][ni][3]); }
            else     { pm[3][ni][0] = fmaxf(pm[3][ni][0], acc[3][ni][2]);
                       pm[3][ni][1] = fmaxf(pm[3][ni][1], acc[3][ni][3]); }
            pm[3][ni][0] = fmaxf(pm[3][ni][0], acc[4][ni][2]);
            pm[3][ni][1] = fmaxf(pm[3][ni][1], acc[4][ni][3]);
        }
#pragma unroll
        for (int off = 4; off < 32; off <<= 1)
#pragma unroll
            for (int p = 0; p < 4; p++)
#pragma unroll
                for (int ni = 0; ni < 4; ni++) {
                    pm[p][ni][0] = fmaxf(pm[p][ni][0], __shfl_xor_sync(0xffffffff, pm[p][ni][0], off));
                    pm[p][ni][1] = fmaxf(pm[p][ni][1], __shfl_xor_sync(0xffffffff, pm[p][ni][1], off));
                }
        if (g4 == 0) {
#pragma unroll
            for (int p = 0; p < 4; p++) {
                int wp = wm*4 + p;
#pragma unroll
                for (int ni = 0; ni < 4; ni++) {
                    int col = nB + ni*8 + tig*2;
                    float b0v = sBase[wp*C2_LDB + col];
                    float b1v = sBase[wp*C2_LDB + col + 1];
                    float2 o;
                    o.x = fmaxf(pm[p][ni][0] + b0v, 0.f);
                    o.y = fmaxf(pm[p][ni][1] + b1v, 0.f);
                    *(float2*)&g_x2[(size_t)(ibase+wp)*128 + col] = o;
                }
            }
        }
    }
}

// ---------------- l1 (192->1024) tf32 GEMM, k-chunk 32, + fused relu + P-max ----------------
#define L1_LDA 36
__global__ __launch_bounds__(256) void l1max_kernel(
    const float* __restrict__ w, const float* __restrict__ bias)
{
    __shared__ float sA[128*L1_LDA];
    __shared__ float sB[32*136];
    __shared__ float sbias[128];
    __shared__ unsigned int sred[128];
    int tid = threadIdx.x;
    int lane = tid & 31, warp = tid >> 5;
    int g4 = lane >> 2, tig = lane & 3;
    int b = blockIdx.z;
    int n0 = blockIdx.x * 128, m0 = blockIdx.y * 128;
    int pbase = b * PP + m0;
    const float4* x1v = (const float4*)g_x1;
    const float4* x2v = (const float4*)g_x2;
    const float4* wv  = (const float4*)w;
    if (tid < 128) { sred[tid] = 0u; sbias[tid] = bias[n0 + tid]; }

    int wm = warp >> 2, wn = warp & 3;
    float acc[4][4][4];
#pragma unroll
    for (int mi = 0; mi < 4; mi++)
#pragma unroll
        for (int ni = 0; ni < 4; ni++)
#pragma unroll
            for (int c = 0; c < 4; c++) acc[mi][ni][c] = 0.f;

    for (int ks = 0; ks < 6; ks++) {
        __syncthreads();
#pragma unroll
        for (int r = 0; r < 4; r++) {
            int fi = tid + r*256;
            int pt = fi >> 3, kq = fi & 7;
            float4 v = (ks < 2) ? x1v[(size_t)(pbase+pt)*16 + ks*8 + kq]
                                : x2v[(size_t)(pbase+pt)*32 + (ks-2)*8 + kq];
            *(float4*)&sA[pt*L1_LDA + kq*4] =
                make_float4(tfbits(v.x), tfbits(v.y), tfbits(v.z), tfbits(v.w));
        }
#pragma unroll
        for (int r = 0; r < 4; r++) {
            int fi = tid + r*256;
            int kk = fi >> 5, nq = fi & 31;
            float4 v = wv[(size_t)(ks*32+kk)*256 + (n0>>2) + nq];
            *(float4*)&sB[kk*136 + nq*4] =
                make_float4(tfbits(v.x), tfbits(v.y), tfbits(v.z), tfbits(v.w));
        }
        __syncthreads();
#pragma unroll
        for (int kh = 0; kh < 4; kh++) {
            int k0 = kh*8;
            uint32_t A[4][4];
#pragma unroll
            for (int mi = 0; mi < 4; mi++) {
                int row = wm*64 + mi*16 + g4;
                A[mi][0] = __float_as_uint(sA[row*L1_LDA + k0 + tig]);
                A[mi][1] = __float_as_uint(sA[(row+8)*L1_LDA + k0 + tig]);
                A[mi][2] = __float_as_uint(sA[row*L1_LDA + k0 + tig + 4]);
                A[mi][3] = __float_as_uint(sA[(row+8)*L1_LDA + k0 + tig + 4]);
            }
            uint32_t Bf[4][2];
#pragma unroll
            for (int ni = 0; ni < 4; ni++) {
                int col = wn*32 + ni*8 + g4;
                Bf[ni][0] = __float_as_uint(sB[(k0+tig)*136 + col]);
                Bf[ni][1] = __float_as_uint(sB[(k0+tig+4)*136 + col]);
            }
#pragma unroll
            for (int mi = 0; mi < 4; mi++)
#pragma unroll
                for (int ni = 0; ni < 4; ni++)
                    mma8(acc[mi][ni][0], acc[mi][ni][1], acc[mi][ni][2], acc[mi][ni][3],
                         A[mi][0], A[mi][1], A[mi][2], A[mi][3], Bf[ni][0], Bf[ni][1]);
        }
    }
#pragma unroll
    for (int ni = 0; ni < 4; ni++) {
        float v0 = -3.4e38f, v1 = -3.4e38f;
#pragma unroll
        for (int mi = 0; mi < 4; mi++) {
            v0 = fmaxf(v0, fmaxf(acc[mi][ni][0], acc[mi][ni][2]));
            v1 = fmaxf(v1, fmaxf(acc[mi][ni][1], acc[mi][ni][3]));
        }
#pragma unroll
        for (int off = 4; off < 32; off <<= 1) {
            v0 = fmaxf(v0, __shfl_xor_sync(0xffffffff, v0, off));
            v1 = fmaxf(v1, __shfl_xor_sync(0xffffffff, v1, off));
        }
        if (g4 == 0) {
            int col = wn*32 + ni*8 + tig*2;
            float a0 = fmaxf(v0 + sbias[col], 0.f);
            float a1 = fmaxf(v1 + sbias[col+1], 0.f);
            atomicMax(&sred[col],   __float_as_uint(a0));
            atomicMax(&sred[col+1], __float_as_uint(a1));
        }
    }
    __syncthreads();
    if (tid < 128) atomicMax(&g_pool[b*1024 + n0 + tid], sred[tid]);
}

// ---------------- head0: h0 = relu(pool @ m_w0 + b0), grid (2, 32) ----------------
__global__ __launch_bounds__(256) void head0_kernel(
    const float* __restrict__ w0, const float* __restrict__ b0)
{
    __shared__ float sp[1024];
    int b = blockIdx.y, tid = threadIdx.x;
    int o = blockIdx.x * 256 + tid;
    for (int c = tid; c < 1024; c += 256) sp[c] = __uint_as_float(g_pool[b*1024 + c]);
    __syncthreads();
    float a0 = 0.f, a1 = 0.f, a2 = 0.f, a3 = 0.f;
    for (int c = 0; c < 1024; c += 4) {
        a0 = fmaf(sp[c+0], w0[(size_t)(c+0)*512 + o], a0);
        a1 = fmaf(sp[c+1], w0[(size_t)(c+1)*512 + o], a1);
        a2 = fmaf(sp[c+2], w0[(size_t)(c+2)*512 + o], a2);
        a3 = fmaf(sp[c+3], w0[(size_t)(c+3)*512 + o], a3);
    }
    g_h0[b*512 + o] = fmaxf(((a0 + a1) + (a2 + a3)) + b0[o], 0.f);
}

// ---------------- head1: 512->256 relu ->40 + log_softmax, grid 32 ----------------
__global__ __launch_bounds__(256) void head1_kernel(
    const float* __restrict__ w1, const float* __restrict__ b1,
    const float* __restrict__ w2, const float* __restrict__ b2,
    float* __restrict__ out)
{
    __shared__ float sh0[512], sh1[256], sl[40], red[2];
    int b = blockIdx.x, tid = threadIdx.x;
    for (int c = tid; c < 512; c += 256) sh0[c] = g_h0[b*512 + c];
    __syncthreads();
    {
        float a0 = 0.f, a1 = 0.f;
        for (int c = 0; c < 512; c += 2) {
            a0 = fmaf(sh0[c],   w1[(size_t)c*256 + tid],     a0);
            a1 = fmaf(sh0[c+1], w1[(size_t)(c+1)*256 + tid], a1);
        }
        sh1[tid] = fmaxf(a0 + a1 + b1[tid], 0.f);
    }
    __syncthreads();
    if (tid < 40) {
        float a = b2[tid];
        for (int c = 0; c < 256; c++) a += sh1[c] * w2[c*40 + tid];
        sl[tid] = a;
    }
    __syncthreads();
    if (tid == 0) {
        float mxv = -3.4e38f;
        for (int t = 0; t < 40; t++) mxv = fmaxf(mxv, sl[t]);
        float s = 0.f;
        for (int t = 0; t < 40; t++) s += expf(sl[t] - mxv);
        red[0] = mxv; red[1] = logf(s);
    }
    __syncthreads();
    if (tid < 40) out[b*40 + tid] = sl[tid] - red[0] - red[1];
}

// ---------------- launch ----------------
extern "C" void kernel_launch(void* const* d_in, const int* in_sizes, int n_in,
                              void* d_out, int out_size)
{
    const float* pos   = (const float*)d_in[0];
    const float* c1_w0 = (const float*)d_in[2];
    const float* c1_b0 = (const float*)d_in[3];
    const float* c1_w1 = (const float*)d_in[4];
    const float* c1_b1 = (const float*)d_in[5];
    const float* c1_w2 = (const float*)d_in[6];
    const float* c1_b2 = (const float*)d_in[7];
    const float* c2_w0 = (const float*)d_in[8];
    const float* c2_b0 = (const float*)d_in[9];
    const float* l1_w  = (const float*)d_in[10];
    const float* l1_b  = (const float*)d_in[11];
    const float* m_w0  = (const float*)d_in[12];
    const float* m_b0  = (const float*)d_in[13];
    const float* m_w1  = (const float*)d_in[14];
    const float* m_b1  = (const float*)d_in[15];
    const float* m_w2  = (const float*)d_in[16];
    const float* m_b2  = (const float*)d_in[17];
    float* out = (float*)d_out;

    const int smem_kpos  = 4096*4 + 5120*4 + 5120*4;                                     // 57344
    const int smem_conv1 = (576 + 4608 + 128 + 160*C1_LDD) * 4;                          // 64768
    const int smem_knn2  = (128*KF_LDA + 64*KF_LDA + 128*KF_LDA + 128 + 64
                            + 128*KNN + 128*KNN) * 4;                                     // 108288
    const int smem_conv2 = (64*C2_LDW + 160*C2_LDD + 8*68 + 8*C2_LDB + 128 + 320) * 4;   // ~86.5 KB

    cudaFuncSetAttribute(knn_pos_kernel,  cudaFuncAttributeMaxDynamicSharedMemorySize, smem_kpos);
    cudaFuncSetAttribute(conv1_kernel,    cudaFuncAttributeMaxDynamicSharedMemorySize, smem_conv1);
    cudaFuncSetAttribute(knn_feat_kernel, cudaFuncAttributeMaxDynamicSharedMemorySize, smem_knn2);
    cudaFuncSetAttribute(conv2_kernel,    cudaFuncAttributeMaxDynamicSharedMemorySize, smem_conv2);

    fuse_w01_kernel<<<1, 512>>>(c1_w0, c1_b0, c1_w1, c1_b1);
    knn_pos_kernel<<<dim3(4, 32), 512, smem_kpos>>>(pos);
    conv1_kernel<<<296, 256, smem_conv1>>>(pos, c1_w2, c1_b2);
    knn_feat_kernel<<<dim3(8, 32), 256, smem_knn2>>>();
    conv2_kernel<<<296, 256, smem_conv2>>>(c2_w0, c2_b0);
    l1max_kernel<<<dim3(8, 8, 32), 256>>>(l1_w, l1_b);
    head0_kernel<<<dim3(2, 32), 256>>>(m_w0, m_b0);
    head1_kernel<<<32, 256>>>(m_w1, m_b1, m_w2, m_b2, out);
}